// round 7
// baseline (speedup 1.0000x reference)
#include <cuda_runtime.h>
#include <math.h>
#include <float.h>

#define T_   32
#define N_   1024
#define D_   128
#define HG   100
#define FEAT 3200
#define HC   16
#define KNN  20
#define NP1  820
#define NP2  656

// ---------------- scratch (device globals; no allocs) ----------------
__device__ float g_bufA[T_*N_*D_];
__device__ float g_bufB[T_*N_*D_];
__device__ float g_gi[T_*N_*3*HG];
__device__ float g_tfeat[N_*FEAT];
__device__ float g_G[N_*N_];
__device__ float g_diag[N_];
__device__ int   g_nbr1[N_*KNN];
__device__ float g_p1[N_*HC], g_q1[N_*HC];
__device__ float g_x1f[N_*HC];
__device__ float g_sc1[N_];
__device__ float g_pool1[NP1*HC];
__device__ float g_vec1[HC];
__device__ float g_sq2[NP1];
__device__ int   g_nbr2[NP1*KNN];
__device__ float g_p2[NP1*HC], g_q2[NP1*HC];
__device__ float g_x2f[NP1*HC];
__device__ float g_sc2[NP1];
__device__ float g_pool2[NP2*HC];
__device__ float g_vec2[HC];

// ------------- conv1d (1024ch, k=5, pad=2) + leaky -------------
// grid (16, T), 256 thr; block tile: 64 out-ch x 128 pos; thread: 4 o x 8 h
__global__ __launch_bounds__(256, 2)
void conv_kernel(const float* __restrict__ in, const float* __restrict__ w,
                 const float* __restrict__ b, float* __restrict__ out)
{
    __shared__ float xs[16*132];
    __shared__ float ws[16*5*64];
    const int tid = threadIdx.x;
    const int t = blockIdx.y;
    const int obase = blockIdx.x * 64;
    const int to = tid >> 4, th = tid & 15;
    float acc[4][8];
#pragma unroll
    for (int u = 0; u < 4; u++)
#pragma unroll
        for (int h = 0; h < 8; h++) acc[u][h] = 0.f;
    const float* inT = in + (size_t)t * (N_*D_);

    for (int ic0 = 0; ic0 < N_; ic0 += 16) {
        for (int idx = tid; idx < 16*132; idx += 256) {
            int i = idx / 132, c = idx % 132;
            xs[idx] = (c >= 2 && c < 130) ? inT[(ic0 + i) * D_ + (c - 2)] : 0.f;
        }
        for (int idx = tid; idx < 5120; idx += 256) {
            int o = idx / 80, r = idx % 80;
            ws[r * 64 + o] = w[(size_t)(obase + o) * 5120 + ic0 * 5 + r];
        }
        __syncthreads();
#pragma unroll 2
        for (int i = 0; i < 16; i++) {
            float xw[12];
            const float4* xp = (const float4*)(xs + i*132 + (th << 3));
            float4 a = xp[0], bb = xp[1], cc = xp[2];
            xw[0]=a.x; xw[1]=a.y; xw[2]=a.z; xw[3]=a.w;
            xw[4]=bb.x; xw[5]=bb.y; xw[6]=bb.z; xw[7]=bb.w;
            xw[8]=cc.x; xw[9]=cc.y; xw[10]=cc.z; xw[11]=cc.w;
#pragma unroll
            for (int k = 0; k < 5; k++) {
                const float4 wv = *(const float4*)(ws + (i*5 + k)*64 + (to << 2));
#pragma unroll
                for (int h = 0; h < 8; h++) {
                    float xv = xw[h + k];
                    acc[0][h] += wv.x * xv; acc[1][h] += wv.y * xv;
                    acc[2][h] += wv.z * xv; acc[3][h] += wv.w * xv;
                }
            }
        }
        __syncthreads();
    }
#pragma unroll
    for (int u = 0; u < 4; u++) {
        int o = obase + (to << 2) + u;
        float bb = b[o];
        float* op = out + (size_t)t * (N_*D_) + (size_t)o * D_ + (th << 3);
#pragma unroll
        for (int h = 0; h < 8; h++) {
            float v = acc[u][h] + bb;
            op[h] = v > 0.f ? v : 0.1f * v;
        }
    }
}

// --------- SGEMM  C[m][n] = sum_k A[m][k]*B[n][k] (+bias[n]) ----------
// 64x64 tile, 256 thr, 4x4/thread. M%64==0, K%16==0, Ncols guarded.
__global__ __launch_bounds__(256)
void sgemm_nt(const float* __restrict__ A, const float* __restrict__ B,
              const float* __restrict__ bias, float* __restrict__ C,
              int M, int Ncols, int Kd)
{
    __shared__ float As[16][64];
    __shared__ float Bs[16][64];
    const int tid = threadIdx.x;
    const int tx = tid & 15, ty = tid >> 4;
    const int m0 = blockIdx.y * 64, n0 = blockIdx.x * 64;
    float acc[4][4];
#pragma unroll
    for (int i = 0; i < 4; i++)
#pragma unroll
        for (int j = 0; j < 4; j++) acc[i][j] = 0.f;

    for (int k0 = 0; k0 < Kd; k0 += 16) {
#pragma unroll
        for (int l = 0; l < 4; l++) {
            int idx = tid + l * 256;
            int row = idx >> 4, kk = idx & 15;
            As[kk][row] = A[(size_t)(m0 + row) * Kd + k0 + kk];
            Bs[kk][row] = (n0 + row < Ncols) ? B[(size_t)(n0 + row) * Kd + k0 + kk] : 0.f;
        }
        __syncthreads();
#pragma unroll
        for (int k = 0; k < 16; k++) {
            float4 a4 = *(const float4*)&As[k][tx << 2];
            float4 b4 = *(const float4*)&Bs[k][ty << 2];
            float av[4] = {a4.x, a4.y, a4.z, a4.w};
            float bv[4] = {b4.x, b4.y, b4.z, b4.w};
#pragma unroll
            for (int i = 0; i < 4; i++)
#pragma unroll
                for (int j = 0; j < 4; j++) acc[i][j] += av[i] * bv[j];
        }
        __syncthreads();
    }
#pragma unroll
    for (int i = 0; i < 4; i++) {
        int m = m0 + (tx << 2) + i;
#pragma unroll
        for (int j = 0; j < 4; j++) {
            int n = n0 + (ty << 2) + j;
            if (n < Ncols)
                C[(size_t)m * Ncols + n] = acc[i][j] + (bias ? bias[n] : 0.f);
        }
    }
}

// ---------------- GRU over T=32 (8 nodes / block) ----------------
__global__ __launch_bounds__(320)
void gru_kernel(const float* __restrict__ gi, const float* __restrict__ whh,
                const float* __restrict__ bhh, float* __restrict__ tf)
{
    __shared__ float h_s[8][HG];
    __shared__ float gh_s[8][304];
    const int tid = threadIdx.x;
    const int n0 = blockIdx.x * 8;
    for (int p = tid; p < 8 * HG; p += 320) h_s[p / HG][p % HG] = 0.f;
    __syncthreads();

    for (int t = 0; t < T_; t++) {
        if (tid < 300) {
            const int j = tid;
            float acc[8];
#pragma unroll
            for (int n = 0; n < 8; n++) acc[n] = 0.f;
            const float4* wr = (const float4*)(whh + (size_t)j * HG);
#pragma unroll 5
            for (int d4 = 0; d4 < HG / 4; d4++) {
                float4 w4 = wr[d4];
#pragma unroll
                for (int n = 0; n < 8; n++) {
                    float4 h4 = ((const float4*)h_s[n])[d4];
                    acc[n] += w4.x*h4.x + w4.y*h4.y + w4.z*h4.z + w4.w*h4.w;
                }
            }
            float bb = bhh[j];
#pragma unroll
            for (int n = 0; n < 8; n++) gh_s[n][j] = acc[n] + bb;
        }
        __syncthreads();
        for (int p = tid; p < 8 * HG; p += 320) {
            int n = p / HG, d = p % HG;
            int ng = n0 + n;
            const float* gin = gi + ((size_t)t * N_ + ng) * (3 * HG);
            float rg = 1.f / (1.f + expf(-(gin[d]        + gh_s[n][d])));
            float zg = 1.f / (1.f + expf(-(gin[HG + d]   + gh_s[n][HG + d])));
            float nn = tanhf(gin[2*HG + d] + rg * gh_s[n][2*HG + d]);
            float hnew = (1.f - zg) * nn + zg * h_s[n][d];
            tf[(size_t)ng * FEAT + t * HG + d] = hnew > 0.f ? hnew : 0.1f * hnew;
            h_s[n][d] = hnew;
        }
        __syncthreads();
    }
}

// ---------------- small kernels ----------------
__global__ void diag_kernel(const float* __restrict__ G, float* __restrict__ dg)
{
    int n = blockIdx.x * blockDim.x + threadIdx.x;
    if (n < N_) dg[n] = G[(size_t)n * N_ + n];
}

// top-K of -(d2) = 2*G_ij - G_ii - G_jj (desc, ties -> lower index)
__global__ __launch_bounds__(256)
void topk1_kernel(const float* __restrict__ G, const float* __restrict__ dg,
                  int* __restrict__ nbr)
{
    __shared__ float s[N_];
    __shared__ float rv[8]; __shared__ int ri[8];
    const int i = blockIdx.x, tid = threadIdx.x;
    const float dii = dg[i];
    for (int j = tid; j < N_; j += 256) s[j] = 2.f * G[(size_t)i * N_ + j] - dii - dg[j];
    __syncthreads();
    for (int it = 0; it < KNN; it++) {
        float bv = -FLT_MAX; int bi = 1 << 30;
        for (int j = tid; j < N_; j += 256) {
            float v = s[j];
            if (v > bv || (v == bv && j < bi)) { bv = v; bi = j; }
        }
        for (int off = 16; off; off >>= 1) {
            float ov = __shfl_down_sync(0xffffffffu, bv, off);
            int   oi = __shfl_down_sync(0xffffffffu, bi, off);
            if (ov > bv || (ov == bv && oi < bi)) { bv = ov; bi = oi; }
        }
        if ((tid & 31) == 0) { rv[tid >> 5] = bv; ri[tid >> 5] = bi; }
        __syncthreads();
        if (tid == 0) {
            float fv = rv[0]; int fi = ri[0];
            for (int w = 1; w < 8; w++)
                if (rv[w] > fv || (rv[w] == fv && ri[w] < fi)) { fv = rv[w]; fi = ri[w]; }
            nbr[i * KNN + it] = fi;
            s[fi] = -FLT_MAX;
        }
        __syncthreads();
    }
}

__global__ __launch_bounds__(256)
void topk2_kernel(const float* __restrict__ x, const float* __restrict__ sq,
                  int Nn, int* __restrict__ nbr)
{
    __shared__ float s[NP1 + 12];
    __shared__ float xi[HC];
    __shared__ float rv[8]; __shared__ int ri[8];
    const int i = blockIdx.x, tid = threadIdx.x;
    if (tid < HC) xi[tid] = x[(size_t)i * HC + tid];
    __syncthreads();
    const float sqi = sq[i];
    for (int j = tid; j < Nn; j += 256) {
        const float* xj = x + (size_t)j * HC;
        float dot = 0.f;
#pragma unroll
        for (int c = 0; c < HC; c++) dot += xi[c] * xj[c];
        s[j] = 2.f * dot - sqi - sq[j];
    }
    __syncthreads();
    for (int it = 0; it < KNN; it++) {
        float bv = -FLT_MAX; int bi = 1 << 30;
        for (int j = tid; j < Nn; j += 256) {
            float v = s[j];
            if (v > bv || (v == bv && j < bi)) { bv = v; bi = j; }
        }
        for (int off = 16; off; off >>= 1) {
            float ov = __shfl_down_sync(0xffffffffu, bv, off);
            int   oi = __shfl_down_sync(0xffffffffu, bi, off);
            if (ov > bv || (ov == bv && oi < bi)) { bv = ov; bi = oi; }
        }
        if ((tid & 31) == 0) { rv[tid >> 5] = bv; ri[tid >> 5] = bi; }
        __syncthreads();
        if (tid == 0) {
            float fv = rv[0]; int fi = ri[0];
            for (int w = 1; w < 8; w++)
                if (rv[w] > fv || (rv[w] == fv && ri[w] < fi)) { fv = rv[w]; fi = ri[w]; }
            nbr[i * KNN + it] = fi;
            s[fi] = -FLT_MAX;
        }
        __syncthreads();
    }
}

// p = t @ w1[:FEAT], q = t @ w1[FEAT:]   (one block per node)
__global__ __launch_bounds__(256)
void pq1_kernel(const float* __restrict__ tf, const float* __restrict__ w1,
                float* __restrict__ p, float* __restrict__ q)
{
    __shared__ float redm[8][32];
    const int n = blockIdx.x, tid = threadIdx.x;
    float ap[HC], aq[HC];
#pragma unroll
    for (int c = 0; c < HC; c++) { ap[c] = 0.f; aq[c] = 0.f; }
    for (int f = tid; f < FEAT; f += 256) {
        float xv = tf[(size_t)n * FEAT + f];
        const float4* wp = (const float4*)(w1 + (size_t)f * HC);
        const float4* wq = (const float4*)(w1 + (size_t)(FEAT + f) * HC);
#pragma unroll
        for (int c4 = 0; c4 < 4; c4++) {
            float4 a = wp[c4];
            ap[c4*4+0] += xv*a.x; ap[c4*4+1] += xv*a.y;
            ap[c4*4+2] += xv*a.z; ap[c4*4+3] += xv*a.w;
            float4 b = wq[c4];
            aq[c4*4+0] += xv*b.x; aq[c4*4+1] += xv*b.y;
            aq[c4*4+2] += xv*b.z; aq[c4*4+3] += xv*b.w;
        }
    }
    const int lane = tid & 31, wid = tid >> 5;
    for (int c = 0; c < 32; c++) {
        float v = (c < HC) ? ap[c] : aq[c - HC];
        for (int off = 16; off; off >>= 1) v += __shfl_down_sync(0xffffffffu, v, off);
        if (lane == 0) redm[wid][c] = v;
    }
    __syncthreads();
    if (tid < 32) {
        float v = 0.f;
        for (int w = 0; w < 8; w++) v += redm[w][tid];
        if (tid < HC) p[(size_t)n * HC + tid] = v;
        else          q[(size_t)n * HC + tid - HC] = v;
    }
}

__global__ __launch_bounds__(256)
void pq2_kernel(const float* __restrict__ x, const float* __restrict__ w1,
                float* __restrict__ p, float* __restrict__ q, int Nn)
{
    int n = blockIdx.x * blockDim.x + threadIdx.x;
    if (n >= Nn) return;
    float xi[HC];
#pragma unroll
    for (int c = 0; c < HC; c++) xi[c] = x[(size_t)n * HC + c];
#pragma unroll
    for (int c = 0; c < HC; c++) {
        float pp = 0.f, qq = 0.f;
#pragma unroll
        for (int u = 0; u < HC; u++) {
            pp += xi[u] * w1[u * HC + c];
            qq += xi[u] * w1[(HC + u) * HC + c];
        }
        p[(size_t)n * HC + c] = pp;
        q[(size_t)n * HC + c] = qq;
    }
}

// edge MLP + max over K neighbors
__global__ __launch_bounds__(256)
void edge_kernel(const float* __restrict__ p, const float* __restrict__ q,
                 const float* __restrict__ b1, const float* __restrict__ w2,
                 const float* __restrict__ b2, const int* __restrict__ nbr,
                 float* __restrict__ out, int Nn, int doRelu)
{
    __shared__ float w2s[HC*HC];
    __shared__ float b1s[HC], b2s[HC];
    const int tid = threadIdx.x;
    if (tid < HC*HC) w2s[tid] = w2[tid];
    if (tid < HC) { b1s[tid] = b1[tid]; b2s[tid] = b2[tid]; }
    __syncthreads();
    const int n = blockIdx.x * blockDim.x + tid;
    if (n >= Nn) return;
    float base[HC], best[HC];
#pragma unroll
    for (int c = 0; c < HC; c++) {
        base[c] = p[(size_t)n*HC + c] - q[(size_t)n*HC + c] + b1s[c];
        best[c] = -FLT_MAX;
    }
    for (int kk = 0; kk < KNN; kk++) {
        int j = nbr[n * KNN + kk];
        const float* qj = q + (size_t)j * HC;
        float o[HC];
#pragma unroll
        for (int c = 0; c < HC; c++) o[c] = b2s[c];
#pragma unroll
        for (int u = 0; u < HC; u++) {
            float hv = base[u] + qj[u];
            hv = hv > 0.f ? hv : 0.f;
#pragma unroll
            for (int c = 0; c < HC; c++) o[c] += hv * w2s[u*HC + c];
        }
#pragma unroll
        for (int c = 0; c < HC; c++) best[c] = fmaxf(best[c], o[c]);
    }
#pragma unroll
    for (int c = 0; c < HC; c++) {
        float v = best[c];
        if (doRelu) v = fmaxf(v, 0.f);
        out[(size_t)n * HC + c] = v;
    }
}

__global__ void score_kernel(const float* __restrict__ x, const float* __restrict__ w,
                             int Nn, float* __restrict__ s)
{
    int n = blockIdx.x * blockDim.x + threadIdx.x;
    if (n >= Nn) return;
    float nw = 0.f, d = 0.f;
#pragma unroll
    for (int c = 0; c < HC; c++) nw += w[c] * w[c];
    nw = sqrtf(nw);
#pragma unroll
    for (int c = 0; c < HC; c++) d += x[(size_t)n*HC + c] * w[c];
    s[n] = tanhf(d / nw);
}

__global__ void sq_kernel(const float* __restrict__ x, int Nn, float* __restrict__ sq)
{
    int n = blockIdx.x * blockDim.x + threadIdx.x;
    if (n >= Nn) return;
    float a = 0.f;
#pragma unroll
    for (int c = 0; c < HC; c++) { float v = x[(size_t)n*HC + c]; a += v * v; }
    sq[n] = a;
}

// reproduce jax.lax.top_k stable descending order: out[rank] = x[n]*s[n]
__global__ void rank_pool_kernel(const float* __restrict__ x, const float* __restrict__ s,
                                 int Nn, int nkeep, float* __restrict__ out)
{
    int n = blockIdx.x * blockDim.x + threadIdx.x;
    if (n >= Nn) return;
    float sn = s[n];
    int rank = 0;
    for (int m = 0; m < Nn; m++) {
        float sm = s[m];
        if (sm > sn || (sm == sn && m < n)) rank++;
    }
    if (rank < nkeep) {
#pragma unroll
        for (int c = 0; c < HC; c++)
            out[(size_t)rank * HC + c] = x[(size_t)n * HC + c] * sn;
    }
}

// gated attention pool: vec = sum softmax(x@gw+gb) * x
__global__ __launch_bounds__(256)
void gap_kernel(const float* __restrict__ x, const float* __restrict__ gw,
                const float* __restrict__ gb, int Nn, float* __restrict__ vec)
{
    __shared__ float a[NP1 + 12];
    __shared__ float red[8];
    const int tid = threadIdx.x;
    float lmax = -FLT_MAX;
    for (int n = tid; n < Nn; n += 256) {
        float d = gb[0];
#pragma unroll
        for (int c = 0; c < HC; c++) d += x[(size_t)n*HC + c] * gw[c];
        a[n] = d;
        lmax = fmaxf(lmax, d);
    }
    for (int off = 16; off; off >>= 1) lmax = fmaxf(lmax, __shfl_xor_sync(0xffffffffu, lmax, off));
    if ((tid & 31) == 0) red[tid >> 5] = lmax;
    __syncthreads();
    lmax = red[0];
    for (int w = 1; w < 8; w++) lmax = fmaxf(lmax, red[w]);
    __syncthreads();
    float lsum = 0.f;
    for (int n = tid; n < Nn; n += 256) {
        float e = expf(a[n] - lmax);
        a[n] = e;
        lsum += e;
    }
    for (int off = 16; off; off >>= 1) lsum += __shfl_xor_sync(0xffffffffu, lsum, off);
    if ((tid & 31) == 0) red[tid >> 5] = lsum;
    __syncthreads();
    lsum = 0.f;
    for (int w = 0; w < 8; w++) lsum += red[w];
    if (tid < HC) {
        float v = 0.f;
        for (int n = 0; n < Nn; n++) v += a[n] * x[(size_t)n*HC + tid];
        vec[tid] = v / lsum;
    }
}

__global__ void final_kernel(const float* __restrict__ v1, const float* __restrict__ v2,
                             const float* __restrict__ w, const float* __restrict__ b,
                             float* __restrict__ out)
{
    int c = threadIdx.x;
    if (c < 2) {
        float acc = b[c];
#pragma unroll
        for (int u = 0; u < HC; u++) acc += (v1[u] + v2[u]) * w[u*2 + c];
        out[c] = acc;
    }
}

// ---------------- launch ----------------
extern "C" void kernel_launch(void* const* d_in, const int* in_sizes, int n_in,
                              void* d_out, int out_size)
{
    const float* ts      = (const float*)d_in[0];
    const float* c1w     = (const float*)d_in[1];
    const float* c1b     = (const float*)d_in[2];
    const float* c2w     = (const float*)d_in[3];
    const float* c2b     = (const float*)d_in[4];
    const float* c3w     = (const float*)d_in[5];
    const float* c3b     = (const float*)d_in[6];
    const float* wih     = (const float*)d_in[7];
    const float* whh     = (const float*)d_in[8];
    const float* bih     = (const float*)d_in[9];
    const float* bhh     = (const float*)d_in[10];
    const float* m1w1    = (const float*)d_in[11];
    const float* m1b1    = (const float*)d_in[12];
    const float* m1w2    = (const float*)d_in[13];
    const float* m1b2    = (const float*)d_in[14];
    const float* p1w     = (const float*)d_in[15];
    const float* g1w     = (const float*)d_in[16];
    const float* g1b     = (const float*)d_in[17];
    const float* m2w1    = (const float*)d_in[18];
    const float* m2b1    = (const float*)d_in[19];
    const float* m2w2    = (const float*)d_in[20];
    const float* m2b2    = (const float*)d_in[21];
    const float* p2w     = (const float*)d_in[22];
    const float* g2w     = (const float*)d_in[23];
    const float* g2b     = (const float*)d_in[24];
    const float* l2w     = (const float*)d_in[25];
    const float* l2b     = (const float*)d_in[26];
    float* out           = (float*)d_out;

    float *bufA, *bufB, *gi, *tf, *G, *dg, *p1, *q1, *x1f, *sc1, *pool1, *vec1;
    float *sq2, *p2, *q2, *x2f, *sc2, *pool2, *vec2;
    int *nbr1, *nbr2;
    cudaGetSymbolAddress((void**)&bufA,  g_bufA);
    cudaGetSymbolAddress((void**)&bufB,  g_bufB);
    cudaGetSymbolAddress((void**)&gi,    g_gi);
    cudaGetSymbolAddress((void**)&tf,    g_tfeat);
    cudaGetSymbolAddress((void**)&G,     g_G);
    cudaGetSymbolAddress((void**)&dg,    g_diag);
    cudaGetSymbolAddress((void**)&nbr1,  g_nbr1);
    cudaGetSymbolAddress((void**)&p1,    g_p1);
    cudaGetSymbolAddress((void**)&q1,    g_q1);
    cudaGetSymbolAddress((void**)&x1f,   g_x1f);
    cudaGetSymbolAddress((void**)&sc1,   g_sc1);
    cudaGetSymbolAddress((void**)&pool1, g_pool1);
    cudaGetSymbolAddress((void**)&vec1,  g_vec1);
    cudaGetSymbolAddress((void**)&sq2,   g_sq2);
    cudaGetSymbolAddress((void**)&nbr2,  g_nbr2);
    cudaGetSymbolAddress((void**)&p2,    g_p2);
    cudaGetSymbolAddress((void**)&q2,    g_q2);
    cudaGetSymbolAddress((void**)&x2f,   g_x2f);
    cudaGetSymbolAddress((void**)&sc2,   g_sc2);
    cudaGetSymbolAddress((void**)&pool2, g_pool2);
    cudaGetSymbolAddress((void**)&vec2,  g_vec2);

    // conv chain (leaky fused)
    conv_kernel<<<dim3(16, T_), 256>>>(ts,   c1w, c1b, bufA);
    conv_kernel<<<dim3(16, T_), 256>>>(bufA, c2w, c2b, bufB);
    conv_kernel<<<dim3(16, T_), 256>>>(bufB, c3w, c3b, bufA);

    // gi = d @ wih.T + bih   (M = T*N, Ncols = 300, K = 128)
    sgemm_nt<<<dim3(5, (T_*N_)/64), 256>>>(bufA, wih, bih, gi, T_*N_, 3*HG, D_);

    // GRU recurrence -> tfeat (leaky fused)
    gru_kernel<<<N_/8, 320>>>(gi, whh, bhh, tf);

    // Gram matrix + knn1
    sgemm_nt<<<dim3(16, 16), 256>>>(tf, tf, nullptr, G, N_, N_, FEAT);
    diag_kernel<<<4, 256>>>(G, dg);
    topk1_kernel<<<N_, 256>>>(G, dg, nbr1);

    // DGCN1
    pq1_kernel<<<N_, 256>>>(tf, m1w1, p1, q1);
    edge_kernel<<<4, 256>>>(p1, q1, m1b1, m1w2, m1b2, nbr1, x1f, N_, 1);

    // pool1 + gap1
    score_kernel<<<4, 256>>>(x1f, p1w, N_, sc1);
    rank_pool_kernel<<<4, 256>>>(x1f, sc1, N_, NP1, pool1);
    gap_kernel<<<1, 256>>>(pool1, g1w, g1b, NP1, vec1);

    // DGCN2
    sq_kernel<<<4, 256>>>(pool1, NP1, sq2);
    topk2_kernel<<<NP1, 256>>>(pool1, sq2, NP1, nbr2);
    pq2_kernel<<<4, 256>>>(pool1, m2w1, p2, q2, NP1);
    edge_kernel<<<4, 256>>>(p2, q2, m2b1, m2w2, m2b2, nbr2, x2f, NP1, 0);

    // pool2 + gap2
    score_kernel<<<4, 256>>>(x2f, p2w, NP1, sc2);
    rank_pool_kernel<<<4, 256>>>(x2f, sc2, NP1, NP2, pool2);
    gap_kernel<<<1, 256>>>(pool2, g2w, g2b, NP2, vec2);

    // final linear
    final_kernel<<<1, 32>>>(vec1, vec2, l2w, l2b, out);
}

// round 9
// speedup vs baseline: 1.9915x; 1.9915x over previous
#include <cuda_runtime.h>
#include <cuda_bf16.h>
#include <mma.h>
#include <math.h>
#include <float.h>
#include <stdint.h>

using namespace nvcuda;

#define T_   32
#define N_   1024
#define D_   128
#define HG   100
#define FEAT 3200
#define HC   16
#define KNN  20
#define NP1  820
#define NP2  656

// ---------------- scratch (device globals; no allocs) ----------------
__device__ float g_bufA[T_*N_*D_];                 // conv3 output fp32 [t][o][h]
__device__ float g_gi[T_*N_*3*HG];
__device__ float g_tfeat[N_*FEAT];
__device__ float g_G[N_*N_];
__device__ float g_diag[N_];
__device__ int   g_nbr1[N_*KNN];
__device__ float g_p1[N_*HC], g_q1[N_*HC];
__device__ float g_x1f[N_*HC];
__device__ float g_sc1[N_];
__device__ float g_pool1[NP1*HC];
__device__ float g_vec1[HC];
__device__ float g_sq2[NP1];
__device__ int   g_nbr2[NP1*KNN];
__device__ float g_p2[NP1*HC], g_q2[NP1*HC];
__device__ float g_x2f[NP1*HC];
__device__ float g_sc2[NP1];
__device__ float g_pool2[NP2*HC];
__device__ float g_vec2[HC];
// bf16 hi/lo padded transposed activations: [t][132 rows][1024 ch]
__device__ __nv_bfloat16 g_xa_hi[T_*132*1024];
__device__ __nv_bfloat16 g_xa_lo[T_*132*1024];
__device__ __nv_bfloat16 g_xb_hi[T_*132*1024];
__device__ __nv_bfloat16 g_xb_lo[T_*132*1024];
// repacked weights [k][o][ic] bf16 hi/lo
__device__ __nv_bfloat16 g_wk_hi[5*1024*1024];
__device__ __nv_bfloat16 g_wk_lo[5*1024*1024];

// ---------------- prep kernels ----------------
__global__ void prep_w_kernel(const float* __restrict__ w,
                              __nv_bfloat16* __restrict__ whi, __nv_bfloat16* __restrict__ wlo)
{
    int idx = blockIdx.x * 256 + threadIdx.x;
    if (idx >= 5 * 1024 * 1024) return;
    int k = idx >> 20, o = (idx >> 10) & 1023, ic = idx & 1023;
    float v = w[(size_t)o * 5120 + ic * 5 + k];
    __nv_bfloat16 h = __float2bfloat16(v);
    whi[idx] = h;
    wlo[idx] = __float2bfloat16(v - __bfloat162float(h));
}

// transpose+split: in fp32 [t][c][128] -> Xp bf16 [t][h+2][c]
__global__ void prep_x_kernel(const float* __restrict__ in,
                              __nv_bfloat16* __restrict__ xhi, __nv_bfloat16* __restrict__ xlo)
{
    __shared__ float tile[32][33];
    int t = blockIdx.z, c0 = blockIdx.x * 32, h0 = blockIdx.y * 32;
    int lx = threadIdx.x & 31, ly = threadIdx.x >> 5;
#pragma unroll
    for (int i = 0; i < 4; i++) {
        int c = c0 + ly + i * 8;
        tile[ly + i * 8][lx] = in[((size_t)t * 1024 + c) * 128 + h0 + lx];
    }
    __syncthreads();
#pragma unroll
    for (int i = 0; i < 4; i++) {
        int h = h0 + ly + i * 8;
        float v = tile[lx][ly + i * 8];
        __nv_bfloat16 hb = __float2bfloat16(v);
        size_t o = ((size_t)t * 132 + h + 2) * 1024 + c0 + lx;
        xhi[o] = hb;
        xlo[o] = __float2bfloat16(v - __bfloat162float(hb));
    }
}

__global__ void zero_pad_kernel(__nv_bfloat16* a, __nv_bfloat16* b,
                                __nv_bfloat16* c, __nv_bfloat16* d)
{
    int idx = blockIdx.x * 256 + threadIdx.x;   // 32t * 4rows * 1024
    if (idx >= 32 * 4 * 1024) return;
    int t = idx >> 12, r = (idx >> 10) & 3, ic = idx & 1023;
    int hp = (r < 2) ? r : 128 + r;
    size_t o = ((size_t)t * 132 + hp) * 1024 + ic;
    __nv_bfloat16 z = __float2bfloat16(0.f);
    a[o] = z; b[o] = z; c[o] = z; d[o] = z;
}

// ---------------- wmma conv kernel ----------------
// grid (8 o-tiles, 32 t), 256 thr (8 warps). C[o, h] = sum_{k,ic} Wk[o,ic]*Xp[t][h+k][ic]
// smem: X [2 splits][132 rows][72], W [2 splits][128 rows][72]; epilogue reuses as f32 [128][132]
#define XLD 72
#define XS_ELEMS (2*132*XLD)
#define WS_ELEMS (2*128*XLD)
#define CV_SMEM ((XS_ELEMS + WS_ELEMS) * 2)

__global__ __launch_bounds__(256)
void conv_wmma_kernel(const __nv_bfloat16* __restrict__ xhi, const __nv_bfloat16* __restrict__ xlo,
                      const __nv_bfloat16* __restrict__ whi, const __nv_bfloat16* __restrict__ wlo,
                      const float* __restrict__ bias,
                      __nv_bfloat16* __restrict__ ohi, __nv_bfloat16* __restrict__ olo,
                      float* __restrict__ of32, int mode)
{
    extern __shared__ char smem[];
    __nv_bfloat16* Xs = (__nv_bfloat16*)smem;
    __nv_bfloat16* Wsm = Xs + XS_ELEMS;
    float* cs = (float*)smem;                       // aliased epilogue buffer [128][132]

    const int tid = threadIdx.x;
    const int wid = tid >> 5;
    const int o0 = blockIdx.x * 128;
    const int t  = blockIdx.y;
    const int m0 = (wid >> 1) * 32;                 // warp row offset (o)
    const int n0 = (wid & 1) * 64;                  // warp col offset (h)

    wmma::fragment<wmma::accumulator, 16, 16, 16, float> acc[2][4];
#pragma unroll
    for (int i = 0; i < 2; i++)
#pragma unroll
        for (int j = 0; j < 4; j++) wmma::fill_fragment(acc[i][j], 0.f);

    for (int ch = 0; ch < 16; ch++) {
        const int ic0 = ch << 6;
        for (int s = 0; s < 5; s++) {
            __syncthreads();                        // previous reads done
            if (s == 0) {
                for (int u = tid; u < 2112; u += 256) {      // X: 2 splits x 132 x 8 uint4
                    int p = (u >= 1056) ? 1 : 0;
                    int r = u - p * 1056;
                    int row = r >> 3, cb = (r & 7) << 3;
                    const __nv_bfloat16* src = (p ? xlo : xhi)
                        + (((size_t)t * 132 + row) << 10) + ic0 + cb;
                    *(uint4*)(Xs + p * (132*XLD) + row * XLD + cb) = *(const uint4*)src;
                }
            }
            for (int u = tid; u < 2048; u += 256) {          // W_s: 2 splits x 128 x 8 uint4
                int p = (u >= 1024) ? 1 : 0;
                int r = u - p * 1024;
                int row = r >> 3, cb = (r & 7) << 3;
                const __nv_bfloat16* src = (p ? wlo : whi)
                    + ((size_t)s << 20) + ((size_t)(o0 + row) << 10) + ic0 + cb;
                *(uint4*)(Wsm + p * (128*XLD) + row * XLD + cb) = *(const uint4*)src;
            }
            __syncthreads();

#pragma unroll
            for (int pass = 0; pass < 3; pass++) {
                const __nv_bfloat16* Ab = Wsm + ((pass == 2) ? 128*XLD : 0);
                const __nv_bfloat16* Bb = Xs + ((pass == 1) ? 132*XLD : 0) + (size_t)s * XLD;
#pragma unroll
                for (int ks = 0; ks < 4; ks++) {
                    wmma::fragment<wmma::matrix_a, 16, 16, 16, __nv_bfloat16, wmma::row_major> a[2];
                    wmma::fragment<wmma::matrix_b, 16, 16, 16, __nv_bfloat16, wmma::col_major> b;
#pragma unroll
                    for (int i = 0; i < 2; i++)
                        wmma::load_matrix_sync(a[i], Ab + (m0 + i * 16) * XLD + ks * 16, XLD);
#pragma unroll
                    for (int j = 0; j < 4; j++) {
                        wmma::load_matrix_sync(b, Bb + (n0 + j * 16) * XLD + ks * 16, XLD);
#pragma unroll
                        for (int i = 0; i < 2; i++)
                            wmma::mma_sync(acc[i][j], a[i], b, acc[i][j]);
                    }
                }
            }
        }
    }

    __syncthreads();                                // all mma reads done before aliasing
#pragma unroll
    for (int i = 0; i < 2; i++)
#pragma unroll
        for (int j = 0; j < 4; j++)
            wmma::store_matrix_sync(cs + (m0 + i * 16) * 132 + (n0 + j * 16),
                                    acc[i][j], 132, wmma::mem_row_major);
    __syncthreads();

    if (mode == 0) {
        // write transposed hi/lo: [t][h+2][channel]; channel fastest -> coalesced
        for (int idx = tid; idx < 128 * 128; idx += 256) {
            int o_r = idx & 127, h = idx >> 7;
            float v = cs[o_r * 132 + h] + bias[o0 + o_r];
            v = v > 0.f ? v : 0.1f * v;
            __nv_bfloat16 hb = __float2bfloat16(v);
            size_t g = (((size_t)t * 132) + h + 2) * 1024 + o0 + o_r;
            ohi[g] = hb;
            olo[g] = __float2bfloat16(v - __bfloat162float(hb));
        }
    } else {
        // fp32 [t][o][h]; h fastest -> coalesced
        for (int idx = tid; idx < 128 * 128; idx += 256) {
            int h = idx & 127, o_r = idx >> 7;
            float v = cs[o_r * 132 + h] + bias[o0 + o_r];
            of32[((size_t)t << 17) + (size_t)(o0 + o_r) * 128 + h] = v > 0.f ? v : 0.1f * v;
        }
    }
}

// --------- SGEMM  C[m][n] = sum_k A[m][k]*B[n][k] (+bias[n]) ----------
__global__ __launch_bounds__(256)
void sgemm_nt(const float* __restrict__ A, const float* __restrict__ B,
              const float* __restrict__ bias, float* __restrict__ C,
              int M, int Ncols, int Kd)
{
    __shared__ float As[16][64];
    __shared__ float Bs[16][64];
    const int tid = threadIdx.x;
    const int tx = tid & 15, ty = tid >> 4;
    const int m0 = blockIdx.y * 64, n0 = blockIdx.x * 64;
    float acc[4][4];
#pragma unroll
    for (int i = 0; i < 4; i++)
#pragma unroll
        for (int j = 0; j < 4; j++) acc[i][j] = 0.f;

    for (int k0 = 0; k0 < Kd; k0 += 16) {
#pragma unroll
        for (int l = 0; l < 4; l++) {
            int idx = tid + l * 256;
            int row = idx >> 4, kk = idx & 15;
            As[kk][row] = A[(size_t)(m0 + row) * Kd + k0 + kk];
            Bs[kk][row] = (n0 + row < Ncols) ? B[(size_t)(n0 + row) * Kd + k0 + kk] : 0.f;
        }
        __syncthreads();
#pragma unroll
        for (int k = 0; k < 16; k++) {
            float4 a4 = *(const float4*)&As[k][tx << 2];
            float4 b4 = *(const float4*)&Bs[k][ty << 2];
            float av[4] = {a4.x, a4.y, a4.z, a4.w};
            float bv[4] = {b4.x, b4.y, b4.z, b4.w};
#pragma unroll
            for (int i = 0; i < 4; i++)
#pragma unroll
                for (int j = 0; j < 4; j++) acc[i][j] += av[i] * bv[j];
        }
        __syncthreads();
    }
#pragma unroll
    for (int i = 0; i < 4; i++) {
        int m = m0 + (tx << 2) + i;
#pragma unroll
        for (int j = 0; j < 4; j++) {
            int n = n0 + (ty << 2) + j;
            if (n < Ncols)
                C[(size_t)m * Ncols + n] = acc[i][j] + (bias ? bias[n] : 0.f);
        }
    }
}

// ---------------- GRU over T=32 (8 nodes / block) ----------------
__global__ __launch_bounds__(320)
void gru_kernel(const float* __restrict__ gi, const float* __restrict__ whh,
                const float* __restrict__ bhh, float* __restrict__ tf)
{
    __shared__ float h_s[8][HG];
    __shared__ float gh_s[8][304];
    const int tid = threadIdx.x;
    const int n0 = blockIdx.x * 8;
    for (int p = tid; p < 8 * HG; p += 320) h_s[p / HG][p % HG] = 0.f;
    __syncthreads();

    for (int t = 0; t < T_; t++) {
        if (tid < 300) {
            const int j = tid;
            float acc[8];
#pragma unroll
            for (int n = 0; n < 8; n++) acc[n] = 0.f;
            const float4* wr = (const float4*)(whh + (size_t)j * HG);
#pragma unroll 5
            for (int d4 = 0; d4 < HG / 4; d4++) {
                float4 w4 = wr[d4];
#pragma unroll
                for (int n = 0; n < 8; n++) {
                    float4 h4 = ((const float4*)h_s[n])[d4];
                    acc[n] += w4.x*h4.x + w4.y*h4.y + w4.z*h4.z + w4.w*h4.w;
                }
            }
            float bb = bhh[j];
#pragma unroll
            for (int n = 0; n < 8; n++) gh_s[n][j] = acc[n] + bb;
        }
        __syncthreads();
        for (int p = tid; p < 8 * HG; p += 320) {
            int n = p / HG, d = p % HG;
            int ng = n0 + n;
            const float* gin = gi + ((size_t)t * N_ + ng) * (3 * HG);
            float rg = 1.f / (1.f + expf(-(gin[d]        + gh_s[n][d])));
            float zg = 1.f / (1.f + expf(-(gin[HG + d]   + gh_s[n][HG + d])));
            float nn = tanhf(gin[2*HG + d] + rg * gh_s[n][2*HG + d]);
            float hnew = (1.f - zg) * nn + zg * h_s[n][d];
            tf[(size_t)ng * FEAT + t * HG + d] = hnew > 0.f ? hnew : 0.1f * hnew;
            h_s[n][d] = hnew;
        }
        __syncthreads();
    }
}

// ---------------- small kernels ----------------
__global__ void diag_kernel(const float* __restrict__ G, float* __restrict__ dg)
{
    int n = blockIdx.x * blockDim.x + threadIdx.x;
    if (n < N_) dg[n] = G[(size_t)n * N_ + n];
}

__global__ __launch_bounds__(256)
void topk1_kernel(const float* __restrict__ G, const float* __restrict__ dg,
                  int* __restrict__ nbr)
{
    __shared__ float s[N_];
    __shared__ float rv[8]; __shared__ int ri[8];
    const int i = blockIdx.x, tid = threadIdx.x;
    const float dii = dg[i];
    for (int j = tid; j < N_; j += 256) s[j] = 2.f * G[(size_t)i * N_ + j] - dii - dg[j];
    __syncthreads();
    for (int it = 0; it < KNN; it++) {
        float bv = -FLT_MAX; int bi = 1 << 30;
        for (int j = tid; j < N_; j += 256) {
            float v = s[j];
            if (v > bv || (v == bv && j < bi)) { bv = v; bi = j; }
        }
        for (int off = 16; off; off >>= 1) {
            float ov = __shfl_down_sync(0xffffffffu, bv, off);
            int   oi = __shfl_down_sync(0xffffffffu, bi, off);
            if (ov > bv || (ov == bv && oi < bi)) { bv = ov; bi = oi; }
        }
        if ((tid & 31) == 0) { rv[tid >> 5] = bv; ri[tid >> 5] = bi; }
        __syncthreads();
        if (tid == 0) {
            float fv = rv[0]; int fi = ri[0];
            for (int w = 1; w < 8; w++)
                if (rv[w] > fv || (rv[w] == fv && ri[w] < fi)) { fv = rv[w]; fi = ri[w]; }
            nbr[i * KNN + it] = fi;
            s[fi] = -FLT_MAX;
        }
        __syncthreads();
    }
}

__global__ __launch_bounds__(256)
void topk2_kernel(const float* __restrict__ x, const float* __restrict__ sq,
                  int Nn, int* __restrict__ nbr)
{
    __shared__ float s[NP1 + 12];
    __shared__ float xi[HC];
    __shared__ float rv[8]; __shared__ int ri[8];
    const int i = blockIdx.x, tid = threadIdx.x;
    if (tid < HC) xi[tid] = x[(size_t)i * HC + tid];
    __syncthreads();
    const float sqi = sq[i];
    for (int j = tid; j < Nn; j += 256) {
        const float* xj = x + (size_t)j * HC;
        float dot = 0.f;
#pragma unroll
        for (int c = 0; c < HC; c++) dot += xi[c] * xj[c];
        s[j] = 2.f * dot - sqi - sq[j];
    }
    __syncthreads();
    for (int it = 0; it < KNN; it++) {
        float bv = -FLT_MAX; int bi = 1 << 30;
        for (int j = tid; j < Nn; j += 256) {
            float v = s[j];
            if (v > bv || (v == bv && j < bi)) { bv = v; bi = j; }
        }
        for (int off = 16; off; off >>= 1) {
            float ov = __shfl_down_sync(0xffffffffu, bv, off);
            int   oi = __shfl_down_sync(0xffffffffu, bi, off);
            if (ov > bv || (ov == bv && oi < bi)) { bv = ov; bi = oi; }
        }
        if ((tid & 31) == 0) { rv[tid >> 5] = bv; ri[tid >> 5] = bi; }
        __syncthreads();
        if (tid == 0) {
            float fv = rv[0]; int fi = ri[0];
            for (int w = 1; w < 8; w++)
                if (rv[w] > fv || (rv[w] == fv && ri[w] < fi)) { fv = rv[w]; fi = ri[w]; }
            nbr[i * KNN + it] = fi;
            s[fi] = -FLT_MAX;
        }
        __syncthreads();
    }
}

__global__ __launch_bounds__(256)
void pq1_kernel(const float* __restrict__ tf, const float* __restrict__ w1,
                float* __restrict__ p, float* __restrict__ q)
{
    __shared__ float redm[8][32];
    const int n = blockIdx.x, tid = threadIdx.x;
    float ap[HC], aq[HC];
#pragma unroll
    for (int c = 0; c < HC; c++) { ap[c] = 0.f; aq[c] = 0.f; }
    for (int f = tid; f < FEAT; f += 256) {
        float xv = tf[(size_t)n * FEAT + f];
        const float4* wp = (const float4*)(w1 + (size_t)f * HC);
        const float4* wq = (const float4*)(w1 + (size_t)(FEAT + f) * HC);
#pragma unroll
        for (int c4 = 0; c4 < 4; c4++) {
            float4 a = wp[c4];
            ap[c4*4+0] += xv*a.x; ap[c4*4+1] += xv*a.y;
            ap[c4*4+2] += xv*a.z; ap[c4*4+3] += xv*a.w;
            float4 b = wq[c4];
            aq[c4*4+0] += xv*b.x; aq[c4*4+1] += xv*b.y;
            aq[c4*4+2] += xv*b.z; aq[c4*4+3] += xv*b.w;
        }
    }
    const int lane = tid & 31, wid = tid >> 5;
    for (int c = 0; c < 32; c++) {
        float v = (c < HC) ? ap[c] : aq[c - HC];
        for (int off = 16; off; off >>= 1) v += __shfl_down_sync(0xffffffffu, v, off);
        if (lane == 0) redm[wid][c] = v;
    }
    __syncthreads();
    if (tid < 32) {
        float v = 0.f;
        for (int w = 0; w < 8; w++) v += redm[w][tid];
        if (tid < HC) p[(size_t)n * HC + tid] = v;
        else          q[(size_t)n * HC + tid - HC] = v;
    }
}

__global__ __launch_bounds__(256)
void pq2_kernel(const float* __restrict__ x, const float* __restrict__ w1,
                float* __restrict__ p, float* __restrict__ q, int Nn)
{
    int n = blockIdx.x * blockDim.x + threadIdx.x;
    if (n >= Nn) return;
    float xi[HC];
#pragma unroll
    for (int c = 0; c < HC; c++) xi[c] = x[(size_t)n * HC + c];
#pragma unroll
    for (int c = 0; c < HC; c++) {
        float pp = 0.f, qq = 0.f;
#pragma unroll
        for (int u = 0; u < HC; u++) {
            pp += xi[u] * w1[u * HC + c];
            qq += xi[u] * w1[(HC + u) * HC + c];
        }
        p[(size_t)n * HC + c] = pp;
        q[(size_t)n * HC + c] = qq;
    }
}

__global__ __launch_bounds__(256)
void edge_kernel(const float* __restrict__ p, const float* __restrict__ q,
                 const float* __restrict__ b1, const float* __restrict__ w2,
                 const float* __restrict__ b2, const int* __restrict__ nbr,
                 float* __restrict__ out, int Nn, int doRelu)
{
    __shared__ float w2s[HC*HC];
    __shared__ float b1s[HC], b2s[HC];
    const int tid = threadIdx.x;
    if (tid < HC*HC) w2s[tid] = w2[tid];
    if (tid < HC) { b1s[tid] = b1[tid]; b2s[tid] = b2[tid]; }
    __syncthreads();
    const int n = blockIdx.x * blockDim.x + tid;
    if (n >= Nn) return;
    float base[HC], best[HC];
#pragma unroll
    for (int c = 0; c < HC; c++) {
        base[c] = p[(size_t)n*HC + c] - q[(size_t)n*HC + c] + b1s[c];
        best[c] = -FLT_MAX;
    }
    for (int kk = 0; kk < KNN; kk++) {
        int j = nbr[n * KNN + kk];
        const float* qj = q + (size_t)j * HC;
        float o[HC];
#pragma unroll
        for (int c = 0; c < HC; c++) o[c] = b2s[c];
#pragma unroll
        for (int u = 0; u < HC; u++) {
            float hv = base[u] + qj[u];
            hv = hv > 0.f ? hv : 0.f;
#pragma unroll
            for (int c = 0; c < HC; c++) o[c] += hv * w2s[u*HC + c];
        }
#pragma unroll
        for (int c = 0; c < HC; c++) best[c] = fmaxf(best[c], o[c]);
    }
#pragma unroll
    for (int c = 0; c < HC; c++) {
        float v = best[c];
        if (doRelu) v = fmaxf(v, 0.f);
        out[(size_t)n * HC + c] = v;
    }
}

__global__ void score_kernel(const float* __restrict__ x, const float* __restrict__ w,
                             int Nn, float* __restrict__ s)
{
    int n = blockIdx.x * blockDim.x + threadIdx.x;
    if (n >= Nn) return;
    float nw = 0.f, d = 0.f;
#pragma unroll
    for (int c = 0; c < HC; c++) nw += w[c] * w[c];
    nw = sqrtf(nw);
#pragma unroll
    for (int c = 0; c < HC; c++) d += x[(size_t)n*HC + c] * w[c];
    s[n] = tanhf(d / nw);
}

__global__ void sq_kernel(const float* __restrict__ x, int Nn, float* __restrict__ sq)
{
    int n = blockIdx.x * blockDim.x + threadIdx.x;
    if (n >= Nn) return;
    float a = 0.f;
#pragma unroll
    for (int c = 0; c < HC; c++) { float v = x[(size_t)n*HC + c]; a += v * v; }
    sq[n] = a;
}

__global__ void rank_pool_kernel(const float* __restrict__ x, const float* __restrict__ s,
                                 int Nn, int nkeep, float* __restrict__ out)
{
    int n = blockIdx.x * blockDim.x + threadIdx.x;
    if (n >= Nn) return;
    float sn = s[n];
    int rank = 0;
    for (int m = 0; m < Nn; m++) {
        float sm = s[m];
        if (sm > sn || (sm == sn && m < n)) rank++;
    }
    if (rank < nkeep) {
#pragma unroll
        for (int c = 0; c < HC; c++)
            out[(size_t)rank * HC + c] = x[(size_t)n * HC + c] * sn;
    }
}

__global__ __launch_bounds__(256)
void gap_kernel(const float* __restrict__ x, const float* __restrict__ gw,
                const float* __restrict__ gb, int Nn, float* __restrict__ vec)
{
    __shared__ float a[NP1 + 12];
    __shared__ float red[8];
    const int tid = threadIdx.x;
    float lmax = -FLT_MAX;
    for (int n = tid; n < Nn; n += 256) {
        float d = gb[0];
#pragma unroll
        for (int c = 0; c < HC; c++) d += x[(size_t)n*HC + c] * gw[c];
        a[n] = d;
        lmax = fmaxf(lmax, d);
    }
    for (int off = 16; off; off >>= 1) lmax = fmaxf(lmax, __shfl_xor_sync(0xffffffffu, lmax, off));
    if ((tid & 31) == 0) red[tid >> 5] = lmax;
    __syncthreads();
    lmax = red[0];
    for (int w = 1; w < 8; w++) lmax = fmaxf(lmax, red[w]);
    __syncthreads();
    float lsum = 0.f;
    for (int n = tid; n < Nn; n += 256) {
        float e = expf(a[n] - lmax);
        a[n] = e;
        lsum += e;
    }
    for (int off = 16; off; off >>= 1) lsum += __shfl_xor_sync(0xffffffffu, lsum, off);
    if ((tid & 31) == 0) red[tid >> 5] = lsum;
    __syncthreads();
    lsum = 0.f;
    for (int w = 0; w < 8; w++) lsum += red[w];
    if (tid < HC) {
        float v = 0.f;
        for (int n = 0; n < Nn; n++) v += a[n] * x[(size_t)n*HC + tid];
        vec[tid] = v / lsum;
    }
}

__global__ void final_kernel(const float* __restrict__ v1, const float* __restrict__ v2,
                             const float* __restrict__ w, const float* __restrict__ b,
                             float* __restrict__ out)
{
    int c = threadIdx.x;
    if (c < 2) {
        float acc = b[c];
#pragma unroll
        for (int u = 0; u < HC; u++) acc += (v1[u] + v2[u]) * w[u*2 + c];
        out[c] = acc;
    }
}

// ---------------- launch ----------------
extern "C" void kernel_launch(void* const* d_in, const int* in_sizes, int n_in,
                              void* d_out, int out_size)
{
    const float* ts   = (const float*)d_in[0];
    const float* c1w  = (const float*)d_in[1];
    const float* c1b  = (const float*)d_in[2];
    const float* c2w  = (const float*)d_in[3];
    const float* c2b  = (const float*)d_in[4];
    const float* c3w  = (const float*)d_in[5];
    const float* c3b  = (const float*)d_in[6];
    const float* wih  = (const float*)d_in[7];
    const float* whh  = (const float*)d_in[8];
    const float* bih  = (const float*)d_in[9];
    const float* bhh  = (const float*)d_in[10];
    const float* m1w1 = (const float*)d_in[11];
    const float* m1b1 = (const float*)d_in[12];
    const float* m1w2 = (const float*)d_in[13];
    const float* m1b2 = (const float*)d_in[14];
    const float* p1w  = (const float*)d_in[15];
    const float* g1w  = (const float*)d_in[16];
    const float* g1b  = (const float*)d_in[17];
    const float* m2w1 = (const float*)d_in[18];
    const float* m2b1 = (const float*)d_in[19];
    const float* m2w2 = (const float*)d_in[20];
    const float* m2b2 = (const float*)d_in[21];
    const float* p2w  = (const float*)d_in[22];
    const float* g2w  = (const float*)d_in[23];
    const float* g2b  = (const float*)d_in[24];
    const float* l2w  = (const float*)d_in[25];
    const float* l2b  = (const float*)d_in[26];
    float* out        = (float*)d_out;

    float *bufA, *gi, *tf, *G, *dg, *p1, *q1, *x1f, *sc1, *pool1, *vec1;
    float *sq2, *p2, *q2, *x2f, *sc2, *pool2, *vec2;
    int *nbr1, *nbr2;
    __nv_bfloat16 *xa_hi, *xa_lo, *xb_hi, *xb_lo, *wk_hi, *wk_lo;
    cudaGetSymbolAddress((void**)&bufA,  g_bufA);
    cudaGetSymbolAddress((void**)&gi,    g_gi);
    cudaGetSymbolAddress((void**)&tf,    g_tfeat);
    cudaGetSymbolAddress((void**)&G,     g_G);
    cudaGetSymbolAddress((void**)&dg,    g_diag);
    cudaGetSymbolAddress((void**)&nbr1,  g_nbr1);
    cudaGetSymbolAddress((void**)&p1,    g_p1);
    cudaGetSymbolAddress((void**)&q1,    g_q1);
    cudaGetSymbolAddress((void**)&x1f,   g_x1f);
    cudaGetSymbolAddress((void**)&sc1,   g_sc1);
    cudaGetSymbolAddress((void**)&pool1, g_pool1);
    cudaGetSymbolAddress((void**)&vec1,  g_vec1);
    cudaGetSymbolAddress((void**)&sq2,   g_sq2);
    cudaGetSymbolAddress((void**)&nbr2,  g_nbr2);
    cudaGetSymbolAddress((void**)&p2,    g_p2);
    cudaGetSymbolAddress((void**)&q2,    g_q2);
    cudaGetSymbolAddress((void**)&x2f,   g_x2f);
    cudaGetSymbolAddress((void**)&sc2,   g_sc2);
    cudaGetSymbolAddress((void**)&pool2, g_pool2);
    cudaGetSymbolAddress((void**)&vec2,  g_vec2);
    cudaGetSymbolAddress((void**)&xa_hi, g_xa_hi);
    cudaGetSymbolAddress((void**)&xa_lo, g_xa_lo);
    cudaGetSymbolAddress((void**)&xb_hi, g_xb_hi);
    cudaGetSymbolAddress((void**)&xb_lo, g_xb_lo);
    cudaGetSymbolAddress((void**)&wk_hi, g_wk_hi);
    cudaGetSymbolAddress((void**)&wk_lo, g_wk_lo);

    cudaFuncSetAttribute(conv_wmma_kernel, cudaFuncAttributeMaxDynamicSharedMemorySize, CV_SMEM);

    // prep: pad zeros, transpose input, repack weights
    zero_pad_kernel<<<512, 256>>>(xa_hi, xa_lo, xb_hi, xb_lo);
    prep_x_kernel<<<dim3(32, 4, 32), 256>>>(ts, xa_hi, xa_lo);
    prep_w_kernel<<<20480, 256>>>(c1w, wk_hi, wk_lo);
    conv_wmma_kernel<<<dim3(8, 32), 256, CV_SMEM>>>(xa_hi, xa_lo, wk_hi, wk_lo, c1b,
                                                    xb_hi, xb_lo, nullptr, 0);
    prep_w_kernel<<<20480, 256>>>(c2w, wk_hi, wk_lo);
    conv_wmma_kernel<<<dim3(8, 32), 256, CV_SMEM>>>(xb_hi, xb_lo, wk_hi, wk_lo, c2b,
                                                    xa_hi, xa_lo, nullptr, 0);
    prep_w_kernel<<<20480, 256>>>(c3w, wk_hi, wk_lo);
    conv_wmma_kernel<<<dim3(8, 32), 256, CV_SMEM>>>(xa_hi, xa_lo, wk_hi, wk_lo, c3b,
                                                    nullptr, nullptr, bufA, 1);

    // gi = d @ wih.T + bih
    sgemm_nt<<<dim3(5, (T_*N_)/64), 256>>>(bufA, wih, bih, gi, T_*N_, 3*HG, D_);
    gru_kernel<<<N_/8, 320>>>(gi, whh, bhh, tf);

    // Gram + knn1
    sgemm_nt<<<dim3(16, 16), 256>>>(tf, tf, nullptr, G, N_, N_, FEAT);
    diag_kernel<<<4, 256>>>(G, dg);
    topk1_kernel<<<N_, 256>>>(G, dg, nbr1);

    // DGCN1
    pq1_kernel<<<N_, 256>>>(tf, m1w1, p1, q1);
    edge_kernel<<<4, 256>>>(p1, q1, m1b1, m1w2, m1b2, nbr1, x1f, N_, 1);

    score_kernel<<<4, 256>>>(x1f, p1w, N_, sc1);
    rank_pool_kernel<<<4, 256>>>(x1f, sc1, N_, NP1, pool1);
    gap_kernel<<<1, 256>>>(pool1, g1w, g1b, NP1, vec1);

    // DGCN2
    sq_kernel<<<4, 256>>>(pool1, NP1, sq2);
    topk2_kernel<<<NP1, 256>>>(pool1, sq2, NP1, nbr2);
    pq2_kernel<<<4, 256>>>(pool1, m2w1, p2, q2, NP1);
    edge_kernel<<<4, 256>>>(p2, q2, m2b1, m2w2, m2b2, nbr2, x2f, NP1, 0);

    score_kernel<<<4, 256>>>(x2f, p2w, NP1, sc2);
    rank_pool_kernel<<<4, 256>>>(x2f, sc2, NP1, NP2, pool2);
    gap_kernel<<<1, 256>>>(pool2, g2w, g2b, NP2, vec2);

    final_kernel<<<1, 32>>>(vec1, vec2, l2w, l2b, out);
}

// round 10
// speedup vs baseline: 2.5721x; 1.2915x over previous
#include <cuda_runtime.h>
#include <cuda_bf16.h>
#include <mma.h>
#include <math.h>
#include <float.h>
#include <stdint.h>

using namespace nvcuda;

#define T_   32
#define N_   1024
#define D_   128
#define HG   100
#define FEAT 3200
#define HC   16
#define KNN  20
#define NP1  820
#define NP2  656

// ---------------- scratch (device globals; no allocs) ----------------
__device__ float g_gi[T_*N_*3*HG];
__device__ float g_tfeat[N_*FEAT];
__device__ __nv_bfloat16 g_tf_hi[N_*FEAT];
__device__ __nv_bfloat16 g_tf_lo[N_*FEAT];
__device__ float g_G[N_*N_];
__device__ float g_diag[N_];
__device__ int   g_nbr1[N_*KNN];
__device__ float g_p1[N_*HC], g_q1[N_*HC];
__device__ float g_x1f[N_*HC];
__device__ float g_sc1[N_];
__device__ float g_pool1[NP1*HC];
__device__ float g_vec1[HC];
__device__ float g_sq2[NP1];
__device__ int   g_nbr2[NP1*KNN];
__device__ float g_p2[NP1*HC], g_q2[NP1*HC];
__device__ float g_x2f[NP1*HC];
__device__ float g_sc2[NP1];
__device__ float g_pool2[NP2*HC];
__device__ float g_vec2[HC];
// bf16 hi/lo padded transposed activations: [t][132 rows][1024 ch]
__device__ __nv_bfloat16 g_xa_hi[T_*132*1024];
__device__ __nv_bfloat16 g_xa_lo[T_*132*1024];
__device__ __nv_bfloat16 g_xb_hi[T_*132*1024];   // also reused as gi-A [32768][128]
__device__ __nv_bfloat16 g_xb_lo[T_*132*1024];
// repacked weights [k][o][ic] bf16 hi/lo
__device__ __nv_bfloat16 g_wk_hi[5*1024*1024];
__device__ __nv_bfloat16 g_wk_lo[5*1024*1024];
__device__ __nv_bfloat16 g_wih_hi[3*HG*D_];
__device__ __nv_bfloat16 g_wih_lo[3*HG*D_];

// ---------------- cp.async helpers ----------------
__device__ __forceinline__ uint32_t smem_u32(const void* p) {
    uint32_t a;
    asm("{ .reg .u64 t; cvta.to.shared.u64 t, %1; cvt.u32.u64 %0, t; }" : "=r"(a) : "l"(p));
    return a;
}
__device__ __forceinline__ void cpa16(uint32_t dst, const void* src) {
    asm volatile("cp.async.cg.shared.global [%0], [%1], 16;" :: "r"(dst), "l"(src));
}
#define CPA_COMMIT asm volatile("cp.async.commit_group;" ::: "memory")
#define CPA_WAIT0  asm volatile("cp.async.wait_group 0;" ::: "memory")

// ---------------- prep kernels ----------------
__global__ void prep_w_kernel(const float* __restrict__ w,
                              __nv_bfloat16* __restrict__ whi, __nv_bfloat16* __restrict__ wlo)
{
    int idx = blockIdx.x * 256 + threadIdx.x;
    if (idx >= 5 * 1024 * 1024) return;
    int k = idx >> 20, o = (idx >> 10) & 1023, ic = idx & 1023;
    float v = w[(size_t)o * 5120 + ic * 5 + k];
    __nv_bfloat16 h = __float2bfloat16(v);
    whi[idx] = h;
    wlo[idx] = __float2bfloat16(v - __bfloat162float(h));
}

__global__ void split_kernel(const float* __restrict__ in,
                             __nv_bfloat16* __restrict__ hi, __nv_bfloat16* __restrict__ lo, int n)
{
    int i = blockIdx.x * 256 + threadIdx.x;
    if (i >= n) return;
    float v = in[i];
    __nv_bfloat16 h = __float2bfloat16(v);
    hi[i] = h;
    lo[i] = __float2bfloat16(v - __bfloat162float(h));
}

// transpose+split: in fp32 [t][c][128] -> Xp bf16 [t][h+2][c]
__global__ void prep_x_kernel(const float* __restrict__ in,
                              __nv_bfloat16* __restrict__ xhi, __nv_bfloat16* __restrict__ xlo)
{
    __shared__ float tile[32][33];
    int t = blockIdx.z, c0 = blockIdx.x * 32, h0 = blockIdx.y * 32;
    int lx = threadIdx.x & 31, ly = threadIdx.x >> 5;
#pragma unroll
    for (int i = 0; i < 4; i++) {
        int c = c0 + ly + i * 8;
        tile[ly + i * 8][lx] = in[((size_t)t * 1024 + c) * 128 + h0 + lx];
    }
    __syncthreads();
#pragma unroll
    for (int i = 0; i < 4; i++) {
        int h = h0 + ly + i * 8;
        float v = tile[lx][ly + i * 8];
        __nv_bfloat16 hb = __float2bfloat16(v);
        size_t o = ((size_t)t * 132 + h + 2) * 1024 + c0 + lx;
        xhi[o] = hb;
        xlo[o] = __float2bfloat16(v - __bfloat162float(hb));
    }
}

__global__ void zero_pad_kernel(__nv_bfloat16* a, __nv_bfloat16* b,
                                __nv_bfloat16* c, __nv_bfloat16* d)
{
    int idx = blockIdx.x * 256 + threadIdx.x;   // 32t * 4rows * 1024
    if (idx >= 32 * 4 * 1024) return;
    int t = idx >> 12, r = (idx >> 10) & 3, ic = idx & 1023;
    int hp = (r < 2) ? r : 128 + r;
    size_t o = ((size_t)t * 132 + hp) * 1024 + ic;
    __nv_bfloat16 z = __float2bfloat16(0.f);
    a[o] = z; b[o] = z; c[o] = z; d[o] = z;
}

// ---------------- wmma conv kernel (cp.async double-buffered) ----------------
// grid (8 o-tiles, 32 t), 256 thr (8 warps). C[o, h] = sum_{k,ic} Wk[o,ic]*Xp[t][h+k][ic]
// smem bytes: X ping-pong 2 x (2 splits x 132 x 72 bf16 = 38016), at 0
//             W ping-pong 2 x (2 splits x 128 x 72 bf16 = 36864), at 76032
#define XLD 72
#define CV_XB 38016u
#define CV_WOFF 76032u
#define CV_WB 36864u
#define CV_SMEM 149760

__device__ __forceinline__ void conv_issue_stage(
    int qq, int tid, int t, int o0, uint32_t smX, uint32_t smW,
    const __nv_bfloat16* xhi, const __nv_bfloat16* xlo,
    const __nv_bfloat16* whi, const __nv_bfloat16* wlo)
{
    const int ch = qq / 5, s = qq % 5, ic0 = ch << 6;
    const uint32_t wb = smW + (uint32_t)(qq & 1) * CV_WB;
    for (int u = tid; u < 2048; u += 256) {
        int p = u >> 10, r = u & 1023;
        int row = r >> 3, cb = (r & 7) << 3;
        const __nv_bfloat16* src = (p ? wlo : whi)
            + ((size_t)s << 20) + ((size_t)(o0 + row) << 10) + ic0 + cb;
        cpa16(wb + (uint32_t)(p * 128 + row) * 144u + cb * 2, src);
    }
    if (s == 0) {
        const uint32_t xb = smX + (uint32_t)(ch & 1) * CV_XB;
        for (int u = tid; u < 2112; u += 256) {
            int p = (u >= 1056) ? 1 : 0;
            int r = u - p * 1056;
            int row = r >> 3, cb = (r & 7) << 3;
            const __nv_bfloat16* src = (p ? xlo : xhi)
                + (((size_t)t * 132 + row) << 10) + ic0 + cb;
            cpa16(xb + (uint32_t)(p * 132 + row) * 144u + cb * 2, src);
        }
    }
    CPA_COMMIT;
}

__global__ __launch_bounds__(256)
void conv_wmma_kernel(const __nv_bfloat16* __restrict__ xhi, const __nv_bfloat16* __restrict__ xlo,
                      const __nv_bfloat16* __restrict__ whi, const __nv_bfloat16* __restrict__ wlo,
                      const float* __restrict__ bias,
                      __nv_bfloat16* __restrict__ ohi, __nv_bfloat16* __restrict__ olo,
                      int mode)
{
    extern __shared__ char smem[];
    const uint32_t smX = smem_u32(smem);
    const uint32_t smW = smX + CV_WOFF;
    float* cs = (float*)smem;                       // aliased epilogue buffer [128][132]

    const int tid = threadIdx.x;
    const int wid = tid >> 5;
    const int o0 = blockIdx.x * 128;
    const int t  = blockIdx.y;
    const int m0 = (wid >> 1) * 32;                 // warp row offset (o)
    const int n0 = (wid & 1) * 64;                  // warp col offset (h)

    wmma::fragment<wmma::accumulator, 16, 16, 16, float> acc[2][4];
#pragma unroll
    for (int i = 0; i < 2; i++)
#pragma unroll
        for (int j = 0; j < 4; j++) wmma::fill_fragment(acc[i][j], 0.f);

    conv_issue_stage(0, tid, t, o0, smX, smW, xhi, xlo, whi, wlo);

    for (int q = 0; q < 80; q++) {
        const int ch = q / 5, s = q % 5;
        CPA_WAIT0;
        __syncthreads();
        if (q < 79)
            conv_issue_stage(q + 1, tid, t, o0, smX, smW, xhi, xlo, whi, wlo);

        const __nv_bfloat16* Xbase = (const __nv_bfloat16*)(smem) + (size_t)(ch & 1) * (2*132*XLD);
        const __nv_bfloat16* Wbase = (const __nv_bfloat16*)(smem + CV_WOFF) + (size_t)(q & 1) * (2*128*XLD);

#pragma unroll
        for (int pass = 0; pass < 3; pass++) {
            const __nv_bfloat16* Ab = Wbase + ((pass == 2) ? 128*XLD : 0);
            const __nv_bfloat16* Bb = Xbase + ((pass == 1) ? 132*XLD : 0) + (size_t)s * XLD;
#pragma unroll
            for (int ks = 0; ks < 4; ks++) {
                wmma::fragment<wmma::matrix_a, 16, 16, 16, __nv_bfloat16, wmma::row_major> a[2];
                wmma::fragment<wmma::matrix_b, 16, 16, 16, __nv_bfloat16, wmma::col_major> b;
#pragma unroll
                for (int i = 0; i < 2; i++)
                    wmma::load_matrix_sync(a[i], Ab + (m0 + i * 16) * XLD + ks * 16, XLD);
#pragma unroll
                for (int j = 0; j < 4; j++) {
                    wmma::load_matrix_sync(b, Bb + (n0 + j * 16) * XLD + ks * 16, XLD);
#pragma unroll
                    for (int i = 0; i < 2; i++)
                        wmma::mma_sync(acc[i][j], a[i], b, acc[i][j]);
                }
            }
        }
    }

    __syncthreads();                                // all mma reads done before aliasing
#pragma unroll
    for (int i = 0; i < 2; i++)
#pragma unroll
        for (int j = 0; j < 4; j++)
            wmma::store_matrix_sync(cs + (m0 + i * 16) * 132 + (n0 + j * 16),
                                    acc[i][j], 132, wmma::mem_row_major);
    __syncthreads();

    if (mode == 0) {
        // write transposed hi/lo: [t][h+2][channel]; channel fastest -> coalesced
        for (int idx = tid; idx < 128 * 128; idx += 256) {
            int o_r = idx & 127, h = idx >> 7;
            float v = cs[o_r * 132 + h] + bias[o0 + o_r];
            v = v > 0.f ? v : 0.1f * v;
            __nv_bfloat16 hb = __float2bfloat16(v);
            size_t g = (((size_t)t * 132) + h + 2) * 1024 + o0 + o_r;
            ohi[g] = hb;
            olo[g] = __float2bfloat16(v - __bfloat162float(hb));
        }
    } else {
        // hi/lo row-major [(t*1024 + o)][h]; h fastest -> coalesced
        for (int idx = tid; idx < 128 * 128; idx += 256) {
            int h = idx & 127, o_r = idx >> 7;
            float v = cs[o_r * 132 + h] + bias[o0 + o_r];
            v = v > 0.f ? v : 0.1f * v;
            __nv_bfloat16 hb = __float2bfloat16(v);
            size_t g = ((size_t)t * 1024 + o0 + o_r) * 128 + h;
            ohi[g] = hb;
            olo[g] = __float2bfloat16(v - __bfloat162float(hb));
        }
    }
}

// ------------- generic 3-pass bf16 wmma GEMM-NT -------------
// C[m][n] = sum_k A[m][k]*B[n][k] (+bias[n]); M%128==0, K%64==0, N guarded.
// grid (ceil(N/64), M/128), 256 thr, 8 warps (4x2), warp tile 32x32.
// smem: As [2][128][72], Bs [2][64][72] bf16 = 55296 B; epilogue [128][68] f32 aliased.
#define WM_SMEM 55296

__global__ __launch_bounds__(256)
void wmma3_nt(const __nv_bfloat16* __restrict__ Ahi, const __nv_bfloat16* __restrict__ Alo,
              const __nv_bfloat16* __restrict__ Bhi, const __nv_bfloat16* __restrict__ Blo,
              const float* __restrict__ bias, float* __restrict__ C,
              int M, int Ncols, int Kd)
{
    extern __shared__ char sm[];
    __nv_bfloat16* As = (__nv_bfloat16*)sm;
    __nv_bfloat16* Bs = As + 2*128*72;
    float* cs = (float*)sm;
    const int tid = threadIdx.x, wid = tid >> 5;
    const int n0g = blockIdx.x * 64, m0g = blockIdx.y * 128;
    const int m0 = (wid >> 1) * 32, n0 = (wid & 1) * 32;

    wmma::fragment<wmma::accumulator, 16, 16, 16, float> acc[2][2];
#pragma unroll
    for (int i = 0; i < 2; i++)
#pragma unroll
        for (int j = 0; j < 2; j++) wmma::fill_fragment(acc[i][j], 0.f);

    for (int k0 = 0; k0 < Kd; k0 += 64) {
        __syncthreads();
        for (int u = tid; u < 2048; u += 256) {
            int p = u >> 10, r = u & 1023;
            int row = r >> 3, cb = (r & 7) << 3;
            *(uint4*)(As + (p*128 + row) * 72 + cb) =
                *(const uint4*)((p ? Alo : Ahi) + (size_t)(m0g + row) * Kd + k0 + cb);
        }
        for (int u = tid; u < 1024; u += 256) {
            int p = u >> 9, r = u & 511;
            int row = r >> 3, cb = (r & 7) << 3;
            uint4 v = make_uint4(0, 0, 0, 0);
            if (n0g + row < Ncols)
                v = *(const uint4*)((p ? Blo : Bhi) + (size_t)(n0g + row) * Kd + k0 + cb);
            *(uint4*)(Bs + (p*64 + row) * 72 + cb) = v;
        }
        __syncthreads();
#pragma unroll
        for (int pass = 0; pass < 3; pass++) {
            const __nv_bfloat16* Ab = As + ((pass == 2) ? 128*72 : 0);
            const __nv_bfloat16* Bb = Bs + ((pass == 1) ? 64*72 : 0);
#pragma unroll
            for (int ks = 0; ks < 4; ks++) {
                wmma::fragment<wmma::matrix_a, 16, 16, 16, __nv_bfloat16, wmma::row_major> a[2];
                wmma::fragment<wmma::matrix_b, 16, 16, 16, __nv_bfloat16, wmma::col_major> b[2];
#pragma unroll
                for (int i = 0; i < 2; i++)
                    wmma::load_matrix_sync(a[i], Ab + (m0 + i * 16) * 72 + ks * 16, 72);
#pragma unroll
                for (int j = 0; j < 2; j++)
                    wmma::load_matrix_sync(b[j], Bb + (n0 + j * 16) * 72 + ks * 16, 72);
#pragma unroll
                for (int i = 0; i < 2; i++)
#pragma unroll
                    for (int j = 0; j < 2; j++)
                        wmma::mma_sync(acc[i][j], a[i], b[j], acc[i][j]);
            }
        }
    }
    __syncthreads();
#pragma unroll
    for (int i = 0; i < 2; i++)
#pragma unroll
        for (int j = 0; j < 2; j++)
            wmma::store_matrix_sync(cs + (m0 + i * 16) * 68 + (n0 + j * 16),
                                    acc[i][j], 68, wmma::mem_row_major);
    __syncthreads();
    for (int idx = tid; idx < 128 * 64; idx += 256) {
        int m_r = idx >> 6, nn = idx & 63;
        int n = n0g + nn;
        if (n < Ncols)
            C[(size_t)(m0g + m_r) * Ncols + n] = cs[m_r * 68 + nn] + (bias ? bias[n] : 0.f);
    }
}

// ---------------- GRU over T=32 (8 nodes / block) ----------------
__global__ __launch_bounds__(320)
void gru_kernel(const float* __restrict__ gi, const float* __restrict__ whh,
                const float* __restrict__ bhh, float* __restrict__ tf,
                __nv_bfloat16* __restrict__ tfhi, __nv_bfloat16* __restrict__ tflo)
{
    __shared__ float h_s[8][HG];
    __shared__ float gh_s[8][304];
    const int tid = threadIdx.x;
    const int n0 = blockIdx.x * 8;
    for (int p = tid; p < 8 * HG; p += 320) h_s[p / HG][p % HG] = 0.f;
    __syncthreads();

    for (int t = 0; t < T_; t++) {
        if (tid < 300) {
            const int j = tid;
            float acc[8];
#pragma unroll
            for (int n = 0; n < 8; n++) acc[n] = 0.f;
            const float4* wr = (const float4*)(whh + (size_t)j * HG);
#pragma unroll 5
            for (int d4 = 0; d4 < HG / 4; d4++) {
                float4 w4 = wr[d4];
#pragma unroll
                for (int n = 0; n < 8; n++) {
                    float4 h4 = ((const float4*)h_s[n])[d4];
                    acc[n] += w4.x*h4.x + w4.y*h4.y + w4.z*h4.z + w4.w*h4.w;
                }
            }
            float bb = bhh[j];
#pragma unroll
            for (int n = 0; n < 8; n++) gh_s[n][j] = acc[n] + bb;
        }
        __syncthreads();
        for (int p = tid; p < 8 * HG; p += 320) {
            int n = p / HG, d = p % HG;
            int ng = n0 + n;
            const float* gin = gi + ((size_t)t * N_ + ng) * (3 * HG);
            float rg = 1.f / (1.f + expf(-(gin[d]        + gh_s[n][d])));
            float zg = 1.f / (1.f + expf(-(gin[HG + d]   + gh_s[n][HG + d])));
            float nn = tanhf(gin[2*HG + d] + rg * gh_s[n][2*HG + d]);
            float hnew = (1.f - zg) * nn + zg * h_s[n][d];
            float act = hnew > 0.f ? hnew : 0.1f * hnew;
            size_t idx = (size_t)ng * FEAT + t * HG + d;
            tf[idx] = act;
            __nv_bfloat16 hb = __float2bfloat16(act);
            tfhi[idx] = hb;
            tflo[idx] = __float2bfloat16(act - __bfloat162float(hb));
            h_s[n][d] = hnew;
        }
        __syncthreads();
    }
}

// ---------------- small kernels ----------------
__global__ void diag_kernel(const float* __restrict__ G, float* __restrict__ dg)
{
    int n = blockIdx.x * blockDim.x + threadIdx.x;
    if (n < N_) dg[n] = G[(size_t)n * N_ + n];
}

__global__ __launch_bounds__(256)
void topk1_kernel(const float* __restrict__ G, const float* __restrict__ dg,
                  int* __restrict__ nbr)
{
    __shared__ float s[N_];
    __shared__ float rv[8]; __shared__ int ri[8];
    const int i = blockIdx.x, tid = threadIdx.x;
    const float dii = dg[i];
    for (int j = tid; j < N_; j += 256) s[j] = 2.f * G[(size_t)i * N_ + j] - dii - dg[j];
    __syncthreads();
    for (int it = 0; it < KNN; it++) {
        float bv = -FLT_MAX; int bi = 1 << 30;
        for (int j = tid; j < N_; j += 256) {
            float v = s[j];
            if (v > bv || (v == bv && j < bi)) { bv = v; bi = j; }
        }
        for (int off = 16; off; off >>= 1) {
            float ov = __shfl_down_sync(0xffffffffu, bv, off);
            int   oi = __shfl_down_sync(0xffffffffu, bi, off);
            if (ov > bv || (ov == bv && oi < bi)) { bv = ov; bi = oi; }
        }
        if ((tid & 31) == 0) { rv[tid >> 5] = bv; ri[tid >> 5] = bi; }
        __syncthreads();
        if (tid == 0) {
            float fv = rv[0]; int fi = ri[0];
            for (int w = 1; w < 8; w++)
                if (rv[w] > fv || (rv[w] == fv && ri[w] < fi)) { fv = rv[w]; fi = ri[w]; }
            nbr[i * KNN + it] = fi;
            s[fi] = -FLT_MAX;
        }
        __syncthreads();
    }
}

__global__ __launch_bounds__(256)
void topk2_kernel(const float* __restrict__ x, const float* __restrict__ sq,
                  int Nn, int* __restrict__ nbr)
{
    __shared__ float s[NP1 + 12];
    __shared__ float xi[HC];
    __shared__ float rv[8]; __shared__ int ri[8];
    const int i = blockIdx.x, tid = threadIdx.x;
    if (tid < HC) xi[tid] = x[(size_t)i * HC + tid];
    __syncthreads();
    const float sqi = sq[i];
    for (int j = tid; j < Nn; j += 256) {
        const float* xj = x + (size_t)j * HC;
        float dot = 0.f;
#pragma unroll
        for (int c = 0; c < HC; c++) dot += xi[c] * xj[c];
        s[j] = 2.f * dot - sqi - sq[j];
    }
    __syncthreads();
    for (int it = 0; it < KNN; it++) {
        float bv = -FLT_MAX; int bi = 1 << 30;
        for (int j = tid; j < Nn; j += 256) {
            float v = s[j];
            if (v > bv || (v == bv && j < bi)) { bv = v; bi = j; }
        }
        for (int off = 16; off; off >>= 1) {
            float ov = __shfl_down_sync(0xffffffffu, bv, off);
            int   oi = __shfl_down_sync(0xffffffffu, bi, off);
            if (ov > bv || (ov == bv && oi < bi)) { bv = ov; bi = oi; }
        }
        if ((tid & 31) == 0) { rv[tid >> 5] = bv; ri[tid >> 5] = bi; }
        __syncthreads();
        if (tid == 0) {
            float fv = rv[0]; int fi = ri[0];
            for (int w = 1; w < 8; w++)
                if (rv[w] > fv || (rv[w] == fv && ri[w] < fi)) { fv = rv[w]; fi = ri[w]; }
            nbr[i * KNN + it] = fi;
            s[fi] = -FLT_MAX;
        }
        __syncthreads();
    }
}

__global__ __launch_bounds__(256)
void pq1_kernel(const float* __restrict__ tf, const float* __restrict__ w1,
                float* __restrict__ p, float* __restrict__ q)
{
    __shared__ float redm[8][32];
    const int n = blockIdx.x, tid = threadIdx.x;
    float ap[HC], aq[HC];
#pragma unroll
    for (int c = 0; c < HC; c++) { ap[c] = 0.f; aq[c] = 0.f; }
    for (int f = tid; f < FEAT; f += 256) {
        float xv = tf[(size_t)n * FEAT + f];
        const float4* wp = (const float4*)(w1 + (size_t)f * HC);
        const float4* wq = (const float4*)(w1 + (size_t)(FEAT + f) * HC);
#pragma unroll
        for (int c4 = 0; c4 < 4; c4++) {
            float4 a = wp[c4];
            ap[c4*4+0] += xv*a.x; ap[c4*4+1] += xv*a.y;
            ap[c4*4+2] += xv*a.z; ap[c4*4+3] += xv*a.w;
            float4 b = wq[c4];
            aq[c4*4+0] += xv*b.x; aq[c4*4+1] += xv*b.y;
            aq[c4*4+2] += xv*b.z; aq[c4*4+3] += xv*b.w;
        }
    }
    const int lane = tid & 31, wid = tid >> 5;
    for (int c = 0; c < 32; c++) {
        float v = (c < HC) ? ap[c] : aq[c - HC];
        for (int off = 16; off; off >>= 1) v += __shfl_down_sync(0xffffffffu, v, off);
        if (lane == 0) redm[wid][c] = v;
    }
    __syncthreads();
    if (tid < 32) {
        float v = 0.f;
        for (int w = 0; w < 8; w++) v += redm[w][tid];
        if (tid < HC) p[(size_t)n * HC + tid] = v;
        else          q[(size_t)n * HC + tid - HC] = v;
    }
}

__global__ __launch_bounds__(256)
void pq2_kernel(const float* __restrict__ x, const float* __restrict__ w1,
                float* __restrict__ p, float* __restrict__ q, int Nn)
{
    int n = blockIdx.x * blockDim.x + threadIdx.x;
    if (n >= Nn) return;
    float xi[HC];
#pragma unroll
    for (int c = 0; c < HC; c++) xi[c] = x[(size_t)n * HC + c];
#pragma unroll
    for (int c = 0; c < HC; c++) {
        float pp = 0.f, qq = 0.f;
#pragma unroll
        for (int u = 0; u < HC; u++) {
            pp += xi[u] * w1[u * HC + c];
            qq += xi[u] * w1[(HC + u) * HC + c];
        }
        p[(size_t)n * HC + c] = pp;
        q[(size_t)n * HC + c] = qq;
    }
}

__global__ __launch_bounds__(256)
void edge_kernel(const float* __restrict__ p, const float* __restrict__ q,
                 const float* __restrict__ b1, const float* __restrict__ w2,
                 const float* __restrict__ b2, const int* __restrict__ nbr,
                 float* __restrict__ out, int Nn, int doRelu)
{
    __shared__ float w2s[HC*HC];
    __shared__ float b1s[HC], b2s[HC];
    const int tid = threadIdx.x;
    if (tid < HC*HC) w2s[tid] = w2[tid];
    if (tid < HC) { b1s[tid] = b1[tid]; b2s[tid] = b2[tid]; }
    __syncthreads();
    const int n = blockIdx.x * blockDim.x + tid;
    if (n >= Nn) return;
    float base[HC], best[HC];
#pragma unroll
    for (int c = 0; c < HC; c++) {
        base[c] = p[(size_t)n*HC + c] - q[(size_t)n*HC + c] + b1s[c];
        best[c] = -FLT_MAX;
    }
    for (int kk = 0; kk < KNN; kk++) {
        int j = nbr[n * KNN + kk];
        const float* qj = q + (size_t)j * HC;
        float o[HC];
#pragma unroll
        for (int c = 0; c < HC; c++) o[c] = b2s[c];
#pragma unroll
        for (int u = 0; u < HC; u++) {
            float hv = base[u] + qj[u];
            hv = hv > 0.f ? hv : 0.f;
#pragma unroll
            for (int c = 0; c < HC; c++) o[c] += hv * w2s[u*HC + c];
        }
#pragma unroll
        for (int c = 0; c < HC; c++) best[c] = fmaxf(best[c], o[c]);
    }
#pragma unroll
    for (int c = 0; c < HC; c++) {
        float v = best[c];
        if (doRelu) v = fmaxf(v, 0.f);
        out[(size_t)n * HC + c] = v;
    }
}

__global__ void score_kernel(const float* __restrict__ x, const float* __restrict__ w,
                             int Nn, float* __restrict__ s)
{
    int n = blockIdx.x * blockDim.x + threadIdx.x;
    if (n >= Nn) return;
    float nw = 0.f, d = 0.f;
#pragma unroll
    for (int c = 0; c < HC; c++) nw += w[c] * w[c];
    nw = sqrtf(nw);
#pragma unroll
    for (int c = 0; c < HC; c++) d += x[(size_t)n*HC + c] * w[c];
    s[n] = tanhf(d / nw);
}

__global__ void sq_kernel(const float* __restrict__ x, int Nn, float* __restrict__ sq)
{
    int n = blockIdx.x * blockDim.x + threadIdx.x;
    if (n >= Nn) return;
    float a = 0.f;
#pragma unroll
    for (int c = 0; c < HC; c++) { float v = x[(size_t)n*HC + c]; a += v * v; }
    sq[n] = a;
}

__global__ void rank_pool_kernel(const float* __restrict__ x, const float* __restrict__ s,
                                 int Nn, int nkeep, float* __restrict__ out)
{
    int n = blockIdx.x * blockDim.x + threadIdx.x;
    if (n >= Nn) return;
    float sn = s[n];
    int rank = 0;
    for (int m = 0; m < Nn; m++) {
        float sm = s[m];
        if (sm > sn || (sm == sn && m < n)) rank++;
    }
    if (rank < nkeep) {
#pragma unroll
        for (int c = 0; c < HC; c++)
            out[(size_t)rank * HC + c] = x[(size_t)n * HC + c] * sn;
    }
}

__global__ __launch_bounds__(256)
void gap_kernel(const float* __restrict__ x, const float* __restrict__ gw,
                const float* __restrict__ gb, int Nn, float* __restrict__ vec)
{
    __shared__ float a[NP1 + 12];
    __shared__ float red[8];
    const int tid = threadIdx.x;
    float lmax = -FLT_MAX;
    for (int n = tid; n < Nn; n += 256) {
        float d = gb[0];
#pragma unroll
        for (int c = 0; c < HC; c++) d += x[(size_t)n*HC + c] * gw[c];
        a[n] = d;
        lmax = fmaxf(lmax, d);
    }
    for (int off = 16; off; off >>= 1) lmax = fmaxf(lmax, __shfl_xor_sync(0xffffffffu, lmax, off));
    if ((tid & 31) == 0) red[tid >> 5] = lmax;
    __syncthreads();
    lmax = red[0];
    for (int w = 1; w < 8; w++) lmax = fmaxf(lmax, red[w]);
    __syncthreads();
    float lsum = 0.f;
    for (int n = tid; n < Nn; n += 256) {
        float e = expf(a[n] - lmax);
        a[n] = e;
        lsum += e;
    }
    for (int off = 16; off; off >>= 1) lsum += __shfl_xor_sync(0xffffffffu, lsum, off);
    if ((tid & 31) == 0) red[tid >> 5] = lsum;
    __syncthreads();
    lsum = 0.f;
    for (int w = 0; w < 8; w++) lsum += red[w];
    if (tid < HC) {
        float v = 0.f;
        for (int n = 0; n < Nn; n++) v += a[n] * x[(size_t)n*HC + tid];
        vec[tid] = v / lsum;
    }
}

__global__ void final_kernel(const float* __restrict__ v1, const float* __restrict__ v2,
                             const float* __restrict__ w, const float* __restrict__ b,
                             float* __restrict__ out)
{
    int c = threadIdx.x;
    if (c < 2) {
        float acc = b[c];
#pragma unroll
        for (int u = 0; u < HC; u++) acc += (v1[u] + v2[u]) * w[u*2 + c];
        out[c] = acc;
    }
}

// ---------------- launch ----------------
extern "C" void kernel_launch(void* const* d_in, const int* in_sizes, int n_in,
                              void* d_out, int out_size)
{
    const float* ts   = (const float*)d_in[0];
    const float* c1w  = (const float*)d_in[1];
    const float* c1b  = (const float*)d_in[2];
    const float* c2w  = (const float*)d_in[3];
    const float* c2b  = (const float*)d_in[4];
    const float* c3w  = (const float*)d_in[5];
    const float* c3b  = (const float*)d_in[6];
    const float* wih  = (const float*)d_in[7];
    const float* whh  = (const float*)d_in[8];
    const float* bih  = (const float*)d_in[9];
    const float* bhh  = (const float*)d_in[10];
    const float* m1w1 = (const float*)d_in[11];
    const float* m1b1 = (const float*)d_in[12];
    const float* m1w2 = (const float*)d_in[13];
    const float* m1b2 = (const float*)d_in[14];
    const float* p1w  = (const float*)d_in[15];
    const float* g1w  = (const float*)d_in[16];
    const float* g1b  = (const float*)d_in[17];
    const float* m2w1 = (const float*)d_in[18];
    const float* m2b1 = (const float*)d_in[19];
    const float* m2w2 = (const float*)d_in[20];
    const float* m2b2 = (const float*)d_in[21];
    const float* p2w  = (const float*)d_in[22];
    const float* g2w  = (const float*)d_in[23];
    const float* g2b  = (const float*)d_in[24];
    const float* l2w  = (const float*)d_in[25];
    const float* l2b  = (const float*)d_in[26];
    float* out        = (float*)d_out;

    float *gi, *tf, *G, *dg, *p1, *q1, *x1f, *sc1, *pool1, *vec1;
    float *sq2, *p2, *q2, *x2f, *sc2, *pool2, *vec2;
    int *nbr1, *nbr2;
    __nv_bfloat16 *xa_hi, *xa_lo, *xb_hi, *xb_lo, *wk_hi, *wk_lo;
    __nv_bfloat16 *tfhi, *tflo, *wihhi, *wihlo;
    cudaGetSymbolAddress((void**)&gi,    g_gi);
    cudaGetSymbolAddress((void**)&tf,    g_tfeat);
    cudaGetSymbolAddress((void**)&tfhi,  g_tf_hi);
    cudaGetSymbolAddress((void**)&tflo,  g_tf_lo);
    cudaGetSymbolAddress((void**)&G,     g_G);
    cudaGetSymbolAddress((void**)&dg,    g_diag);
    cudaGetSymbolAddress((void**)&nbr1,  g_nbr1);
    cudaGetSymbolAddress((void**)&p1,    g_p1);
    cudaGetSymbolAddress((void**)&q1,    g_q1);
    cudaGetSymbolAddress((void**)&x1f,   g_x1f);
    cudaGetSymbolAddress((void**)&sc1,   g_sc1);
    cudaGetSymbolAddress((void**)&pool1, g_pool1);
    cudaGetSymbolAddress((void**)&vec1,  g_vec1);
    cudaGetSymbolAddress((void**)&sq2,   g_sq2);
    cudaGetSymbolAddress((void**)&nbr2,  g_nbr2);
    cudaGetSymbolAddress((void**)&p2,    g_p2);
    cudaGetSymbolAddress((void**)&q2,    g_q2);
    cudaGetSymbolAddress((void**)&x2f,   g_x2f);
    cudaGetSymbolAddress((void**)&sc2,   g_sc2);
    cudaGetSymbolAddress((void**)&pool2, g_pool2);
    cudaGetSymbolAddress((void**)&vec2,  g_vec2);
    cudaGetSymbolAddress((void**)&xa_hi, g_xa_hi);
    cudaGetSymbolAddress((void**)&xa_lo, g_xa_lo);
    cudaGetSymbolAddress((void**)&xb_hi, g_xb_hi);
    cudaGetSymbolAddress((void**)&xb_lo, g_xb_lo);
    cudaGetSymbolAddress((void**)&wk_hi, g_wk_hi);
    cudaGetSymbolAddress((void**)&wk_lo, g_wk_lo);
    cudaGetSymbolAddress((void**)&wihhi, g_wih_hi);
    cudaGetSymbolAddress((void**)&wihlo, g_wih_lo);

    cudaFuncSetAttribute(conv_wmma_kernel, cudaFuncAttributeMaxDynamicSharedMemorySize, CV_SMEM);
    cudaFuncSetAttribute(wmma3_nt, cudaFuncAttributeMaxDynamicSharedMemorySize, WM_SMEM);

    // prep: pad zeros, transpose input, repack weights
    zero_pad_kernel<<<512, 256>>>(xa_hi, xa_lo, xb_hi, xb_lo);
    prep_x_kernel<<<dim3(32, 4, 32), 256>>>(ts, xa_hi, xa_lo);
    prep_w_kernel<<<20480, 256>>>(c1w, wk_hi, wk_lo);
    conv_wmma_kernel<<<dim3(8, 32), 256, CV_SMEM>>>(xa_hi, xa_lo, wk_hi, wk_lo, c1b,
                                                    xb_hi, xb_lo, 0);
    prep_w_kernel<<<20480, 256>>>(c2w, wk_hi, wk_lo);
    conv_wmma_kernel<<<dim3(8, 32), 256, CV_SMEM>>>(xb_hi, xb_lo, wk_hi, wk_lo, c2b,
                                                    xa_hi, xa_lo, 0);
    prep_w_kernel<<<20480, 256>>>(c3w, wk_hi, wk_lo);
    // conv3: write hi/lo row-major [t*1024+o][128] into the freed xb buffers
    conv_wmma_kernel<<<dim3(8, 32), 256, CV_SMEM>>>(xa_hi, xa_lo, wk_hi, wk_lo, c3b,
                                                    xb_hi, xb_lo, 1);

    // gi = d @ wih.T + bih  (wmma 3-pass)
    split_kernel<<<(3*HG*D_ + 255)/256, 256>>>(wih, wihhi, wihlo, 3*HG*D_);
    wmma3_nt<<<dim3(5, (T_*N_)/128), 256, WM_SMEM>>>(xb_hi, xb_lo, wihhi, wihlo,
                                                     bih, gi, T_*N_, 3*HG, D_);
    gru_kernel<<<N_/8, 320>>>(gi, whh, bhh, tf, tfhi, tflo);

    // Gram (wmma 3-pass) + knn1
    wmma3_nt<<<dim3(16, 8), 256, WM_SMEM>>>(tfhi, tflo, tfhi, tflo,
                                            nullptr, G, N_, N_, FEAT);
    diag_kernel<<<4, 256>>>(G, dg);
    topk1_kernel<<<N_, 256>>>(G, dg, nbr1);

    // DGCN1
    pq1_kernel<<<N_, 256>>>(tf, m1w1, p1, q1);
    edge_kernel<<<4, 256>>>(p1, q1, m1b1, m1w2, m1b2, nbr1, x1f, N_, 1);

    score_kernel<<<4, 256>>>(x1f, p1w, N_, sc1);
    rank_pool_kernel<<<4, 256>>>(x1f, sc1, N_, NP1, pool1);
    gap_kernel<<<1, 256>>>(pool1, g1w, g1b, NP1, vec1);

    // DGCN2
    sq_kernel<<<4, 256>>>(pool1, NP1, sq2);
    topk2_kernel<<<NP1, 256>>>(pool1, sq2, NP1, nbr2);
    pq2_kernel<<<4, 256>>>(pool1, m2w1, p2, q2, NP1);
    edge_kernel<<<4, 256>>>(p2, q2, m2b1, m2w2, m2b2, nbr2, x2f, NP1, 0);

    score_kernel<<<4, 256>>>(x2f, p2w, NP1, sc2);
    rank_pool_kernel<<<4, 256>>>(x2f, sc2, NP1, NP2, pool2);
    gap_kernel<<<1, 256>>>(pool2, g2w, g2b, NP2, vec2);

    final_kernel<<<1, 32>>>(vec1, vec2, l2w, l2b, out);
}

// round 12
// speedup vs baseline: 2.7221x; 1.0583x over previous
#include <cuda_runtime.h>
#include <cuda_bf16.h>
#include <mma.h>
#include <math.h>
#include <float.h>
#include <stdint.h>

using namespace nvcuda;

#define T_   32
#define N_   1024
#define D_   128
#define HG   100
#define FEAT 3200
#define HC   16
#define KNN  20
#define NP1  820
#define NP2  656

// ---------------- scratch (device globals; no allocs) ----------------
__device__ float g_gi[T_*N_*3*HG];
__device__ float g_tfeat[N_*FEAT];
__device__ __nv_bfloat16 g_tf_hi[N_*FEAT];
__device__ __nv_bfloat16 g_tf_lo[N_*FEAT];
__device__ float g_G[N_*N_];
__device__ float g_diag[N_];
__device__ int   g_nbr1[N_*KNN];
__device__ float g_p1[N_*HC], g_q1[N_*HC];
__device__ float g_x1f[N_*HC];
__device__ float g_sc1[N_];
__device__ float g_pool1[NP1*HC];
__device__ float g_vec1[HC];
__device__ float g_sq2[NP1];
__device__ int   g_nbr2[NP1*KNN];
__device__ float g_p2[NP1*HC], g_q2[NP1*HC];
__device__ float g_x2f[NP1*HC];
__device__ float g_sc2[NP1];
__device__ float g_pool2[NP2*HC];
__device__ float g_vec2[HC];
// bf16 hi/lo padded transposed activations: [t][132 rows][1024 ch]
__device__ __nv_bfloat16 g_xa_hi[T_*132*1024];
__device__ __nv_bfloat16 g_xa_lo[T_*132*1024];
__device__ __nv_bfloat16 g_xb_hi[T_*132*1024];   // also reused as gi-A [32768][128]
__device__ __nv_bfloat16 g_xb_lo[T_*132*1024];
// repacked weights [k][o][ic] bf16 hi/lo
__device__ __nv_bfloat16 g_wk_hi[5*1024*1024];
__device__ __nv_bfloat16 g_wk_lo[5*1024*1024];
__device__ __nv_bfloat16 g_wih_hi[3*HG*D_];
__device__ __nv_bfloat16 g_wih_lo[3*HG*D_];

// ---------------- cp.async helpers ----------------
__device__ __forceinline__ uint32_t smem_u32(const void* p) {
    uint32_t a;
    asm("{ .reg .u64 t; cvta.to.shared.u64 t, %1; cvt.u32.u64 %0, t; }" : "=r"(a) : "l"(p));
    return a;
}
__device__ __forceinline__ void cpa16(uint32_t dst, const void* src) {
    asm volatile("cp.async.cg.shared.global [%0], [%1], 16;" :: "r"(dst), "l"(src));
}
#define CPA_COMMIT asm volatile("cp.async.commit_group;" ::: "memory")
#define CPA_WAIT0  asm volatile("cp.async.wait_group 0;" ::: "memory")

// ---------------- prep kernels ----------------
// repack conv weight w[o][ic*5+k] -> wk[k][o][ic] hi/lo bf16 (coalesced via smem)
__global__ __launch_bounds__(256)
void prep_w_kernel(const float* __restrict__ w,
                   __nv_bfloat16* __restrict__ whi, __nv_bfloat16* __restrict__ wlo)
{
    __shared__ float buf[5120];
    const int o = blockIdx.x, tid = threadIdx.x;
    const float* src = w + (size_t)o * 5120;
    for (int i = tid; i < 5120; i += 256) buf[i] = src[i];
    __syncthreads();
#pragma unroll
    for (int k = 0; k < 5; k++) {
        for (int ic = tid; ic < 1024; ic += 256) {
            float v = buf[ic * 5 + k];          // stride 5 words: conflict-free (5 coprime 32)
            __nv_bfloat16 h = __float2bfloat16(v);
            size_t idx = ((size_t)k << 20) + ((size_t)o << 10) + ic;
            whi[idx] = h;
            wlo[idx] = __float2bfloat16(v - __bfloat162float(h));
        }
    }
}

__global__ void split_kernel(const float* __restrict__ in,
                             __nv_bfloat16* __restrict__ hi, __nv_bfloat16* __restrict__ lo, int n)
{
    int i = blockIdx.x * 256 + threadIdx.x;
    if (i >= n) return;
    float v = in[i];
    __nv_bfloat16 h = __float2bfloat16(v);
    hi[i] = h;
    lo[i] = __float2bfloat16(v - __bfloat162float(h));
}

// transpose+split: in fp32 [t][c][128] -> Xp bf16 [t][h+2][c]
__global__ void prep_x_kernel(const float* __restrict__ in,
                              __nv_bfloat16* __restrict__ xhi, __nv_bfloat16* __restrict__ xlo)
{
    __shared__ float tile[32][33];
    int t = blockIdx.z, c0 = blockIdx.x * 32, h0 = blockIdx.y * 32;
    int lx = threadIdx.x & 31, ly = threadIdx.x >> 5;
#pragma unroll
    for (int i = 0; i < 4; i++) {
        int c = c0 + ly + i * 8;
        tile[ly + i * 8][lx] = in[((size_t)t * 1024 + c) * 128 + h0 + lx];
    }
    __syncthreads();
#pragma unroll
    for (int i = 0; i < 4; i++) {
        int h = h0 + ly + i * 8;
        float v = tile[lx][ly + i * 8];
        __nv_bfloat16 hb = __float2bfloat16(v);
        size_t o = ((size_t)t * 132 + h + 2) * 1024 + c0 + lx;
        xhi[o] = hb;
        xlo[o] = __float2bfloat16(v - __bfloat162float(hb));
    }
}

__global__ void zero_pad_kernel(__nv_bfloat16* a, __nv_bfloat16* b,
                                __nv_bfloat16* c, __nv_bfloat16* d)
{
    int idx = blockIdx.x * 256 + threadIdx.x;   // 32t * 4rows * 1024
    if (idx >= 32 * 4 * 1024) return;
    int t = idx >> 12, r = (idx >> 10) & 3, ic = idx & 1023;
    int hp = (r < 2) ? r : 128 + r;
    size_t o = ((size_t)t * 132 + hp) * 1024 + ic;
    __nv_bfloat16 z = __float2bfloat16(0.f);
    a[o] = z; b[o] = z; c[o] = z; d[o] = z;
}

// ---------------- wmma conv kernel (cp.async double-buffered) ----------------
// grid (8 o-tiles, 32 t), 256 thr (8 warps). C[o, h] = sum_{k,ic} Wk[o,ic]*Xp[t][h+k][ic]
#define XLD 72
#define CV_XB 38016u
#define CV_WOFF 76032u
#define CV_WB 36864u
#define CV_SMEM 149760

__device__ __forceinline__ void conv_issue_stage(
    int qq, int tid, int t, int o0, uint32_t smX, uint32_t smW,
    const __nv_bfloat16* xhi, const __nv_bfloat16* xlo,
    const __nv_bfloat16* whi, const __nv_bfloat16* wlo)
{
    const int ch = qq / 5, s = qq % 5, ic0 = ch << 6;
    const uint32_t wb = smW + (uint32_t)(qq & 1) * CV_WB;
    for (int u = tid; u < 2048; u += 256) {
        int p = u >> 10, r = u & 1023;
        int row = r >> 3, cb = (r & 7) << 3;
        const __nv_bfloat16* src = (p ? wlo : whi)
            + ((size_t)s << 20) + ((size_t)(o0 + row) << 10) + ic0 + cb;
        cpa16(wb + (uint32_t)(p * 128 + row) * 144u + cb * 2, src);
    }
    if (s == 0) {
        const uint32_t xb = smX + (uint32_t)(ch & 1) * CV_XB;
        for (int u = tid; u < 2112; u += 256) {
            int p = (u >= 1056) ? 1 : 0;
            int r = u - p * 1056;
            int row = r >> 3, cb = (r & 7) << 3;
            const __nv_bfloat16* src = (p ? xlo : xhi)
                + (((size_t)t * 132 + row) << 10) + ic0 + cb;
            cpa16(xb + (uint32_t)(p * 132 + row) * 144u + cb * 2, src);
        }
    }
    CPA_COMMIT;
}

__global__ __launch_bounds__(256)
void conv_wmma_kernel(const __nv_bfloat16* __restrict__ xhi, const __nv_bfloat16* __restrict__ xlo,
                      const __nv_bfloat16* __restrict__ whi, const __nv_bfloat16* __restrict__ wlo,
                      const float* __restrict__ bias,
                      __nv_bfloat16* __restrict__ ohi, __nv_bfloat16* __restrict__ olo,
                      int mode)
{
    extern __shared__ char smem[];
    const uint32_t smX = smem_u32(smem);
    const uint32_t smW = smX + CV_WOFF;
    float* cs = (float*)smem;                       // aliased epilogue buffer [128][132]

    const int tid = threadIdx.x;
    const int wid = tid >> 5;
    const int o0 = blockIdx.x * 128;
    const int t  = blockIdx.y;
    const int m0 = (wid >> 1) * 32;                 // warp row offset (o)
    const int n0 = (wid & 1) * 64;                  // warp col offset (h)

    wmma::fragment<wmma::accumulator, 16, 16, 16, float> acc[2][4];
#pragma unroll
    for (int i = 0; i < 2; i++)
#pragma unroll
        for (int j = 0; j < 4; j++) wmma::fill_fragment(acc[i][j], 0.f);

    conv_issue_stage(0, tid, t, o0, smX, smW, xhi, xlo, whi, wlo);

    for (int q = 0; q < 80; q++) {
        const int ch = q / 5, s = q % 5;
        CPA_WAIT0;
        __syncthreads();
        if (q < 79)
            conv_issue_stage(q + 1, tid, t, o0, smX, smW, xhi, xlo, whi, wlo);

        const __nv_bfloat16* Xbase = (const __nv_bfloat16*)(smem) + (size_t)(ch & 1) * (2*132*XLD);
        const __nv_bfloat16* Wbase = (const __nv_bfloat16*)(smem + CV_WOFF) + (size_t)(q & 1) * (2*128*XLD);
        const __nv_bfloat16* Whi_s = Wbase;
        const __nv_bfloat16* Wlo_s = Wbase + 128*XLD;
        const __nv_bfloat16* Xhi_s = Xbase + (size_t)s * XLD;
        const __nv_bfloat16* Xlo_s = Xbase + 132*XLD + (size_t)s * XLD;

#pragma unroll
        for (int ks = 0; ks < 4; ks++) {
            wmma::fragment<wmma::matrix_a, 16, 16, 16, __nv_bfloat16, wmma::row_major> ah[2], al[2];
            wmma::fragment<wmma::matrix_b, 16, 16, 16, __nv_bfloat16, wmma::col_major> bh[4], bl[4];
#pragma unroll
            for (int i = 0; i < 2; i++) {
                wmma::load_matrix_sync(ah[i], Whi_s + (m0 + i * 16) * XLD + ks * 16, XLD);
                wmma::load_matrix_sync(al[i], Wlo_s + (m0 + i * 16) * XLD + ks * 16, XLD);
            }
#pragma unroll
            for (int j = 0; j < 4; j++) {
                wmma::load_matrix_sync(bh[j], Xhi_s + (n0 + j * 16) * XLD + ks * 16, XLD);
                wmma::load_matrix_sync(bl[j], Xlo_s + (n0 + j * 16) * XLD + ks * 16, XLD);
            }
#pragma unroll
            for (int i = 0; i < 2; i++)
#pragma unroll
                for (int j = 0; j < 4; j++) wmma::mma_sync(acc[i][j], ah[i], bh[j], acc[i][j]);
#pragma unroll
            for (int i = 0; i < 2; i++)
#pragma unroll
                for (int j = 0; j < 4; j++) wmma::mma_sync(acc[i][j], ah[i], bl[j], acc[i][j]);
#pragma unroll
            for (int i = 0; i < 2; i++)
#pragma unroll
                for (int j = 0; j < 4; j++) wmma::mma_sync(acc[i][j], al[i], bh[j], acc[i][j]);
        }
    }

    __syncthreads();                                // all mma reads done before aliasing
#pragma unroll
    for (int i = 0; i < 2; i++)
#pragma unroll
        for (int j = 0; j < 4; j++)
            wmma::store_matrix_sync(cs + (m0 + i * 16) * 132 + (n0 + j * 16),
                                    acc[i][j], 132, wmma::mem_row_major);
    __syncthreads();

    if (mode == 0) {
        // write transposed hi/lo: [t][h+2][channel]; channel fastest -> coalesced
        for (int idx = tid; idx < 128 * 128; idx += 256) {
            int o_r = idx & 127, h = idx >> 7;
            float v = cs[o_r * 132 + h] + bias[o0 + o_r];
            v = v > 0.f ? v : 0.1f * v;
            __nv_bfloat16 hb = __float2bfloat16(v);
            size_t g = (((size_t)t * 132) + h + 2) * 1024 + o0 + o_r;
            ohi[g] = hb;
            olo[g] = __float2bfloat16(v - __bfloat162float(hb));
        }
    } else {
        // hi/lo row-major [(t*1024 + o)][h]; h fastest -> coalesced
        for (int idx = tid; idx < 128 * 128; idx += 256) {
            int h = idx & 127, o_r = idx >> 7;
            float v = cs[o_r * 132 + h] + bias[o0 + o_r];
            v = v > 0.f ? v : 0.1f * v;
            __nv_bfloat16 hb = __float2bfloat16(v);
            size_t g = ((size_t)t * 1024 + o0 + o_r) * 128 + h;
            ohi[g] = hb;
            olo[g] = __float2bfloat16(v - __bfloat162float(hb));
        }
    }
}

// ------------- generic 3-pass bf16 wmma GEMM-NT -------------
// C[m][n] = sum_k A[m][k]*B[n][k] (+bias[n]); M%128==0, K%64==0, N guarded.
#define WM_SMEM 55296

__global__ __launch_bounds__(256)
void wmma3_nt(const __nv_bfloat16* __restrict__ Ahi, const __nv_bfloat16* __restrict__ Alo,
              const __nv_bfloat16* __restrict__ Bhi, const __nv_bfloat16* __restrict__ Blo,
              const float* __restrict__ bias, float* __restrict__ C,
              int M, int Ncols, int Kd)
{
    extern __shared__ char sm[];
    __nv_bfloat16* As = (__nv_bfloat16*)sm;
    __nv_bfloat16* Bs = As + 2*128*72;
    float* cs = (float*)sm;
    const int tid = threadIdx.x, wid = tid >> 5;
    const int n0g = blockIdx.x * 64, m0g = blockIdx.y * 128;
    const int m0 = (wid >> 1) * 32, n0 = (wid & 1) * 32;

    wmma::fragment<wmma::accumulator, 16, 16, 16, float> acc[2][2];
#pragma unroll
    for (int i = 0; i < 2; i++)
#pragma unroll
        for (int j = 0; j < 2; j++) wmma::fill_fragment(acc[i][j], 0.f);

    for (int k0 = 0; k0 < Kd; k0 += 64) {
        __syncthreads();
        for (int u = tid; u < 2048; u += 256) {
            int p = u >> 10, r = u & 1023;
            int row = r >> 3, cb = (r & 7) << 3;
            *(uint4*)(As + (p*128 + row) * 72 + cb) =
                *(const uint4*)((p ? Alo : Ahi) + (size_t)(m0g + row) * Kd + k0 + cb);
        }
        for (int u = tid; u < 1024; u += 256) {
            int p = u >> 9, r = u & 511;
            int row = r >> 3, cb = (r & 7) << 3;
            uint4 v = make_uint4(0, 0, 0, 0);
            if (n0g + row < Ncols)
                v = *(const uint4*)((p ? Blo : Bhi) + (size_t)(n0g + row) * Kd + k0 + cb);
            *(uint4*)(Bs + (p*64 + row) * 72 + cb) = v;
        }
        __syncthreads();
#pragma unroll
        for (int ks = 0; ks < 4; ks++) {
            wmma::fragment<wmma::matrix_a, 16, 16, 16, __nv_bfloat16, wmma::row_major> ah[2], al[2];
            wmma::fragment<wmma::matrix_b, 16, 16, 16, __nv_bfloat16, wmma::col_major> bh[2], bl[2];
#pragma unroll
            for (int i = 0; i < 2; i++) {
                wmma::load_matrix_sync(ah[i], As + (m0 + i * 16) * 72 + ks * 16, 72);
                wmma::load_matrix_sync(al[i], As + 128*72 + (m0 + i * 16) * 72 + ks * 16, 72);
            }
#pragma unroll
            for (int j = 0; j < 2; j++) {
                wmma::load_matrix_sync(bh[j], Bs + (n0 + j * 16) * 72 + ks * 16, 72);
                wmma::load_matrix_sync(bl[j], Bs + 64*72 + (n0 + j * 16) * 72 + ks * 16, 72);
            }
#pragma unroll
            for (int i = 0; i < 2; i++)
#pragma unroll
                for (int j = 0; j < 2; j++) wmma::mma_sync(acc[i][j], ah[i], bh[j], acc[i][j]);
#pragma unroll
            for (int i = 0; i < 2; i++)
#pragma unroll
                for (int j = 0; j < 2; j++) wmma::mma_sync(acc[i][j], ah[i], bl[j], acc[i][j]);
#pragma unroll
            for (int i = 0; i < 2; i++)
#pragma unroll
                for (int j = 0; j < 2; j++) wmma::mma_sync(acc[i][j], al[i], bh[j], acc[i][j]);
        }
    }
    __syncthreads();
#pragma unroll
    for (int i = 0; i < 2; i++)
#pragma unroll
        for (int j = 0; j < 2; j++)
            wmma::store_matrix_sync(cs + (m0 + i * 16) * 68 + (n0 + j * 16),
                                    acc[i][j], 68, wmma::mem_row_major);
    __syncthreads();
    for (int idx = tid; idx < 128 * 64; idx += 256) {
        int m_r = idx >> 6, nn = idx & 63;
        int n = n0g + nn;
        if (n < Ncols)
            C[(size_t)(m0g + m_r) * Ncols + n] = cs[m_r * 68 + nn] + (bias ? bias[n] : 0.f);
    }
}

// ---------------- GRU over T=32 (8 nodes / block) ----------------
__global__ __launch_bounds__(320)
void gru_kernel(const float* __restrict__ gi, const float* __restrict__ whh,
                const float* __restrict__ bhh, float* __restrict__ tf,
                __nv_bfloat16* __restrict__ tfhi, __nv_bfloat16* __restrict__ tflo)
{
    __shared__ float h_s[8][HG];
    __shared__ float gh_s[8][304];
    const int tid = threadIdx.x;
    const int n0 = blockIdx.x * 8;
    for (int p = tid; p < 8 * HG; p += 320) h_s[p / HG][p % HG] = 0.f;
    __syncthreads();

    for (int t = 0; t < T_; t++) {
        if (tid < 300) {
            const int j = tid;
            float acc[8];
#pragma unroll
            for (int n = 0; n < 8; n++) acc[n] = 0.f;
            const float4* wr = (const float4*)(whh + (size_t)j * HG);
#pragma unroll 5
            for (int d4 = 0; d4 < HG / 4; d4++) {
                float4 w4 = wr[d4];
#pragma unroll
                for (int n = 0; n < 8; n++) {
                    float4 h4 = ((const float4*)h_s[n])[d4];
                    acc[n] += w4.x*h4.x + w4.y*h4.y + w4.z*h4.z + w4.w*h4.w;
                }
            }
            float bb = bhh[j];
#pragma unroll
            for (int n = 0; n < 8; n++) gh_s[n][j] = acc[n] + bb;
        }
        __syncthreads();
        for (int p = tid; p < 8 * HG; p += 320) {
            int n = p / HG, d = p % HG;
            int ng = n0 + n;
            const float* gin = gi + ((size_t)t * N_ + ng) * (3 * HG);
            float rg = 1.f / (1.f + expf(-(gin[d]        + gh_s[n][d])));
            float zg = 1.f / (1.f + expf(-(gin[HG + d]   + gh_s[n][HG + d])));
            float nn = tanhf(gin[2*HG + d] + rg * gh_s[n][2*HG + d]);
            float hnew = (1.f - zg) * nn + zg * h_s[n][d];
            float act = hnew > 0.f ? hnew : 0.1f * hnew;
            size_t idx = (size_t)ng * FEAT + t * HG + d;
            tf[idx] = act;
            __nv_bfloat16 hb = __float2bfloat16(act);
            tfhi[idx] = hb;
            tflo[idx] = __float2bfloat16(act - __bfloat162float(hb));
            h_s[n][d] = hnew;
        }
        __syncthreads();
    }
}

// ---------------- small kernels ----------------
__global__ void diag_kernel(const float* __restrict__ G, float* __restrict__ dg)
{
    int n = blockIdx.x * blockDim.x + threadIdx.x;
    if (n < N_) dg[n] = G[(size_t)n * N_ + n];
}

__global__ __launch_bounds__(256)
void topk1_kernel(const float* __restrict__ G, const float* __restrict__ dg,
                  int* __restrict__ nbr)
{
    __shared__ float s[N_];
    __shared__ float rv[8]; __shared__ int ri[8];
    const int i = blockIdx.x, tid = threadIdx.x;
    const float dii = dg[i];
    for (int j = tid; j < N_; j += 256) s[j] = 2.f * G[(size_t)i * N_ + j] - dii - dg[j];
    __syncthreads();
    for (int it = 0; it < KNN; it++) {
        float bv = -FLT_MAX; int bi = 1 << 30;
        for (int j = tid; j < N_; j += 256) {
            float v = s[j];
            if (v > bv || (v == bv && j < bi)) { bv = v; bi = j; }
        }
        for (int off = 16; off; off >>= 1) {
            float ov = __shfl_down_sync(0xffffffffu, bv, off);
            int   oi = __shfl_down_sync(0xffffffffu, bi, off);
            if (ov > bv || (ov == bv && oi < bi)) { bv = ov; bi = oi; }
        }
        if ((tid & 31) == 0) { rv[tid >> 5] = bv; ri[tid >> 5] = bi; }
        __syncthreads();
        if (tid == 0) {
            float fv = rv[0]; int fi = ri[0];
            for (int w = 1; w < 8; w++)
                if (rv[w] > fv || (rv[w] == fv && ri[w] < fi)) { fv = rv[w]; fi = ri[w]; }
            nbr[i * KNN + it] = fi;
            s[fi] = -FLT_MAX;
        }
        __syncthreads();
    }
}

__global__ __launch_bounds__(256)
void topk2_kernel(const float* __restrict__ x, const float* __restrict__ sq,
                  int Nn, int* __restrict__ nbr)
{
    __shared__ float s[NP1 + 12];
    __shared__ float xi[HC];
    __shared__ float rv[8]; __shared__ int ri[8];
    const int i = blockIdx.x, tid = threadIdx.x;
    if (tid < HC) xi[tid] = x[(size_t)i * HC + tid];
    __syncthreads();
    const float sqi = sq[i];
    for (int j = tid; j < Nn; j += 256) {
        const float* xj = x + (size_t)j * HC;
        float dot = 0.f;
#pragma unroll
        for (int c = 0; c < HC; c++) dot += xi[c] * xj[c];
        s[j] = 2.f * dot - sqi - sq[j];
    }
    __syncthreads();
    for (int it = 0; it < KNN; it++) {
        float bv = -FLT_MAX; int bi = 1 << 30;
        for (int j = tid; j < Nn; j += 256) {
            float v = s[j];
            if (v > bv || (v == bv && j < bi)) { bv = v; bi = j; }
        }
        for (int off = 16; off; off >>= 1) {
            float ov = __shfl_down_sync(0xffffffffu, bv, off);
            int   oi = __shfl_down_sync(0xffffffffu, bi, off);
            if (ov > bv || (ov == bv && oi < bi)) { bv = ov; bi = oi; }
        }
        if ((tid & 31) == 0) { rv[tid >> 5] = bv; ri[tid >> 5] = bi; }
        __syncthreads();
        if (tid == 0) {
            float fv = rv[0]; int fi = ri[0];
            for (int w = 1; w < 8; w++)
                if (rv[w] > fv || (rv[w] == fv && ri[w] < fi)) { fv = rv[w]; fi = ri[w]; }
            nbr[i * KNN + it] = fi;
            s[fi] = -FLT_MAX;
        }
        __syncthreads();
    }
}

__global__ __launch_bounds__(256)
void pq1_kernel(const float* __restrict__ tf, const float* __restrict__ w1,
                float* __restrict__ p, float* __restrict__ q)
{
    __shared__ float redm[8][32];
    const int n = blockIdx.x, tid = threadIdx.x;
    float ap[HC], aq[HC];
#pragma unroll
    for (int c = 0; c < HC; c++) { ap[c] = 0.f; aq[c] = 0.f; }
    for (int f = tid; f < FEAT; f += 256) {
        float xv = tf[(size_t)n * FEAT + f];
        const float4* wp = (const float4*)(w1 + (size_t)f * HC);
        const float4* wq = (const float4*)(w1 + (size_t)(FEAT + f) * HC);
#pragma unroll
        for (int c4 = 0; c4 < 4; c4++) {
            float4 a = wp[c4];
            ap[c4*4+0] += xv*a.x; ap[c4*4+1] += xv*a.y;
            ap[c4*4+2] += xv*a.z; ap[c4*4+3] += xv*a.w;
            float4 b = wq[c4];
            aq[c4*4+0] += xv*b.x; aq[c4*4+1] += xv*b.y;
            aq[c4*4+2] += xv*b.z; aq[c4*4+3] += xv*b.w;
        }
    }
    const int lane = tid & 31, wid = tid >> 5;
    for (int c = 0; c < 32; c++) {
        float v = (c < HC) ? ap[c] : aq[c - HC];
        for (int off = 16; off; off >>= 1) v += __shfl_down_sync(0xffffffffu, v, off);
        if (lane == 0) redm[wid][c] = v;
    }
    __syncthreads();
    if (tid < 32) {
        float v = 0.f;
        for (int w = 0; w < 8; w++) v += redm[w][tid];
        if (tid < HC) p[(size_t)n * HC + tid] = v;
        else          q[(size_t)n * HC + tid - HC] = v;
    }
}

__global__ __launch_bounds__(256)
void pq2_kernel(const float* __restrict__ x, const float* __restrict__ w1,
                float* __restrict__ p, float* __restrict__ q, int Nn)
{
    int n = blockIdx.x * blockDim.x + threadIdx.x;
    if (n >= Nn) return;
    float xi[HC];
#pragma unroll
    for (int c = 0; c < HC; c++) xi[c] = x[(size_t)n * HC + c];
#pragma unroll
    for (int c = 0; c < HC; c++) {
        float pp = 0.f, qq = 0.f;
#pragma unroll
        for (int u = 0; u < HC; u++) {
            pp += xi[u] * w1[u * HC + c];
            qq += xi[u] * w1[(HC + u) * HC + c];
        }
        p[(size_t)n * HC + c] = pp;
        q[(size_t)n * HC + c] = qq;
    }
}

__global__ __launch_bounds__(256)
void edge_kernel(const float* __restrict__ p, const float* __restrict__ q,
                 const float* __restrict__ b1, const float* __restrict__ w2,
                 const float* __restrict__ b2, const int* __restrict__ nbr,
                 float* __restrict__ out, int Nn, int doRelu)
{
    __shared__ float w2s[HC*HC];
    __shared__ float b1s[HC], b2s[HC];
    const int tid = threadIdx.x;
    if (tid < HC*HC) w2s[tid] = w2[tid];
    if (tid < HC) { b1s[tid] = b1[tid]; b2s[tid] = b2[tid]; }
    __syncthreads();
    const int n = blockIdx.x * blockDim.x + tid;
    if (n >= Nn) return;
    float base[HC], best[HC];
#pragma unroll
    for (int c = 0; c < HC; c++) {
        base[c] = p[(size_t)n*HC + c] - q[(size_t)n*HC + c] + b1s[c];
        best[c] = -FLT_MAX;
    }
    for (int kk = 0; kk < KNN; kk++) {
        int j = nbr[n * KNN + kk];
        const float* qj = q + (size_t)j * HC;
        float o[HC];
#pragma unroll
        for (int c = 0; c < HC; c++) o[c] = b2s[c];
#pragma unroll
        for (int u = 0; u < HC; u++) {
            float hv = base[u] + qj[u];
            hv = hv > 0.f ? hv : 0.f;
#pragma unroll
            for (int c = 0; c < HC; c++) o[c] += hv * w2s[u*HC + c];
        }
#pragma unroll
        for (int c = 0; c < HC; c++) best[c] = fmaxf(best[c], o[c]);
    }
#pragma unroll
    for (int c = 0; c < HC; c++) {
        float v = best[c];
        if (doRelu) v = fmaxf(v, 0.f);
        out[(size_t)n * HC + c] = v;
    }
}

__global__ void score_kernel(const float* __restrict__ x, const float* __restrict__ w,
                             int Nn, float* __restrict__ s)
{
    int n = blockIdx.x * blockDim.x + threadIdx.x;
    if (n >= Nn) return;
    float nw = 0.f, d = 0.f;
#pragma unroll
    for (int c = 0; c < HC; c++) nw += w[c] * w[c];
    nw = sqrtf(nw);
#pragma unroll
    for (int c = 0; c < HC; c++) d += x[(size_t)n*HC + c] * w[c];
    s[n] = tanhf(d / nw);
}

__global__ void sq_kernel(const float* __restrict__ x, int Nn, float* __restrict__ sq)
{
    int n = blockIdx.x * blockDim.x + threadIdx.x;
    if (n >= Nn) return;
    float a = 0.f;
#pragma unroll
    for (int c = 0; c < HC; c++) { float v = x[(size_t)n*HC + c]; a += v * v; }
    sq[n] = a;
}

__global__ void rank_pool_kernel(const float* __restrict__ x, const float* __restrict__ s,
                                 int Nn, int nkeep, float* __restrict__ out)
{
    int n = blockIdx.x * blockDim.x + threadIdx.x;
    if (n >= Nn) return;
    float sn = s[n];
    int rank = 0;
    for (int m = 0; m < Nn; m++) {
        float sm = s[m];
        if (sm > sn || (sm == sn && m < n)) rank++;
    }
    if (rank < nkeep) {
#pragma unroll
        for (int c = 0; c < HC; c++)
            out[(size_t)rank * HC + c] = x[(size_t)n * HC + c] * sn;
    }
}

__global__ __launch_bounds__(256)
void gap_kernel(const float* __restrict__ x, const float* __restrict__ gw,
                const float* __restrict__ gb, int Nn, float* __restrict__ vec)
{
    __shared__ float a[NP1 + 12];
    __shared__ float red[8];
    const int tid = threadIdx.x;
    float lmax = -FLT_MAX;
    for (int n = tid; n < Nn; n += 256) {
        float d = gb[0];
#pragma unroll
        for (int c = 0; c < HC; c++) d += x[(size_t)n*HC + c] * gw[c];
        a[n] = d;
        lmax = fmaxf(lmax, d);
    }
    for (int off = 16; off; off >>= 1) lmax = fmaxf(lmax, __shfl_xor_sync(0xffffffffu, lmax, off));
    if ((tid & 31) == 0) red[tid >> 5] = lmax;
    __syncthreads();
    lmax = red[0];
    for (int w = 1; w < 8; w++) lmax = fmaxf(lmax, red[w]);
    __syncthreads();
    float lsum = 0.f;
    for (int n = tid; n < Nn; n += 256) {
        float e = expf(a[n] - lmax);
        a[n] = e;
        lsum += e;
    }
    for (int off = 16; off; off >>= 1) lsum += __shfl_xor_sync(0xffffffffu, lsum, off);
    if ((tid & 31) == 0) red[tid >> 5] = lsum;
    __syncthreads();
    lsum = 0.f;
    for (int w = 0; w < 8; w++) lsum += red[w];
    if (tid < HC) {
        float v = 0.f;
        for (int n = 0; n < Nn; n++) v += a[n] * x[(size_t)n*HC + tid];
        vec[tid] = v / lsum;
    }
}

__global__ void final_kernel(const float* __restrict__ v1, const float* __restrict__ v2,
                             const float* __restrict__ w, const float* __restrict__ b,
                             float* __restrict__ out)
{
    int c = threadIdx.x;
    if (c < 2) {
        float acc = b[c];
#pragma unroll
        for (int u = 0; u < HC; u++) acc += (v1[u] + v2[u]) * w[u*2 + c];
        out[c] = acc;
    }
}

// ---------------- launch ----------------
extern "C" void kernel_launch(void* const* d_in, const int* in_sizes, int n_in,
                              void* d_out, int out_size)
{
    const float* ts   = (const float*)d_in[0];
    const float* c1w  = (const float*)d_in[1];
    const float* c1b  = (const float*)d_in[2];
    const float* c2w  = (const float*)d_in[3];
    const float* c2b  = (const float*)d_in[4];
    const float* c3w  = (const float*)d_in[5];
    const float* c3b  = (const float*)d_in[6];
    const float* wih  = (const float*)d_in[7];
    const float* whh  = (const float*)d_in[8];
    const float* bih  = (const float*)d_in[9];
    const float* bhh  = (const float*)d_in[10];
    const float* m1w1 = (const float*)d_in[11];
    const float* m1b1 = (const float*)d_in[12];
    const float* m1w2 = (const float*)d_in[13];
    const float* m1b2 = (const float*)d_in[14];
    const float* p1w  = (const float*)d_in[15];
    const float* g1w  = (const float*)d_in[16];
    const float* g1b  = (const float*)d_in[17];
    const float* m2w1 = (const float*)d_in[18];
    const float* m2b1 = (const float*)d_in[19];
    const float* m2w2 = (const float*)d_in[20];
    const float* m2b2 = (const float*)d_in[21];
    const float* p2w  = (const float*)d_in[22];
    const float* g2w  = (const float*)d_in[23];
    const float* g2b  = (const float*)d_in[24];
    const float* l2w  = (const float*)d_in[25];
    const float* l2b  = (const float*)d_in[26];
    float* out        = (float*)d_out;

    float *gi, *tf, *G, *dg, *p1, *q1, *x1f, *sc1, *pool1, *vec1;
    float *sq2, *p2, *q2, *x2f, *sc2, *pool2, *vec2;
    int *nbr1, *nbr2;
    __nv_bfloat16 *xa_hi, *xa_lo, *xb_hi, *xb_lo, *wk_hi, *wk_lo;
    __nv_bfloat16 *tfhi, *tflo, *wihhi, *wihlo;
    cudaGetSymbolAddress((void**)&gi,    g_gi);
    cudaGetSymbolAddress((void**)&tf,    g_tfeat);
    cudaGetSymbolAddress((void**)&tfhi,  g_tf_hi);
    cudaGetSymbolAddress((void**)&tflo,  g_tf_lo);
    cudaGetSymbolAddress((void**)&G,     g_G);
    cudaGetSymbolAddress((void**)&dg,    g_diag);
    cudaGetSymbolAddress((void**)&nbr1,  g_nbr1);
    cudaGetSymbolAddress((void**)&p1,    g_p1);
    cudaGetSymbolAddress((void**)&q1,    g_q1);
    cudaGetSymbolAddress((void**)&x1f,   g_x1f);
    cudaGetSymbolAddress((void**)&sc1,   g_sc1);
    cudaGetSymbolAddress((void**)&pool1, g_pool1);
    cudaGetSymbolAddress((void**)&vec1,  g_vec1);
    cudaGetSymbolAddress((void**)&sq2,   g_sq2);
    cudaGetSymbolAddress((void**)&nbr2,  g_nbr2);
    cudaGetSymbolAddress((void**)&p2,    g_p2);
    cudaGetSymbolAddress((void**)&q2,    g_q2);
    cudaGetSymbolAddress((void**)&x2f,   g_x2f);
    cudaGetSymbolAddress((void**)&sc2,   g_sc2);
    cudaGetSymbolAddress((void**)&pool2, g_pool2);
    cudaGetSymbolAddress((void**)&vec2,  g_vec2);
    cudaGetSymbolAddress((void**)&xa_hi, g_xa_hi);
    cudaGetSymbolAddress((void**)&xa_lo, g_xa_lo);
    cudaGetSymbolAddress((void**)&xb_hi, g_xb_hi);
    cudaGetSymbolAddress((void**)&xb_lo, g_xb_lo);
    cudaGetSymbolAddress((void**)&wk_hi, g_wk_hi);
    cudaGetSymbolAddress((void**)&wk_lo, g_wk_lo);
    cudaGetSymbolAddress((void**)&wihhi, g_wih_hi);
    cudaGetSymbolAddress((void**)&wihlo, g_wih_lo);

    cudaFuncSetAttribute(conv_wmma_kernel, cudaFuncAttributeMaxDynamicSharedMemorySize, CV_SMEM);
    cudaFuncSetAttribute(wmma3_nt, cudaFuncAttributeMaxDynamicSharedMemorySize, WM_SMEM);

    // prep: pad zeros, transpose input, repack weights
    zero_pad_kernel<<<512, 256>>>(xa_hi, xa_lo, xb_hi, xb_lo);
    prep_x_kernel<<<dim3(32, 4, 32), 256>>>(ts, xa_hi, xa_lo);
    prep_w_kernel<<<1024, 256>>>(c1w, wk_hi, wk_lo);
    conv_wmma_kernel<<<dim3(8, 32), 256, CV_SMEM>>>(xa_hi, xa_lo, wk_hi, wk_lo, c1b,
                                                    xb_hi, xb_lo, 0);
    prep_w_kernel<<<1024, 256>>>(c2w, wk_hi, wk_lo);
    conv_wmma_kernel<<<dim3(8, 32), 256, CV_SMEM>>>(xb_hi, xb_lo, wk_hi, wk_lo, c2b,
                                                    xa_hi, xa_lo, 0);
    prep_w_kernel<<<1024, 256>>>(c3w, wk_hi, wk_lo);
    // conv3: write hi/lo row-major [t*1024+o][128] into the freed xb buffers
    conv_wmma_kernel<<<dim3(8, 32), 256, CV_SMEM>>>(xa_hi, xa_lo, wk_hi, wk_lo, c3b,
                                                    xb_hi, xb_lo, 1);

    // gi = d @ wih.T + bih  (wmma 3-pass)
    split_kernel<<<(3*HG*D_ + 255)/256, 256>>>(wih, wihhi, wihlo, 3*HG*D_);
    wmma3_nt<<<dim3(5, (T_*N_)/128), 256, WM_SMEM>>>(xb_hi, xb_lo, wihhi, wihlo,
                                                     bih, gi, T_*N_, 3*HG, D_);
    gru_kernel<<<N_/8, 320>>>(gi, whh, bhh, tf, tfhi, tflo);

    // Gram (wmma 3-pass) + knn1
    wmma3_nt<<<dim3(16, 8), 256, WM_SMEM>>>(tfhi, tflo, tfhi, tflo,
                                            nullptr, G, N_, N_, FEAT);
    diag_kernel<<<4, 256>>>(G, dg);
    topk1_kernel<<<N_, 256>>>(G, dg, nbr1);

    // DGCN1
    pq1_kernel<<<N_, 256>>>(tf, m1w1, p1, q1);
    edge_kernel<<<4, 256>>>(p1, q1, m1b1, m1w2, m1b2, nbr1, x1f, N_, 1);

    score_kernel<<<4, 256>>>(x1f, p1w, N_, sc1);
    rank_pool_kernel<<<4, 256>>>(x1f, sc1, N_, NP1, pool1);
    gap_kernel<<<1, 256>>>(pool1, g1w, g1b, NP1, vec1);

    // DGCN2
    sq_kernel<<<4, 256>>>(pool1, NP1, sq2);
    topk2_kernel<<<NP1, 256>>>(pool1, sq2, NP1, nbr2);
    pq2_kernel<<<4, 256>>>(pool1, m2w1, p2, q2, NP1);
    edge_kernel<<<4, 256>>>(p2, q2, m2b1, m2w2, m2b2, nbr2, x2f, NP1, 0);

    score_kernel<<<4, 256>>>(x2f, p2w, NP1, sc2);
    rank_pool_kernel<<<4, 256>>>(x2f, sc2, NP1, NP2, pool2);
    gap_kernel<<<1, 256>>>(pool2, g2w, g2b, NP2, vec2);

    final_kernel<<<1, 32>>>(vec1, vec2, l2w, l2b, out);
}

// round 14
// speedup vs baseline: 2.7250x; 1.0011x over previous
#include <cuda_runtime.h>
#include <cuda_bf16.h>
#include <mma.h>
#include <math.h>
#include <float.h>
#include <stdint.h>

using namespace nvcuda;

#define T_   32
#define N_   1024
#define D_   128
#define HG   100
#define FEAT 3200
#define HC   16
#define KNN  20
#define NP1  820
#define NP2  656

// ---------------- scratch (device globals; no allocs) ----------------
__device__ float g_gi[T_*N_*3*HG];
__device__ float g_tfeat[N_*FEAT];
__device__ __nv_bfloat16 g_tf_hi[N_*FEAT];
__device__ __nv_bfloat16 g_tf_lo[N_*FEAT];
__device__ float g_G[N_*N_];
__device__ float g_diag[N_];
__device__ int   g_nbr1[N_*KNN];
__device__ float g_p1[N_*HC], g_q1[N_*HC];
__device__ float g_x1f[N_*HC];
__device__ float g_sc1[N_];
__device__ float g_pool1[NP1*HC];
__device__ float g_vec1[HC];
__device__ float g_sq2[NP1];
__device__ int   g_nbr2[NP1*KNN];
__device__ float g_p2[NP1*HC], g_q2[NP1*HC];
__device__ float g_x2f[NP1*HC];
__device__ float g_sc2[NP1];
__device__ float g_pool2[NP2*HC];
__device__ float g_vec2[HC];
// bf16 hi/lo padded transposed activations: [t][132 rows][1024 ch]
__device__ __nv_bfloat16 g_xa_hi[T_*132*1024];
__device__ __nv_bfloat16 g_xa_lo[T_*132*1024];
__device__ __nv_bfloat16 g_xb_hi[T_*132*1024];   // also reused as gi-A [32768][128]
__device__ __nv_bfloat16 g_xb_lo[T_*132*1024];
// repacked weights [k][o][ic] bf16 hi/lo
__device__ __nv_bfloat16 g_wk_hi[5*1024*1024];
__device__ __nv_bfloat16 g_wk_lo[5*1024*1024];
__device__ __nv_bfloat16 g_wih_hi[3*HG*D_];
__device__ __nv_bfloat16 g_wih_lo[3*HG*D_];

// ---------------- cp.async helpers ----------------
__device__ __forceinline__ uint32_t smem_u32(const void* p) {
    uint32_t a;
    asm("{ .reg .u64 t; cvta.to.shared.u64 t, %1; cvt.u32.u64 %0, t; }" : "=r"(a) : "l"(p));
    return a;
}
__device__ __forceinline__ void cpa16(uint32_t dst, const void* src) {
    asm volatile("cp.async.cg.shared.global [%0], [%1], 16;" :: "r"(dst), "l"(src));
}
#define CPA_COMMIT asm volatile("cp.async.commit_group;" ::: "memory")
#define CPA_WAIT0  asm volatile("cp.async.wait_group 0;" ::: "memory")

// ---------------- prep kernels ----------------
// repack conv weight w[o][ic*5+k] -> wk[k][o][ic] hi/lo bf16 (coalesced via smem)
__global__ __launch_bounds__(256)
void prep_w_kernel(const float* __restrict__ w,
                   __nv_bfloat16* __restrict__ whi, __nv_bfloat16* __restrict__ wlo)
{
    __shared__ float buf[5120];
    const int o = blockIdx.x, tid = threadIdx.x;
    const float* src = w + (size_t)o * 5120;
    for (int i = tid; i < 5120; i += 256) buf[i] = src[i];
    __syncthreads();
#pragma unroll
    for (int k = 0; k < 5; k++) {
        for (int ic = tid; ic < 1024; ic += 256) {
            float v = buf[ic * 5 + k];
            __nv_bfloat16 h = __float2bfloat16(v);
            size_t idx = ((size_t)k << 20) + ((size_t)o << 10) + ic;
            whi[idx] = h;
            wlo[idx] = __float2bfloat16(v - __bfloat162float(h));
        }
    }
}

__global__ void split_kernel(const float* __restrict__ in,
                             __nv_bfloat16* __restrict__ hi, __nv_bfloat16* __restrict__ lo, int n)
{
    int i = blockIdx.x * 256 + threadIdx.x;
    if (i >= n) return;
    float v = in[i];
    __nv_bfloat16 h = __float2bfloat16(v);
    hi[i] = h;
    lo[i] = __float2bfloat16(v - __bfloat162float(h));
}

// transpose+split: in fp32 [t][c][128] -> Xp bf16 [t][h+2][c]
__global__ void prep_x_kernel(const float* __restrict__ in,
                              __nv_bfloat16* __restrict__ xhi, __nv_bfloat16* __restrict__ xlo)
{
    __shared__ float tile[32][33];
    int t = blockIdx.z, c0 = blockIdx.x * 32, h0 = blockIdx.y * 32;
    int lx = threadIdx.x & 31, ly = threadIdx.x >> 5;
#pragma unroll
    for (int i = 0; i < 4; i++) {
        int c = c0 + ly + i * 8;
        tile[ly + i * 8][lx] = in[((size_t)t * 1024 + c) * 128 + h0 + lx];
    }
    __syncthreads();
#pragma unroll
    for (int i = 0; i < 4; i++) {
        int h = h0 + ly + i * 8;
        float v = tile[lx][ly + i * 8];
        __nv_bfloat16 hb = __float2bfloat16(v);
        size_t o = ((size_t)t * 132 + h + 2) * 1024 + c0 + lx;
        xhi[o] = hb;
        xlo[o] = __float2bfloat16(v - __bfloat162float(hb));
    }
}

__global__ void zero_pad_kernel(__nv_bfloat16* a, __nv_bfloat16* b,
                                __nv_bfloat16* c, __nv_bfloat16* d)
{
    int idx = blockIdx.x * 256 + threadIdx.x;   // 32t * 4rows * 1024
    if (idx >= 32 * 4 * 1024) return;
    int t = idx >> 12, r = (idx >> 10) & 3, ic = idx & 1023;
    int hp = (r < 2) ? r : 128 + r;
    size_t o = ((size_t)t * 132 + hp) * 1024 + ic;
    __nv_bfloat16 z = __float2bfloat16(0.f);
    a[o] = z; b[o] = z; c[o] = z; d[o] = z;
}

// ---------------- wmma conv kernel (cp.async double-buffered, ic-chunk 32) ----------------
// grid (8 o-tiles, 32 t), 256 thr (8 warps), 2 CTAs/SM.
// C[o, h] = sum_{k,ic} Wk[o,ic]*Xp[t][h+k][ic]
#define XLD2 40
#define CV_XB 21120u
#define CV_WOFF 42240u
#define CV_WB 20480u
#define CV_SMEM 83200

__device__ __forceinline__ void conv_issue_stage(
    int qq, int tid, int t, int o0, uint32_t smX, uint32_t smW,
    const __nv_bfloat16* xhi, const __nv_bfloat16* xlo,
    const __nv_bfloat16* whi, const __nv_bfloat16* wlo)
{
    const int ch = qq / 5, s = qq % 5, ic0 = ch << 5;
    const uint32_t wb = smW + (uint32_t)(qq & 1) * CV_WB;
    for (int u = tid; u < 1024; u += 256) {        // W: 2 splits x 128 rows x 4 x 16B
        int p = u >> 9, r = u & 511;
        int row = r >> 2, cb = r & 3;
        const __nv_bfloat16* src = (p ? wlo : whi)
            + ((size_t)s << 20) + ((size_t)(o0 + row) << 10) + ic0 + cb * 8;
        cpa16(wb + (uint32_t)(p * 128 + row) * 80u + cb * 16, src);
    }
    if (s == 0) {
        const uint32_t xb = smX + (uint32_t)(ch & 1) * CV_XB;
        for (int u = tid; u < 1056; u += 256) {    // X: 2 splits x 132 rows x 4 x 16B
            int p = (u >= 528) ? 1 : 0;
            int r = u - p * 528;
            int row = r >> 2, cb = r & 3;
            const __nv_bfloat16* src = (p ? xlo : xhi)
                + (((size_t)t * 132 + row) << 10) + ic0 + cb * 8;
            cpa16(xb + (uint32_t)(p * 132 + row) * 80u + cb * 16, src);
        }
    }
    CPA_COMMIT;
}

__global__ __launch_bounds__(256, 2)
void conv_wmma_kernel(const __nv_bfloat16* __restrict__ xhi, const __nv_bfloat16* __restrict__ xlo,
                      const __nv_bfloat16* __restrict__ whi, const __nv_bfloat16* __restrict__ wlo,
                      const float* __restrict__ bias,
                      __nv_bfloat16* __restrict__ ohi, __nv_bfloat16* __restrict__ olo,
                      int mode)
{
    extern __shared__ char smem[];
    const uint32_t smX = smem_u32(smem);
    const uint32_t smW = smX + CV_WOFF;
    float* cs = (float*)smem;                       // aliased epilogue buffer [128][132]

    const int tid = threadIdx.x;
    const int wid = tid >> 5;
    const int o0 = blockIdx.x * 128;
    const int t  = blockIdx.y;
    const int m0 = (wid >> 1) * 32;                 // warp row offset (o)
    const int n0 = (wid & 1) * 64;                  // warp col offset (h)

    wmma::fragment<wmma::accumulator, 16, 16, 16, float> acc[2][4];
#pragma unroll
    for (int i = 0; i < 2; i++)
#pragma unroll
        for (int j = 0; j < 4; j++) wmma::fill_fragment(acc[i][j], 0.f);

    conv_issue_stage(0, tid, t, o0, smX, smW, xhi, xlo, whi, wlo);

    for (int q = 0; q < 160; q++) {
        const int ch = q / 5, s = q % 5;
        CPA_WAIT0;
        __syncthreads();
        if (q < 159)
            conv_issue_stage(q + 1, tid, t, o0, smX, smW, xhi, xlo, whi, wlo);

        const __nv_bfloat16* Xbase = (const __nv_bfloat16*)(smem) + (size_t)(ch & 1) * (2*132*XLD2);
        const __nv_bfloat16* Wbase = (const __nv_bfloat16*)(smem + CV_WOFF) + (size_t)(q & 1) * (2*128*XLD2);
        const __nv_bfloat16* Whi_s = Wbase;
        const __nv_bfloat16* Wlo_s = Wbase + 128*XLD2;
        const __nv_bfloat16* Xhi_s = Xbase + (size_t)s * XLD2;
        const __nv_bfloat16* Xlo_s = Xbase + 132*XLD2 + (size_t)s * XLD2;

#pragma unroll
        for (int ks = 0; ks < 2; ks++) {
            wmma::fragment<wmma::matrix_a, 16, 16, 16, __nv_bfloat16, wmma::row_major> ah[2], al[2];
            wmma::fragment<wmma::matrix_b, 16, 16, 16, __nv_bfloat16, wmma::col_major> bh[4], bl[4];
#pragma unroll
            for (int i = 0; i < 2; i++) {
                wmma::load_matrix_sync(ah[i], Whi_s + (m0 + i * 16) * XLD2 + ks * 16, XLD2);
                wmma::load_matrix_sync(al[i], Wlo_s + (m0 + i * 16) * XLD2 + ks * 16, XLD2);
            }
#pragma unroll
            for (int j = 0; j < 4; j++) {
                wmma::load_matrix_sync(bh[j], Xhi_s + (n0 + j * 16) * XLD2 + ks * 16, XLD2);
                wmma::load_matrix_sync(bl[j], Xlo_s + (n0 + j * 16) * XLD2 + ks * 16, XLD2);
            }
#pragma unroll
            for (int i = 0; i < 2; i++)
#pragma unroll
                for (int j = 0; j < 4; j++) wmma::mma_sync(acc[i][j], ah[i], bh[j], acc[i][j]);
#pragma unroll
            for (int i = 0; i < 2; i++)
#pragma unroll
                for (int j = 0; j < 4; j++) wmma::mma_sync(acc[i][j], ah[i], bl[j], acc[i][j]);
#pragma unroll
            for (int i = 0; i < 2; i++)
#pragma unroll
                for (int j = 0; j < 4; j++) wmma::mma_sync(acc[i][j], al[i], bh[j], acc[i][j]);
        }
    }

    __syncthreads();                                // all mma reads done before aliasing
#pragma unroll
    for (int i = 0; i < 2; i++)
#pragma unroll
        for (int j = 0; j < 4; j++)
            wmma::store_matrix_sync(cs + (m0 + i * 16) * 132 + (n0 + j * 16),
                                    acc[i][j], 132, wmma::mem_row_major);
    __syncthreads();

    if (mode == 0) {
        // write transposed hi/lo: [t][h+2][channel]; channel fastest -> coalesced
        for (int idx = tid; idx < 128 * 128; idx += 256) {
            int o_r = idx & 127, h = idx >> 7;
            float v = cs[o_r * 132 + h] + bias[o0 + o_r];
            v = v > 0.f ? v : 0.1f * v;
            __nv_bfloat16 hb = __float2bfloat16(v);
            size_t g = (((size_t)t * 132) + h + 2) * 1024 + o0 + o_r;
            ohi[g] = hb;
            olo[g] = __float2bfloat16(v - __bfloat162float(hb));
        }
    } else {
        // hi/lo row-major [(t*1024 + o)][h]; h fastest -> coalesced
        for (int idx = tid; idx < 128 * 128; idx += 256) {
            int h = idx & 127, o_r = idx >> 7;
            float v = cs[o_r * 132 + h] + bias[o0 + o_r];
            v = v > 0.f ? v : 0.1f * v;
            __nv_bfloat16 hb = __float2bfloat16(v);
            size_t g = ((size_t)t * 1024 + o0 + o_r) * 128 + h;
            ohi[g] = hb;
            olo[g] = __float2bfloat16(v - __bfloat162float(hb));
        }
    }
}

// ------------- generic 3-pass bf16 wmma GEMM-NT -------------
// C[m][n] = sum_k A[m][k]*B[n][k] (+bias[n]); M%128==0, K%64==0, N guarded.
#define WM_SMEM 55296

__global__ __launch_bounds__(256)
void wmma3_nt(const __nv_bfloat16* __restrict__ Ahi, const __nv_bfloat16* __restrict__ Alo,
              const __nv_bfloat16* __restrict__ Bhi, const __nv_bfloat16* __restrict__ Blo,
              const float* __restrict__ bias, float* __restrict__ C,
              int M, int Ncols, int Kd)
{
    extern __shared__ char sm[];
    __nv_bfloat16* As = (__nv_bfloat16*)sm;
    __nv_bfloat16* Bs = As + 2*128*72;
    float* cs = (float*)sm;
    const int tid = threadIdx.x, wid = tid >> 5;
    const int n0g = blockIdx.x * 64, m0g = blockIdx.y * 128;
    const int m0 = (wid >> 1) * 32, n0 = (wid & 1) * 32;

    wmma::fragment<wmma::accumulator, 16, 16, 16, float> acc[2][2];
#pragma unroll
    for (int i = 0; i < 2; i++)
#pragma unroll
        for (int j = 0; j < 2; j++) wmma::fill_fragment(acc[i][j], 0.f);

    for (int k0 = 0; k0 < Kd; k0 += 64) {
        __syncthreads();
        for (int u = tid; u < 2048; u += 256) {
            int p = u >> 10, r = u & 1023;
            int row = r >> 3, cb = (r & 7) << 3;
            *(uint4*)(As + (p*128 + row) * 72 + cb) =
                *(const uint4*)((p ? Alo : Ahi) + (size_t)(m0g + row) * Kd + k0 + cb);
        }
        for (int u = tid; u < 1024; u += 256) {
            int p = u >> 9, r = u & 511;
            int row = r >> 3, cb = (r & 7) << 3;
            uint4 v = make_uint4(0, 0, 0, 0);
            if (n0g + row < Ncols)
                v = *(const uint4*)((p ? Blo : Bhi) + (size_t)(n0g + row) * Kd + k0 + cb);
            *(uint4*)(Bs + (p*64 + row) * 72 + cb) = v;
        }
        __syncthreads();
#pragma unroll
        for (int ks = 0; ks < 4; ks++) {
            wmma::fragment<wmma::matrix_a, 16, 16, 16, __nv_bfloat16, wmma::row_major> ah[2], al[2];
            wmma::fragment<wmma::matrix_b, 16, 16, 16, __nv_bfloat16, wmma::col_major> bh[2], bl[2];
#pragma unroll
            for (int i = 0; i < 2; i++) {
                wmma::load_matrix_sync(ah[i], As + (m0 + i * 16) * 72 + ks * 16, 72);
                wmma::load_matrix_sync(al[i], As + 128*72 + (m0 + i * 16) * 72 + ks * 16, 72);
            }
#pragma unroll
            for (int j = 0; j < 2; j++) {
                wmma::load_matrix_sync(bh[j], Bs + (n0 + j * 16) * 72 + ks * 16, 72);
                wmma::load_matrix_sync(bl[j], Bs + 64*72 + (n0 + j * 16) * 72 + ks * 16, 72);
            }
#pragma unroll
            for (int i = 0; i < 2; i++)
#pragma unroll
                for (int j = 0; j < 2; j++) wmma::mma_sync(acc[i][j], ah[i], bh[j], acc[i][j]);
#pragma unroll
            for (int i = 0; i < 2; i++)
#pragma unroll
                for (int j = 0; j < 2; j++) wmma::mma_sync(acc[i][j], ah[i], bl[j], acc[i][j]);
#pragma unroll
            for (int i = 0; i < 2; i++)
#pragma unroll
                for (int j = 0; j < 2; j++) wmma::mma_sync(acc[i][j], al[i], bh[j], acc[i][j]);
        }
    }
    __syncthreads();
#pragma unroll
    for (int i = 0; i < 2; i++)
#pragma unroll
        for (int j = 0; j < 2; j++)
            wmma::store_matrix_sync(cs + (m0 + i * 16) * 68 + (n0 + j * 16),
                                    acc[i][j], 68, wmma::mem_row_major);
    __syncthreads();
    for (int idx = tid; idx < 128 * 64; idx += 256) {
        int m_r = idx >> 6, nn = idx & 63;
        int n = n0g + nn;
        if (n < Ncols)
            C[(size_t)(m0g + m_r) * Ncols + n] = cs[m_r * 68 + nn] + (bias ? bias[n] : 0.f);
    }
}

// ---------------- GRU over T=32 (8 nodes / block) ----------------
__global__ __launch_bounds__(320)
void gru_kernel(const float* __restrict__ gi, const float* __restrict__ whh,
                const float* __restrict__ bhh, float* __restrict__ tf,
                __nv_bfloat16* __restrict__ tfhi, __nv_bfloat16* __restrict__ tflo)
{
    __shared__ float h_s[8][HG];
    __shared__ float gh_s[8][304];
    const int tid = threadIdx.x;
    const int n0 = blockIdx.x * 8;
    for (int p = tid; p < 8 * HG; p += 320) h_s[p / HG][p % HG] = 0.f;
    __syncthreads();

    for (int t = 0; t < T_; t++) {
        if (tid < 300) {
            const int j = tid;
            float acc[8];
#pragma unroll
            for (int n = 0; n < 8; n++) acc[n] = 0.f;
            const float4* wr = (const float4*)(whh + (size_t)j * HG);
#pragma unroll 5
            for (int d4 = 0; d4 < HG / 4; d4++) {
                float4 w4 = wr[d4];
#pragma unroll
                for (int n = 0; n < 8; n++) {
                    float4 h4 = ((const float4*)h_s[n])[d4];
                    acc[n] += w4.x*h4.x + w4.y*h4.y + w4.z*h4.z + w4.w*h4.w;
                }
            }
            float bb = bhh[j];
#pragma unroll
            for (int n = 0; n < 8; n++) gh_s[n][j] = acc[n] + bb;
        }
        __syncthreads();
        for (int p = tid; p < 8 * HG; p += 320) {
            int n = p / HG, d = p % HG;
            int ng = n0 + n;
            const float* gin = gi + ((size_t)t * N_ + ng) * (3 * HG);
            float rg = 1.f / (1.f + expf(-(gin[d]        + gh_s[n][d])));
            float zg = 1.f / (1.f + expf(-(gin[HG + d]   + gh_s[n][HG + d])));
            float nn = tanhf(gin[2*HG + d] + rg * gh_s[n][2*HG + d]);
            float hnew = (1.f - zg) * nn + zg * h_s[n][d];
            float act = hnew > 0.f ? hnew : 0.1f * hnew;
            size_t idx = (size_t)ng * FEAT + t * HG + d;
            tf[idx] = act;
            __nv_bfloat16 hb = __float2bfloat16(act);
            tfhi[idx] = hb;
            tflo[idx] = __float2bfloat16(act - __bfloat162float(hb));
            h_s[n][d] = hnew;
        }
        __syncthreads();
    }
}

// ---------------- small kernels ----------------
__global__ void diag_kernel(const float* __restrict__ G, float* __restrict__ dg)
{
    int n = blockIdx.x * blockDim.x + threadIdx.x;
    if (n < N_) dg[n] = G[(size_t)n * N_ + n];
}

__global__ __launch_bounds__(256)
void topk1_kernel(const float* __restrict__ G, const float* __restrict__ dg,
                  int* __restrict__ nbr)
{
    __shared__ float s[N_];
    __shared__ float rv[8]; __shared__ int ri[8];
    const int i = blockIdx.x, tid = threadIdx.x;
    const float dii = dg[i];
    for (int j = tid; j < N_; j += 256) s[j] = 2.f * G[(size_t)i * N_ + j] - dii - dg[j];
    __syncthreads();
    for (int it = 0; it < KNN; it++) {
        float bv = -FLT_MAX; int bi = 1 << 30;
        for (int j = tid; j < N_; j += 256) {
            float v = s[j];
            if (v > bv || (v == bv && j < bi)) { bv = v; bi = j; }
        }
        for (int off = 16; off; off >>= 1) {
            float ov = __shfl_down_sync(0xffffffffu, bv, off);
            int   oi = __shfl_down_sync(0xffffffffu, bi, off);
            if (ov > bv || (ov == bv && oi < bi)) { bv = ov; bi = oi; }
        }
        if ((tid & 31) == 0) { rv[tid >> 5] = bv; ri[tid >> 5] = bi; }
        __syncthreads();
        if (tid == 0) {
            float fv = rv[0]; int fi = ri[0];
            for (int w = 1; w < 8; w++)
                if (rv[w] > fv || (rv[w] == fv && ri[w] < fi)) { fv = rv[w]; fi = ri[w]; }
            nbr[i * KNN + it] = fi;
            s[fi] = -FLT_MAX;
        }
        __syncthreads();
    }
}

__global__ __launch_bounds__(256)
void topk2_kernel(const float* __restrict__ x, const float* __restrict__ sq,
                  int Nn, int* __restrict__ nbr)
{
    __shared__ float s[NP1 + 12];
    __shared__ float xi[HC];
    __shared__ float rv[8]; __shared__ int ri[8];
    const int i = blockIdx.x, tid = threadIdx.x;
    if (tid < HC) xi[tid] = x[(size_t)i * HC + tid];
    __syncthreads();
    const float sqi = sq[i];
    for (int j = tid; j < Nn; j += 256) {
        const float* xj = x + (size_t)j * HC;
        float dot = 0.f;
#pragma unroll
        for (int c = 0; c < HC; c++) dot += xi[c] * xj[c];
        s[j] = 2.f * dot - sqi - sq[j];
    }
    __syncthreads();
    for (int it = 0; it < KNN; it++) {
        float bv = -FLT_MAX; int bi = 1 << 30;
        for (int j = tid; j < Nn; j += 256) {
            float v = s[j];
            if (v > bv || (v == bv && j < bi)) { bv = v; bi = j; }
        }
        for (int off = 16; off; off >>= 1) {
            float ov = __shfl_down_sync(0xffffffffu, bv, off);
            int   oi = __shfl_down_sync(0xffffffffu, bi, off);
            if (ov > bv || (ov == bv && oi < bi)) { bv = ov; bi = oi; }
        }
        if ((tid & 31) == 0) { rv[tid >> 5] = bv; ri[tid >> 5] = bi; }
        __syncthreads();
        if (tid == 0) {
            float fv = rv[0]; int fi = ri[0];
            for (int w = 1; w < 8; w++)
                if (rv[w] > fv || (rv[w] == fv && ri[w] < fi)) { fv = rv[w]; fi = ri[w]; }
            nbr[i * KNN + it] = fi;
            s[fi] = -FLT_MAX;
        }
        __syncthreads();
    }
}

__global__ __launch_bounds__(256)
void pq1_kernel(const float* __restrict__ tf, const float* __restrict__ w1,
                float* __restrict__ p, float* __restrict__ q)
{
    __shared__ float redm[8][32];
    const int n = blockIdx.x, tid = threadIdx.x;
    float ap[HC], aq[HC];
#pragma unroll
    for (int c = 0; c < HC; c++) { ap[c] = 0.f; aq[c] = 0.f; }
    for (int f = tid; f < FEAT; f += 256) {
        float xv = tf[(size_t)n * FEAT + f];
        const float4* wp = (const float4*)(w1 + (size_t)f * HC);
        const float4* wq = (const float4*)(w1 + (size_t)(FEAT + f) * HC);
#pragma unroll
        for (int c4 = 0; c4 < 4; c4++) {
            float4 a = wp[c4];
            ap[c4*4+0] += xv*a.x; ap[c4*4+1] += xv*a.y;
            ap[c4*4+2] += xv*a.z; ap[c4*4+3] += xv*a.w;
            float4 b = wq[c4];
            aq[c4*4+0] += xv*b.x; aq[c4*4+1] += xv*b.y;
            aq[c4*4+2] += xv*b.z; aq[c4*4+3] += xv*b.w;
        }
    }
    const int lane = tid & 31, wid = tid >> 5;
    for (int c = 0; c < 32; c++) {
        float v = (c < HC) ? ap[c] : aq[c - HC];
        for (int off = 16; off; off >>= 1) v += __shfl_down_sync(0xffffffffu, v, off);
        if (lane == 0) redm[wid][c] = v;
    }
    __syncthreads();
    if (tid < 32) {
        float v = 0.f;
        for (int w = 0; w < 8; w++) v += redm[w][tid];
        if (tid < HC) p[(size_t)n * HC + tid] = v;
        else          q[(size_t)n * HC + tid - HC] = v;
    }
}

__global__ __launch_bounds__(256)
void pq2_kernel(const float* __restrict__ x, const float* __restrict__ w1,
                float* __restrict__ p, float* __restrict__ q, int Nn)
{
    int n = blockIdx.x * blockDim.x + threadIdx.x;
    if (n >= Nn) return;
    float xi[HC];
#pragma unroll
    for (int c = 0; c < HC; c++) xi[c] = x[(size_t)n * HC + c];
#pragma unroll
    for (int c = 0; c < HC; c++) {
        float pp = 0.f, qq = 0.f;
#pragma unroll
        for (int u = 0; u < HC; u++) {
            pp += xi[u] * w1[u * HC + c];
            qq += xi[u] * w1[(HC + u) * HC + c];
        }
        p[(size_t)n * HC + c] = pp;
        q[(size_t)n * HC + c] = qq;
    }
}

__global__ __launch_bounds__(256)
void edge_kernel(const float* __restrict__ p, const float* __restrict__ q,
                 const float* __restrict__ b1, const float* __restrict__ w2,
                 const float* __restrict__ b2, const int* __restrict__ nbr,
                 float* __restrict__ out, int Nn, int doRelu)
{
    __shared__ float w2s[HC*HC];
    __shared__ float b1s[HC], b2s[HC];
    const int tid = threadIdx.x;
    if (tid < HC*HC) w2s[tid] = w2[tid];
    if (tid < HC) { b1s[tid] = b1[tid]; b2s[tid] = b2[tid]; }
    __syncthreads();
    const int n = blockIdx.x * blockDim.x + tid;
    if (n >= Nn) return;
    float base[HC], best[HC];
#pragma unroll
    for (int c = 0; c < HC; c++) {
        base[c] = p[(size_t)n*HC + c] - q[(size_t)n*HC + c] + b1s[c];
        best[c] = -FLT_MAX;
    }
    for (int kk = 0; kk < KNN; kk++) {
        int j = nbr[n * KNN + kk];
        const float* qj = q + (size_t)j * HC;
        float o[HC];
#pragma unroll
        for (int c = 0; c < HC; c++) o[c] = b2s[c];
#pragma unroll
        for (int u = 0; u < HC; u++) {
            float hv = base[u] + qj[u];
            hv = hv > 0.f ? hv : 0.f;
#pragma unroll
            for (int c = 0; c < HC; c++) o[c] += hv * w2s[u*HC + c];
        }
#pragma unroll
        for (int c = 0; c < HC; c++) best[c] = fmaxf(best[c], o[c]);
    }
#pragma unroll
    for (int c = 0; c < HC; c++) {
        float v = best[c];
        if (doRelu) v = fmaxf(v, 0.f);
        out[(size_t)n * HC + c] = v;
    }
}

__global__ void score_kernel(const float* __restrict__ x, const float* __restrict__ w,
                             int Nn, float* __restrict__ s)
{
    int n = blockIdx.x * blockDim.x + threadIdx.x;
    if (n >= Nn) return;
    float nw = 0.f, d = 0.f;
#pragma unroll
    for (int c = 0; c < HC; c++) nw += w[c] * w[c];
    nw = sqrtf(nw);
#pragma unroll
    for (int c = 0; c < HC; c++) d += x[(size_t)n*HC + c] * w[c];
    s[n] = tanhf(d / nw);
}

__global__ void sq_kernel(const float* __restrict__ x, int Nn, float* __restrict__ sq)
{
    int n = blockIdx.x * blockDim.x + threadIdx.x;
    if (n >= Nn) return;
    float a = 0.f;
#pragma unroll
    for (int c = 0; c < HC; c++) { float v = x[(size_t)n*HC + c]; a += v * v; }
    sq[n] = a;
}

__global__ void rank_pool_kernel(const float* __restrict__ x, const float* __restrict__ s,
                                 int Nn, int nkeep, float* __restrict__ out)
{
    int n = blockIdx.x * blockDim.x + threadIdx.x;
    if (n >= Nn) return;
    float sn = s[n];
    int rank = 0;
    for (int m = 0; m < Nn; m++) {
        float sm = s[m];
        if (sm > sn || (sm == sn && m < n)) rank++;
    }
    if (rank < nkeep) {
#pragma unroll
        for (int c = 0; c < HC; c++)
            out[(size_t)rank * HC + c] = x[(size_t)n * HC + c] * sn;
    }
}

__global__ __launch_bounds__(256)
void gap_kernel(const float* __restrict__ x, const float* __restrict__ gw,
                const float* __restrict__ gb, int Nn, float* __restrict__ vec)
{
    __shared__ float a[NP1 + 12];
    __shared__ float red[8];
    const int tid = threadIdx.x;
    float lmax = -FLT_MAX;
    for (int n = tid; n < Nn; n += 256) {
        float d = gb[0];
#pragma unroll
        for (int c = 0; c < HC; c++) d += x[(size_t)n*HC + c] * gw[c];
        a[n] = d;
        lmax = fmaxf(lmax, d);
    }
    for (int off = 16; off; off >>= 1) lmax = fmaxf(lmax, __shfl_xor_sync(0xffffffffu, lmax, off));
    if ((tid & 31) == 0) red[tid >> 5] = lmax;
    __syncthreads();
    lmax = red[0];
    for (int w = 1; w < 8; w++) lmax = fmaxf(lmax, red[w]);
    __syncthreads();
    float lsum = 0.f;
    for (int n = tid; n < Nn; n += 256) {
        float e = expf(a[n] - lmax);
        a[n] = e;
        lsum += e;
    }
    for (int off = 16; off; off >>= 1) lsum += __shfl_xor_sync(0xffffffffu, lsum, off);
    if ((tid & 31) == 0) red[tid >> 5] = lsum;
    __syncthreads();
    lsum = 0.f;
    for (int w = 0; w < 8; w++) lsum += red[w];
    if (tid < HC) {
        float v = 0.f;
        for (int n = 0; n < Nn; n++) v += a[n] * x[(size_t)n*HC + tid];
        vec[tid] = v / lsum;
    }
}

__global__ void final_kernel(const float* __restrict__ v1, const float* __restrict__ v2,
                             const float* __restrict__ w, const float* __restrict__ b,
                             float* __restrict__ out)
{
    int c = threadIdx.x;
    if (c < 2) {
        float acc = b[c];
#pragma unroll
        for (int u = 0; u < HC; u++) acc += (v1[u] + v2[u]) * w[u*2 + c];
        out[c] = acc;
    }
}

// ---------------- launch ----------------
extern "C" void kernel_launch(void* const* d_in, const int* in_sizes, int n_in,
                              void* d_out, int out_size)
{
    const float* ts   = (const float*)d_in[0];
    const float* c1w  = (const float*)d_in[1];
    const float* c1b  = (const float*)d_in[2];
    const float* c2w  = (const float*)d_in[3];
    const float* c2b  = (const float*)d_in[4];
    const float* c3w  = (const float*)d_in[5];
    const float* c3b  = (const float*)d_in[6];
    const float* wih  = (const float*)d_in[7];
    const float* whh  = (const float*)d_in[8];
    const float* bih  = (const float*)d_in[9];
    const float* bhh  = (const float*)d_in[10];
    const float* m1w1 = (const float*)d_in[11];
    const float* m1b1 = (const float*)d_in[12];
    const float* m1w2 = (const float*)d_in[13];
    const float* m1b2 = (const float*)d_in[14];
    const float* p1w  = (const float*)d_in[15];
    const float* g1w  = (const float*)d_in[16];
    const float* g1b  = (const float*)d_in[17];
    const float* m2w1 = (const float*)d_in[18];
    const float* m2b1 = (const float*)d_in[19];
    const float* m2w2 = (const float*)d_in[20];
    const float* m2b2 = (const float*)d_in[21];
    const float* p2w  = (const float*)d_in[22];
    const float* g2w  = (const float*)d_in[23];
    const float* g2b  = (const float*)d_in[24];
    const float* l2w  = (const float*)d_in[25];
    const float* l2b  = (const float*)d_in[26];
    float* out        = (float*)d_out;

    float *gi, *tf, *G, *dg, *p1, *q1, *x1f, *sc1, *pool1, *vec1;
    float *sq2, *p2, *q2, *x2f, *sc2, *pool2, *vec2;
    int *nbr1, *nbr2;
    __nv_bfloat16 *xa_hi, *xa_lo, *xb_hi, *xb_lo, *wk_hi, *wk_lo;
    __nv_bfloat16 *tfhi, *tflo, *wihhi, *wihlo;
    cudaGetSymbolAddress((void**)&gi,    g_gi);
    cudaGetSymbolAddress((void**)&tf,    g_tfeat);
    cudaGetSymbolAddress((void**)&tfhi,  g_tf_hi);
    cudaGetSymbolAddress((void**)&tflo,  g_tf_lo);
    cudaGetSymbolAddress((void**)&G,     g_G);
    cudaGetSymbolAddress((void**)&dg,    g_diag);
    cudaGetSymbolAddress((void**)&nbr1,  g_nbr1);
    cudaGetSymbolAddress((void**)&p1,    g_p1);
    cudaGetSymbolAddress((void**)&q1,    g_q1);
    cudaGetSymbolAddress((void**)&x1f,   g_x1f);
    cudaGetSymbolAddress((void**)&sc1,   g_sc1);
    cudaGetSymbolAddress((void**)&pool1, g_pool1);
    cudaGetSymbolAddress((void**)&vec1,  g_vec1);
    cudaGetSymbolAddress((void**)&sq2,   g_sq2);
    cudaGetSymbolAddress((void**)&nbr2,  g_nbr2);
    cudaGetSymbolAddress((void**)&p2,    g_p2);
    cudaGetSymbolAddress((void**)&q2,    g_q2);
    cudaGetSymbolAddress((void**)&x2f,   g_x2f);
    cudaGetSymbolAddress((void**)&sc2,   g_sc2);
    cudaGetSymbolAddress((void**)&pool2, g_pool2);
    cudaGetSymbolAddress((void**)&vec2,  g_vec2);
    cudaGetSymbolAddress((void**)&xa_hi, g_xa_hi);
    cudaGetSymbolAddress((void**)&xa_lo, g_xa_lo);
    cudaGetSymbolAddress((void**)&xb_hi, g_xb_hi);
    cudaGetSymbolAddress((void**)&xb_lo, g_xb_lo);
    cudaGetSymbolAddress((void**)&wk_hi, g_wk_hi);
    cudaGetSymbolAddress((void**)&wk_lo, g_wk_lo);
    cudaGetSymbolAddress((void**)&wihhi, g_wih_hi);
    cudaGetSymbolAddress((void**)&wihlo, g_wih_lo);

    cudaFuncSetAttribute(conv_wmma_kernel, cudaFuncAttributeMaxDynamicSharedMemorySize, CV_SMEM);
    cudaFuncSetAttribute(wmma3_nt, cudaFuncAttributeMaxDynamicSharedMemorySize, WM_SMEM);

    // prep: pad zeros, transpose input, repack weights
    zero_pad_kernel<<<512, 256>>>(xa_hi, xa_lo, xb_hi, xb_lo);
    prep_x_kernel<<<dim3(32, 4, 32), 256>>>(ts, xa_hi, xa_lo);
    prep_w_kernel<<<1024, 256>>>(c1w, wk_hi, wk_lo);
    conv_wmma_kernel<<<dim3(8, 32), 256, CV_SMEM>>>(xa_hi, xa_lo, wk_hi, wk_lo, c1b,
                                                    xb_hi, xb_lo, 0);
    prep_w_kernel<<<1024, 256>>>(c2w, wk_hi, wk_lo);
    conv_wmma_kernel<<<dim3(8, 32), 256, CV_SMEM>>>(xb_hi, xb_lo, wk_hi, wk_lo, c2b,
                                                    xa_hi, xa_lo, 0);
    prep_w_kernel<<<1024, 256>>>(c3w, wk_hi, wk_lo);
    // conv3: write hi/lo row-major [t*1024+o][128] into the freed xb buffers
    conv_wmma_kernel<<<dim3(8, 32), 256, CV_SMEM>>>(xa_hi, xa_lo, wk_hi, wk_lo, c3b,
                                                    xb_hi, xb_lo, 1);

    // gi = d @ wih.T + bih  (wmma 3-pass)
    split_kernel<<<(3*HG*D_ + 255)/256, 256>>>(wih, wihhi, wihlo, 3*HG*D_);
    wmma3_nt<<<dim3(5, (T_*N_)/128), 256, WM_SMEM>>>(xb_hi, xb_lo, wihhi, wihlo,
                                                     bih, gi, T_*N_, 3*HG, D_);
    gru_kernel<<<N_/8, 320>>>(gi, whh, bhh, tf, tfhi, tflo);

    // Gram (wmma 3-pass) + knn1
    wmma3_nt<<<dim3(16, 8), 256, WM_SMEM>>>(tfhi, tflo, tfhi, tflo,
                                            nullptr, G, N_, N_, FEAT);
    diag_kernel<<<4, 256>>>(G, dg);
    topk1_kernel<<<N_, 256>>>(G, dg, nbr1);

    // DGCN1
    pq1_kernel<<<N_, 256>>>(tf, m1w1, p1, q1);
    edge_kernel<<<4, 256>>>(p1, q1, m1b1, m1w2, m1b2, nbr1, x1f, N_, 1);

    score_kernel<<<4, 256>>>(x1f, p1w, N_, sc1);
    rank_pool_kernel<<<4, 256>>>(x1f, sc1, N_, NP1, pool1);
    gap_kernel<<<1, 256>>>(pool1, g1w, g1b, NP1, vec1);

    // DGCN2
    sq_kernel<<<4, 256>>>(pool1, NP1, sq2);
    topk2_kernel<<<NP1, 256>>>(pool1, sq2, NP1, nbr2);
    pq2_kernel<<<4, 256>>>(pool1, m2w1, p2, q2, NP1);
    edge_kernel<<<4, 256>>>(p2, q2, m2b1, m2w2, m2b2, nbr2, x2f, NP1, 0);

    score_kernel<<<4, 256>>>(x2f, p2w, NP1, sc2);
    rank_pool_kernel<<<4, 256>>>(x2f, sc2, NP1, NP2, pool2);
    gap_kernel<<<1, 256>>>(pool2, g2w, g2b, NP2, vec2);

    final_kernel<<<1, 32>>>(vec1, vec2, l2w, l2b, out);
}

// round 16
// speedup vs baseline: 2.8647x; 1.0513x over previous
#include <cuda_runtime.h>
#include <cuda_bf16.h>
#include <mma.h>
#include <math.h>
#include <float.h>
#include <stdint.h>

using namespace nvcuda;

#define T_   32
#define N_   1024
#define D_   128
#define HG   100
#define FEAT 3200
#define HC   16
#define KNN  20
#define NP1  820
#define NP2  656

// ---------------- scratch (device globals; no allocs) ----------------
__device__ float g_gi[T_*N_*3*HG];
__device__ float g_tfeat[N_*FEAT];
__device__ __nv_bfloat16 g_tf_hi[N_*FEAT];
__device__ __nv_bfloat16 g_tf_lo[N_*FEAT];
__device__ float g_G[N_*N_];
__device__ float g_diag[N_];
__device__ int   g_nbr1[N_*KNN];
__device__ float g_p1[N_*HC], g_q1[N_*HC];
__device__ float g_x1f[N_*HC];
__device__ float g_sc1[N_];
__device__ float g_pool1[NP1*HC];
__device__ float g_vec1[HC];
__device__ float g_sq2[NP1];
__device__ int   g_nbr2[NP1*KNN];
__device__ float g_p2[NP1*HC], g_q2[NP1*HC];
__device__ float g_x2f[NP1*HC];
__device__ float g_sc2[NP1];
__device__ float g_pool2[NP2*HC];
__device__ float g_vec2[HC];
// bf16 hi/lo padded transposed activations: [t][132 rows][1024 ch]
__device__ __nv_bfloat16 g_xa_hi[T_*132*1024];
__device__ __nv_bfloat16 g_xa_lo[T_*132*1024];
__device__ __nv_bfloat16 g_xb_hi[T_*132*1024];   // also reused as gi-A [32768][128]
__device__ __nv_bfloat16 g_xb_lo[T_*132*1024];
// repacked weights [k][o][ic] bf16 hi/lo
__device__ __nv_bfloat16 g_wk_hi[5*1024*1024];
__device__ __nv_bfloat16 g_wk_lo[5*1024*1024];
__device__ __nv_bfloat16 g_wih_hi[3*HG*D_];
__device__ __nv_bfloat16 g_wih_lo[3*HG*D_];

// ---------------- cp.async helpers ----------------
__device__ __forceinline__ uint32_t smem_u32(const void* p) {
    uint32_t a;
    asm("{ .reg .u64 t; cvta.to.shared.u64 t, %1; cvt.u32.u64 %0, t; }" : "=r"(a) : "l"(p));
    return a;
}
__device__ __forceinline__ void cpa16(uint32_t dst, const void* src) {
    asm volatile("cp.async.cg.shared.global [%0], [%1], 16;" :: "r"(dst), "l"(src));
}
#define CPA_COMMIT asm volatile("cp.async.commit_group;" ::: "memory")
#define CPA_WAIT0  asm volatile("cp.async.wait_group 0;" ::: "memory")

// ---------------- prep kernels ----------------
__global__ __launch_bounds__(256)
void prep_w_kernel(const float* __restrict__ w,
                   __nv_bfloat16* __restrict__ whi, __nv_bfloat16* __restrict__ wlo)
{
    __shared__ float buf[5120];
    const int o = blockIdx.x, tid = threadIdx.x;
    const float* src = w + (size_t)o * 5120;
    for (int i = tid; i < 5120; i += 256) buf[i] = src[i];
    __syncthreads();
#pragma unroll
    for (int k = 0; k < 5; k++) {
        for (int ic = tid; ic < 1024; ic += 256) {
            float v = buf[ic * 5 + k];
            __nv_bfloat16 h = __float2bfloat16(v);
            size_t idx = ((size_t)k << 20) + ((size_t)o << 10) + ic;
            whi[idx] = h;
            wlo[idx] = __float2bfloat16(v - __bfloat162float(h));
        }
    }
}

__global__ void split_kernel(const float* __restrict__ in,
                             __nv_bfloat16* __restrict__ hi, __nv_bfloat16* __restrict__ lo, int n)
{
    int i = blockIdx.x * 256 + threadIdx.x;
    if (i >= n) return;
    float v = in[i];
    __nv_bfloat16 h = __float2bfloat16(v);
    hi[i] = h;
    lo[i] = __float2bfloat16(v - __bfloat162float(h));
}

// transpose+split: in fp32 [t][c][128] -> Xp bf16 [t][h+2][c]
__global__ void prep_x_kernel(const float* __restrict__ in,
                              __nv_bfloat16* __restrict__ xhi, __nv_bfloat16* __restrict__ xlo)
{
    __shared__ float tile[32][33];
    int t = blockIdx.z, c0 = blockIdx.x * 32, h0 = blockIdx.y * 32;
    int lx = threadIdx.x & 31, ly = threadIdx.x >> 5;
#pragma unroll
    for (int i = 0; i < 4; i++) {
        int c = c0 + ly + i * 8;
        tile[ly + i * 8][lx] = in[((size_t)t * 1024 + c) * 128 + h0 + lx];
    }
    __syncthreads();
#pragma unroll
    for (int i = 0; i < 4; i++) {
        int h = h0 + ly + i * 8;
        float v = tile[lx][ly + i * 8];
        __nv_bfloat16 hb = __float2bfloat16(v);
        size_t o = ((size_t)t * 132 + h + 2) * 1024 + c0 + lx;
        xhi[o] = hb;
        xlo[o] = __float2bfloat16(v - __bfloat162float(hb));
    }
}

__global__ void zero_pad_kernel(__nv_bfloat16* a, __nv_bfloat16* b,
                                __nv_bfloat16* c, __nv_bfloat16* d)
{
    int idx = blockIdx.x * 256 + threadIdx.x;   // 32t * 4rows * 1024
    if (idx >= 32 * 4 * 1024) return;
    int t = idx >> 12, r = (idx >> 10) & 3, ic = idx & 1023;
    int hp = (r < 2) ? r : 128 + r;
    size_t o = ((size_t)t * 132 + hp) * 1024 + ic;
    __nv_bfloat16 z = __float2bfloat16(0.f);
    a[o] = z; b[o] = z; c[o] = z; d[o] = z;
}

// ---------------- wmma conv kernel (cp.async double-buffered, ic-chunk 32) ----------------
#define XLD2 40
#define CV_XB 21120u
#define CV_WOFF 42240u
#define CV_WB 20480u
#define CV_SMEM 83200

__device__ __forceinline__ void conv_issue_stage(
    int qq, int tid, int t, int o0, uint32_t smX, uint32_t smW,
    const __nv_bfloat16* xhi, const __nv_bfloat16* xlo,
    const __nv_bfloat16* whi, const __nv_bfloat16* wlo)
{
    const int ch = qq / 5, s = qq % 5, ic0 = ch << 5;
    const uint32_t wb = smW + (uint32_t)(qq & 1) * CV_WB;
    for (int u = tid; u < 1024; u += 256) {
        int p = u >> 9, r = u & 511;
        int row = r >> 2, cb = r & 3;
        const __nv_bfloat16* src = (p ? wlo : whi)
            + ((size_t)s << 20) + ((size_t)(o0 + row) << 10) + ic0 + cb * 8;
        cpa16(wb + (uint32_t)(p * 128 + row) * 80u + cb * 16, src);
    }
    if (s == 0) {
        const uint32_t xb = smX + (uint32_t)(ch & 1) * CV_XB;
        for (int u = tid; u < 1056; u += 256) {
            int p = (u >= 528) ? 1 : 0;
            int r = u - p * 528;
            int row = r >> 2, cb = r & 3;
            const __nv_bfloat16* src = (p ? xlo : xhi)
                + (((size_t)t * 132 + row) << 10) + ic0 + cb * 8;
            cpa16(xb + (uint32_t)(p * 132 + row) * 80u + cb * 16, src);
        }
    }
    CPA_COMMIT;
}

__global__ __launch_bounds__(256, 2)
void conv_wmma_kernel(const __nv_bfloat16* __restrict__ xhi, const __nv_bfloat16* __restrict__ xlo,
                      const __nv_bfloat16* __restrict__ whi, const __nv_bfloat16* __restrict__ wlo,
                      const float* __restrict__ bias,
                      __nv_bfloat16* __restrict__ ohi, __nv_bfloat16* __restrict__ olo,
                      int mode)
{
    extern __shared__ char smem[];
    const uint32_t smX = smem_u32(smem);
    const uint32_t smW = smX + CV_WOFF;
    float* cs = (float*)smem;

    const int tid = threadIdx.x;
    const int wid = tid >> 5;
    const int o0 = blockIdx.x * 128;
    const int t  = blockIdx.y;
    const int m0 = (wid >> 1) * 32;
    const int n0 = (wid & 1) * 64;

    wmma::fragment<wmma::accumulator, 16, 16, 16, float> acc[2][4];
#pragma unroll
    for (int i = 0; i < 2; i++)
#pragma unroll
        for (int j = 0; j < 4; j++) wmma::fill_fragment(acc[i][j], 0.f);

    conv_issue_stage(0, tid, t, o0, smX, smW, xhi, xlo, whi, wlo);

    for (int q = 0; q < 160; q++) {
        const int ch = q / 5, s = q % 5;
        CPA_WAIT0;
        __syncthreads();
        if (q < 159)
            conv_issue_stage(q + 1, tid, t, o0, smX, smW, xhi, xlo, whi, wlo);

        const __nv_bfloat16* Xbase = (const __nv_bfloat16*)(smem) + (size_t)(ch & 1) * (2*132*XLD2);
        const __nv_bfloat16* Wbase = (const __nv_bfloat16*)(smem + CV_WOFF) + (size_t)(q & 1) * (2*128*XLD2);
        const __nv_bfloat16* Whi_s = Wbase;
        const __nv_bfloat16* Wlo_s = Wbase + 128*XLD2;
        const __nv_bfloat16* Xhi_s = Xbase + (size_t)s * XLD2;
        const __nv_bfloat16* Xlo_s = Xbase + 132*XLD2 + (size_t)s * XLD2;

#pragma unroll
        for (int ks = 0; ks < 2; ks++) {
            wmma::fragment<wmma::matrix_a, 16, 16, 16, __nv_bfloat16, wmma::row_major> ah[2], al[2];
            wmma::fragment<wmma::matrix_b, 16, 16, 16, __nv_bfloat16, wmma::col_major> bh[4], bl[4];
#pragma unroll
            for (int i = 0; i < 2; i++) {
                wmma::load_matrix_sync(ah[i], Whi_s + (m0 + i * 16) * XLD2 + ks * 16, XLD2);
                wmma::load_matrix_sync(al[i], Wlo_s + (m0 + i * 16) * XLD2 + ks * 16, XLD2);
            }
#pragma unroll
            for (int j = 0; j < 4; j++) {
                wmma::load_matrix_sync(bh[j], Xhi_s + (n0 + j * 16) * XLD2 + ks * 16, XLD2);
                wmma::load_matrix_sync(bl[j], Xlo_s + (n0 + j * 16) * XLD2 + ks * 16, XLD2);
            }
#pragma unroll
            for (int i = 0; i < 2; i++)
#pragma unroll
                for (int j = 0; j < 4; j++) wmma::mma_sync(acc[i][j], ah[i], bh[j], acc[i][j]);
#pragma unroll
            for (int i = 0; i < 2; i++)
#pragma unroll
                for (int j = 0; j < 4; j++) wmma::mma_sync(acc[i][j], ah[i], bl[j], acc[i][j]);
#pragma unroll
            for (int i = 0; i < 2; i++)
#pragma unroll
                for (int j = 0; j < 4; j++) wmma::mma_sync(acc[i][j], al[i], bh[j], acc[i][j]);
        }
    }

    __syncthreads();
#pragma unroll
    for (int i = 0; i < 2; i++)
#pragma unroll
        for (int j = 0; j < 4; j++)
            wmma::store_matrix_sync(cs + (m0 + i * 16) * 132 + (n0 + j * 16),
                                    acc[i][j], 132, wmma::mem_row_major);
    __syncthreads();

    if (mode == 0) {
        for (int idx = tid; idx < 128 * 128; idx += 256) {
            int o_r = idx & 127, h = idx >> 7;
            float v = cs[o_r * 132 + h] + bias[o0 + o_r];
            v = v > 0.f ? v : 0.1f * v;
            __nv_bfloat16 hb = __float2bfloat16(v);
            size_t g = (((size_t)t * 132) + h + 2) * 1024 + o0 + o_r;
            ohi[g] = hb;
            olo[g] = __float2bfloat16(v - __bfloat162float(hb));
        }
    } else {
        for (int idx = tid; idx < 128 * 128; idx += 256) {
            int h = idx & 127, o_r = idx >> 7;
            float v = cs[o_r * 132 + h] + bias[o0 + o_r];
            v = v > 0.f ? v : 0.1f * v;
            __nv_bfloat16 hb = __float2bfloat16(v);
            size_t g = ((size_t)t * 1024 + o0 + o_r) * 128 + h;
            ohi[g] = hb;
            olo[g] = __float2bfloat16(v - __bfloat162float(hb));
        }
    }
}

// ------------- generic 3-pass bf16 wmma GEMM-NT (cp.async double-buffered) -------------
// C[m][n] = sum_k A[m][k]*B[n][k] (+bias[n]); M%128==0, K%64==0, N guarded.
// smem: As [2 buf][2 split][128][72], Bs [2 buf][2 split][64][72] bf16 = 110592 B.
#define WM_AB 18432      // halfs per A buffer (2*128*72)
#define WM_BB 9216       // halfs per B buffer (2*64*72)
#define WM_SMEM 110592

__device__ __forceinline__ void wm_issue(
    int k0, int buf, int tid, int m0g, int n0g, int Ncols, int Kd,
    uint32_t smA, uint32_t smB,
    const __nv_bfloat16* Ahi, const __nv_bfloat16* Alo,
    const __nv_bfloat16* Bhi, const __nv_bfloat16* Blo)
{
    const uint32_t ab = smA + (uint32_t)buf * (WM_AB * 2);
    for (int u = tid; u < 2048; u += 256) {
        int p = u >> 10, r = u & 1023;
        int row = r >> 3, cb = (r & 7) << 3;
        cpa16(ab + (uint32_t)((p * 128 + row) * 72 + cb) * 2,
              (p ? Alo : Ahi) + (size_t)(m0g + row) * Kd + k0 + cb);
    }
    const uint32_t bb = smB + (uint32_t)buf * (WM_BB * 2);
    for (int u = tid; u < 1024; u += 256) {
        int p = u >> 9, r = u & 511;
        int row = r >> 3, cb = (r & 7) << 3;
        if (n0g + row < Ncols)
            cpa16(bb + (uint32_t)((p * 64 + row) * 72 + cb) * 2,
                  (p ? Blo : Bhi) + (size_t)(n0g + row) * Kd + k0 + cb);
    }
    CPA_COMMIT;
}

__global__ __launch_bounds__(256, 2)
void wmma3_nt(const __nv_bfloat16* __restrict__ Ahi, const __nv_bfloat16* __restrict__ Alo,
              const __nv_bfloat16* __restrict__ Bhi, const __nv_bfloat16* __restrict__ Blo,
              const float* __restrict__ bias, float* __restrict__ C,
              int M, int Ncols, int Kd)
{
    extern __shared__ char sm[];
    __nv_bfloat16* As = (__nv_bfloat16*)sm;
    __nv_bfloat16* Bs = As + 2 * WM_AB;
    float* cs = (float*)sm;
    const uint32_t smA = smem_u32(As);
    const uint32_t smB = smem_u32(Bs);
    const int tid = threadIdx.x, wid = tid >> 5;
    const int n0g = blockIdx.x * 64, m0g = blockIdx.y * 128;
    const int m0 = (wid >> 1) * 32, n0 = (wid & 1) * 32;

    // pre-zero B buffers (OOB rows are never async-written)
    for (int u = tid; u < 2 * WM_BB / 8; u += 256)
        *(uint4*)(Bs + u * 8) = make_uint4(0, 0, 0, 0);
    __syncthreads();

    wmma::fragment<wmma::accumulator, 16, 16, 16, float> acc[2][2];
#pragma unroll
    for (int i = 0; i < 2; i++)
#pragma unroll
        for (int j = 0; j < 2; j++) wmma::fill_fragment(acc[i][j], 0.f);

    wm_issue(0, 0, tid, m0g, n0g, Ncols, Kd, smA, smB, Ahi, Alo, Bhi, Blo);

    const int nk = Kd >> 6;
    for (int kk = 0; kk < nk; kk++) {
        CPA_WAIT0;
        __syncthreads();
        if (kk + 1 < nk)
            wm_issue((kk + 1) << 6, (kk + 1) & 1, tid, m0g, n0g, Ncols, Kd,
                     smA, smB, Ahi, Alo, Bhi, Blo);

        const __nv_bfloat16* Ab = As + (size_t)(kk & 1) * WM_AB;
        const __nv_bfloat16* Bb = Bs + (size_t)(kk & 1) * WM_BB;
#pragma unroll
        for (int ks = 0; ks < 4; ks++) {
            wmma::fragment<wmma::matrix_a, 16, 16, 16, __nv_bfloat16, wmma::row_major> ah[2], al[2];
            wmma::fragment<wmma::matrix_b, 16, 16, 16, __nv_bfloat16, wmma::col_major> bh[2], bl[2];
#pragma unroll
            for (int i = 0; i < 2; i++) {
                wmma::load_matrix_sync(ah[i], Ab + (m0 + i * 16) * 72 + ks * 16, 72);
                wmma::load_matrix_sync(al[i], Ab + 128*72 + (m0 + i * 16) * 72 + ks * 16, 72);
            }
#pragma unroll
            for (int j = 0; j < 2; j++) {
                wmma::load_matrix_sync(bh[j], Bb + (n0 + j * 16) * 72 + ks * 16, 72);
                wmma::load_matrix_sync(bl[j], Bb + 64*72 + (n0 + j * 16) * 72 + ks * 16, 72);
            }
#pragma unroll
            for (int i = 0; i < 2; i++)
#pragma unroll
                for (int j = 0; j < 2; j++) wmma::mma_sync(acc[i][j], ah[i], bh[j], acc[i][j]);
#pragma unroll
            for (int i = 0; i < 2; i++)
#pragma unroll
                for (int j = 0; j < 2; j++) wmma::mma_sync(acc[i][j], ah[i], bl[j], acc[i][j]);
#pragma unroll
            for (int i = 0; i < 2; i++)
#pragma unroll
                for (int j = 0; j < 2; j++) wmma::mma_sync(acc[i][j], al[i], bh[j], acc[i][j]);
        }
    }
    __syncthreads();
#pragma unroll
    for (int i = 0; i < 2; i++)
#pragma unroll
        for (int j = 0; j < 2; j++)
            wmma::store_matrix_sync(cs + (m0 + i * 16) * 68 + (n0 + j * 16),
                                    acc[i][j], 68, wmma::mem_row_major);
    __syncthreads();
    for (int idx = tid; idx < 128 * 64; idx += 256) {
        int m_r = idx >> 6, nn = idx & 63;
        int n = n0g + nn;
        if (n < Ncols)
            C[(size_t)(m0g + m_r) * Ncols + n] = cs[m_r * 68 + nn] + (bias ? bias[n] : 0.f);
    }
}

// ---------------- GRU over T=32 (8 nodes / block) ----------------
__global__ __launch_bounds__(320)
void gru_kernel(const float* __restrict__ gi, const float* __restrict__ whh,
                const float* __restrict__ bhh, float* __restrict__ tf,
                __nv_bfloat16* __restrict__ tfhi, __nv_bfloat16* __restrict__ tflo)
{
    __shared__ float h_s[8][HG];
    __shared__ float gh_s[8][304];
    const int tid = threadIdx.x;
    const int n0 = blockIdx.x * 8;
    for (int p = tid; p < 8 * HG; p += 320) h_s[p / HG][p % HG] = 0.f;
    __syncthreads();

    for (int t = 0; t < T_; t++) {
        if (tid < 300) {
            const int j = tid;
            float acc[8];
#pragma unroll
            for (int n = 0; n < 8; n++) acc[n] = 0.f;
            const float4* wr = (const float4*)(whh + (size_t)j * HG);
#pragma unroll 5
            for (int d4 = 0; d4 < HG / 4; d4++) {
                float4 w4 = wr[d4];
#pragma unroll
                for (int n = 0; n < 8; n++) {
                    float4 h4 = ((const float4*)h_s[n])[d4];
                    acc[n] += w4.x*h4.x + w4.y*h4.y + w4.z*h4.z + w4.w*h4.w;
                }
            }
            float bb = bhh[j];
#pragma unroll
            for (int n = 0; n < 8; n++) gh_s[n][j] = acc[n] + bb;
        }
        __syncthreads();
        for (int p = tid; p < 8 * HG; p += 320) {
            int n = p / HG, d = p % HG;
            int ng = n0 + n;
            const float* gin = gi + ((size_t)t * N_ + ng) * (3 * HG);
            float rg = 1.f / (1.f + expf(-(gin[d]        + gh_s[n][d])));
            float zg = 1.f / (1.f + expf(-(gin[HG + d]   + gh_s[n][HG + d])));
            float nn = tanhf(gin[2*HG + d] + rg * gh_s[n][2*HG + d]);
            float hnew = (1.f - zg) * nn + zg * h_s[n][d];
            float act = hnew > 0.f ? hnew : 0.1f * hnew;
            size_t idx = (size_t)ng * FEAT + t * HG + d;
            tf[idx] = act;
            __nv_bfloat16 hb = __float2bfloat16(act);
            tfhi[idx] = hb;
            tflo[idx] = __float2bfloat16(act - __bfloat162float(hb));
            h_s[n][d] = hnew;
        }
        __syncthreads();
    }
}

// ---------------- small kernels ----------------
__global__ void diag_kernel(const float* __restrict__ G, float* __restrict__ dg)
{
    int n = blockIdx.x * blockDim.x + threadIdx.x;
    if (n < N_) dg[n] = G[(size_t)n * N_ + n];
}

__global__ __launch_bounds__(256)
void topk1_kernel(const float* __restrict__ G, const float* __restrict__ dg,
                  int* __restrict__ nbr)
{
    __shared__ float s[N_];
    __shared__ float rv[8]; __shared__ int ri[8];
    const int i = blockIdx.x, tid = threadIdx.x;
    const float dii = dg[i];
    for (int j = tid; j < N_; j += 256) s[j] = 2.f * G[(size_t)i * N_ + j] - dii - dg[j];
    __syncthreads();
    for (int it = 0; it < KNN; it++) {
        float bv = -FLT_MAX; int bi = 1 << 30;
        for (int j = tid; j < N_; j += 256) {
            float v = s[j];
            if (v > bv || (v == bv && j < bi)) { bv = v; bi = j; }
        }
        for (int off = 16; off; off >>= 1) {
            float ov = __shfl_down_sync(0xffffffffu, bv, off);
            int   oi = __shfl_down_sync(0xffffffffu, bi, off);
            if (ov > bv || (ov == bv && oi < bi)) { bv = ov; bi = oi; }
        }
        if ((tid & 31) == 0) { rv[tid >> 5] = bv; ri[tid >> 5] = bi; }
        __syncthreads();
        if (tid == 0) {
            float fv = rv[0]; int fi = ri[0];
            for (int w = 1; w < 8; w++)
                if (rv[w] > fv || (rv[w] == fv && ri[w] < fi)) { fv = rv[w]; fi = ri[w]; }
            nbr[i * KNN + it] = fi;
            s[fi] = -FLT_MAX;
        }
        __syncthreads();
    }
}

__global__ __launch_bounds__(256)
void topk2_kernel(const float* __restrict__ x, const float* __restrict__ sq,
                  int Nn, int* __restrict__ nbr)
{
    __shared__ float s[NP1 + 12];
    __shared__ float xi[HC];
    __shared__ float rv[8]; __shared__ int ri[8];
    const int i = blockIdx.x, tid = threadIdx.x;
    if (tid < HC) xi[tid] = x[(size_t)i * HC + tid];
    __syncthreads();
    const float sqi = sq[i];
    for (int j = tid; j < Nn; j += 256) {
        const float* xj = x + (size_t)j * HC;
        float dot = 0.f;
#pragma unroll
        for (int c = 0; c < HC; c++) dot += xi[c] * xj[c];
        s[j] = 2.f * dot - sqi - sq[j];
    }
    __syncthreads();
    for (int it = 0; it < KNN; it++) {
        float bv = -FLT_MAX; int bi = 1 << 30;
        for (int j = tid; j < Nn; j += 256) {
            float v = s[j];
            if (v > bv || (v == bv && j < bi)) { bv = v; bi = j; }
        }
        for (int off = 16; off; off >>= 1) {
            float ov = __shfl_down_sync(0xffffffffu, bv, off);
            int   oi = __shfl_down_sync(0xffffffffu, bi, off);
            if (ov > bv || (ov == bv && oi < bi)) { bv = ov; bi = oi; }
        }
        if ((tid & 31) == 0) { rv[tid >> 5] = bv; ri[tid >> 5] = bi; }
        __syncthreads();
        if (tid == 0) {
            float fv = rv[0]; int fi = ri[0];
            for (int w = 1; w < 8; w++)
                if (rv[w] > fv || (rv[w] == fv && ri[w] < fi)) { fv = rv[w]; fi = ri[w]; }
            nbr[i * KNN + it] = fi;
            s[fi] = -FLT_MAX;
        }
        __syncthreads();
    }
}

__global__ __launch_bounds__(256)
void pq1_kernel(const float* __restrict__ tf, const float* __restrict__ w1,
                float* __restrict__ p, float* __restrict__ q)
{
    __shared__ float redm[8][32];
    const int n = blockIdx.x, tid = threadIdx.x;
    float ap[HC], aq[HC];
#pragma unroll
    for (int c = 0; c < HC; c++) { ap[c] = 0.f; aq[c] = 0.f; }
    for (int f = tid; f < FEAT; f += 256) {
        float xv = tf[(size_t)n * FEAT + f];
        const float4* wp = (const float4*)(w1 + (size_t)f * HC);
        const float4* wq = (const float4*)(w1 + (size_t)(FEAT + f) * HC);
#pragma unroll
        for (int c4 = 0; c4 < 4; c4++) {
            float4 a = wp[c4];
            ap[c4*4+0] += xv*a.x; ap[c4*4+1] += xv*a.y;
            ap[c4*4+2] += xv*a.z; ap[c4*4+3] += xv*a.w;
            float4 b = wq[c4];
            aq[c4*4+0] += xv*b.x; aq[c4*4+1] += xv*b.y;
            aq[c4*4+2] += xv*b.z; aq[c4*4+3] += xv*b.w;
        }
    }
    const int lane = tid & 31, wid = tid >> 5;
    for (int c = 0; c < 32; c++) {
        float v = (c < HC) ? ap[c] : aq[c - HC];
        for (int off = 16; off; off >>= 1) v += __shfl_down_sync(0xffffffffu, v, off);
        if (lane == 0) redm[wid][c] = v;
    }
    __syncthreads();
    if (tid < 32) {
        float v = 0.f;
        for (int w = 0; w < 8; w++) v += redm[w][tid];
        if (tid < HC) p[(size_t)n * HC + tid] = v;
        else          q[(size_t)n * HC + tid - HC] = v;
    }
}

__global__ __launch_bounds__(256)
void pq2_kernel(const float* __restrict__ x, const float* __restrict__ w1,
                float* __restrict__ p, float* __restrict__ q, int Nn)
{
    int n = blockIdx.x * blockDim.x + threadIdx.x;
    if (n >= Nn) return;
    float xi[HC];
#pragma unroll
    for (int c = 0; c < HC; c++) xi[c] = x[(size_t)n * HC + c];
#pragma unroll
    for (int c = 0; c < HC; c++) {
        float pp = 0.f, qq = 0.f;
#pragma unroll
        for (int u = 0; u < HC; u++) {
            pp += xi[u] * w1[u * HC + c];
            qq += xi[u] * w1[(HC + u) * HC + c];
        }
        p[(size_t)n * HC + c] = pp;
        q[(size_t)n * HC + c] = qq;
    }
}

__global__ __launch_bounds__(256)
void edge_kernel(const float* __restrict__ p, const float* __restrict__ q,
                 const float* __restrict__ b1, const float* __restrict__ w2,
                 const float* __restrict__ b2, const int* __restrict__ nbr,
                 float* __restrict__ out, int Nn, int doRelu)
{
    __shared__ float w2s[HC*HC];
    __shared__ float b1s[HC], b2s[HC];
    const int tid = threadIdx.x;
    if (tid < HC*HC) w2s[tid] = w2[tid];
    if (tid < HC) { b1s[tid] = b1[tid]; b2s[tid] = b2[tid]; }
    __syncthreads();
    const int n = blockIdx.x * blockDim.x + tid;
    if (n >= Nn) return;
    float base[HC], best[HC];
#pragma unroll
    for (int c = 0; c < HC; c++) {
        base[c] = p[(size_t)n*HC + c] - q[(size_t)n*HC + c] + b1s[c];
        best[c] = -FLT_MAX;
    }
    for (int kk = 0; kk < KNN; kk++) {
        int j = nbr[n * KNN + kk];
        const float* qj = q + (size_t)j * HC;
        float o[HC];
#pragma unroll
        for (int c = 0; c < HC; c++) o[c] = b2s[c];
#pragma unroll
        for (int u = 0; u < HC; u++) {
            float hv = base[u] + qj[u];
            hv = hv > 0.f ? hv : 0.f;
#pragma unroll
            for (int c = 0; c < HC; c++) o[c] += hv * w2s[u*HC + c];
        }
#pragma unroll
        for (int c = 0; c < HC; c++) best[c] = fmaxf(best[c], o[c]);
    }
#pragma unroll
    for (int c = 0; c < HC; c++) {
        float v = best[c];
        if (doRelu) v = fmaxf(v, 0.f);
        out[(size_t)n * HC + c] = v;
    }
}

__global__ void score_kernel(const float* __restrict__ x, const float* __restrict__ w,
                             int Nn, float* __restrict__ s)
{
    int n = blockIdx.x * blockDim.x + threadIdx.x;
    if (n >= Nn) return;
    float nw = 0.f, d = 0.f;
#pragma unroll
    for (int c = 0; c < HC; c++) nw += w[c] * w[c];
    nw = sqrtf(nw);
#pragma unroll
    for (int c = 0; c < HC; c++) d += x[(size_t)n*HC + c] * w[c];
    s[n] = tanhf(d / nw);
}

__global__ void sq_kernel(const float* __restrict__ x, int Nn, float* __restrict__ sq)
{
    int n = blockIdx.x * blockDim.x + threadIdx.x;
    if (n >= Nn) return;
    float a = 0.f;
#pragma unroll
    for (int c = 0; c < HC; c++) { float v = x[(size_t)n*HC + c]; a += v * v; }
    sq[n] = a;
}

__global__ void rank_pool_kernel(const float* __restrict__ x, const float* __restrict__ s,
                                 int Nn, int nkeep, float* __restrict__ out)
{
    int n = blockIdx.x * blockDim.x + threadIdx.x;
    if (n >= Nn) return;
    float sn = s[n];
    int rank = 0;
    for (int m = 0; m < Nn; m++) {
        float sm = s[m];
        if (sm > sn || (sm == sn && m < n)) rank++;
    }
    if (rank < nkeep) {
#pragma unroll
        for (int c = 0; c < HC; c++)
            out[(size_t)rank * HC + c] = x[(size_t)n * HC + c] * sn;
    }
}

// gated attention pool: vec = sum softmax(x@gw+gb) * x   (fully parallel accumulation)
__global__ __launch_bounds__(256)
void gap_kernel(const float* __restrict__ x, const float* __restrict__ gw,
                const float* __restrict__ gb, int Nn, float* __restrict__ vec)
{
    __shared__ float a[NP1 + 12];
    __shared__ float red[8];
    __shared__ float vacc[HC];
    const int tid = threadIdx.x;
    if (tid < HC) vacc[tid] = 0.f;
    float lmax = -FLT_MAX;
    for (int n = tid; n < Nn; n += 256) {
        float d = gb[0];
#pragma unroll
        for (int c = 0; c < HC; c++) d += x[(size_t)n*HC + c] * gw[c];
        a[n] = d;
        lmax = fmaxf(lmax, d);
    }
    for (int off = 16; off; off >>= 1) lmax = fmaxf(lmax, __shfl_xor_sync(0xffffffffu, lmax, off));
    if ((tid & 31) == 0) red[tid >> 5] = lmax;
    __syncthreads();
    lmax = red[0];
    for (int w = 1; w < 8; w++) lmax = fmaxf(lmax, red[w]);
    __syncthreads();
    float lsum = 0.f;
    for (int n = tid; n < Nn; n += 256) {
        float e = expf(a[n] - lmax);
        a[n] = e;
        lsum += e;
    }
    for (int off = 16; off; off >>= 1) lsum += __shfl_xor_sync(0xffffffffu, lsum, off);
    if ((tid & 31) == 0) red[tid >> 5] = lsum;
    __syncthreads();
    lsum = 0.f;
    for (int w = 0; w < 8; w++) lsum += red[w];

    // parallel weighted accumulation
    float vloc[HC];
#pragma unroll
    for (int c = 0; c < HC; c++) vloc[c] = 0.f;
    for (int n = tid; n < Nn; n += 256) {
        float e = a[n];
        const float4* xr = (const float4*)(x + (size_t)n * HC);
#pragma unroll
        for (int c4 = 0; c4 < 4; c4++) {
            float4 xv = xr[c4];
            vloc[c4*4+0] += e * xv.x; vloc[c4*4+1] += e * xv.y;
            vloc[c4*4+2] += e * xv.z; vloc[c4*4+3] += e * xv.w;
        }
    }
#pragma unroll
    for (int c = 0; c < HC; c++) {
        float v = vloc[c];
        for (int off = 16; off; off >>= 1) v += __shfl_xor_sync(0xffffffffu, v, off);
        if ((tid & 31) == 0) atomicAdd(&vacc[c], v);
    }
    __syncthreads();
    if (tid < HC) vec[tid] = vacc[tid] / lsum;
}

__global__ void final_kernel(const float* __restrict__ v1, const float* __restrict__ v2,
                             const float* __restrict__ w, const float* __restrict__ b,
                             float* __restrict__ out)
{
    int c = threadIdx.x;
    if (c < 2) {
        float acc = b[c];
#pragma unroll
        for (int u = 0; u < HC; u++) acc += (v1[u] + v2[u]) * w[u*2 + c];
        out[c] = acc;
    }
}

// ---------------- launch ----------------
extern "C" void kernel_launch(void* const* d_in, const int* in_sizes, int n_in,
                              void* d_out, int out_size)
{
    const float* ts   = (const float*)d_in[0];
    const float* c1w  = (const float*)d_in[1];
    const float* c1b  = (const float*)d_in[2];
    const float* c2w  = (const float*)d_in[3];
    const float* c2b  = (const float*)d_in[4];
    const float* c3w  = (const float*)d_in[5];
    const float* c3b  = (const float*)d_in[6];
    const float* wih  = (const float*)d_in[7];
    const float* whh  = (const float*)d_in[8];
    const float* bih  = (const float*)d_in[9];
    const float* bhh  = (const float*)d_in[10];
    const float* m1w1 = (const float*)d_in[11];
    const float* m1b1 = (const float*)d_in[12];
    const float* m1w2 = (const float*)d_in[13];
    const float* m1b2 = (const float*)d_in[14];
    const float* p1w  = (const float*)d_in[15];
    const float* g1w  = (const float*)d_in[16];
    const float* g1b  = (const float*)d_in[17];
    const float* m2w1 = (const float*)d_in[18];
    const float* m2b1 = (const float*)d_in[19];
    const float* m2w2 = (const float*)d_in[20];
    const float* m2b2 = (const float*)d_in[21];
    const float* p2w  = (const float*)d_in[22];
    const float* g2w  = (const float*)d_in[23];
    const float* g2b  = (const float*)d_in[24];
    const float* l2w  = (const float*)d_in[25];
    const float* l2b  = (const float*)d_in[26];
    float* out        = (float*)d_out;

    float *gi, *tf, *G, *dg, *p1, *q1, *x1f, *sc1, *pool1, *vec1;
    float *sq2, *p2, *q2, *x2f, *sc2, *pool2, *vec2;
    int *nbr1, *nbr2;
    __nv_bfloat16 *xa_hi, *xa_lo, *xb_hi, *xb_lo, *wk_hi, *wk_lo;
    __nv_bfloat16 *tfhi, *tflo, *wihhi, *wihlo;
    cudaGetSymbolAddress((void**)&gi,    g_gi);
    cudaGetSymbolAddress((void**)&tf,    g_tfeat);
    cudaGetSymbolAddress((void**)&tfhi,  g_tf_hi);
    cudaGetSymbolAddress((void**)&tflo,  g_tf_lo);
    cudaGetSymbolAddress((void**)&G,     g_G);
    cudaGetSymbolAddress((void**)&dg,    g_diag);
    cudaGetSymbolAddress((void**)&nbr1,  g_nbr1);
    cudaGetSymbolAddress((void**)&p1,    g_p1);
    cudaGetSymbolAddress((void**)&q1,    g_q1);
    cudaGetSymbolAddress((void**)&x1f,   g_x1f);
    cudaGetSymbolAddress((void**)&sc1,   g_sc1);
    cudaGetSymbolAddress((void**)&pool1, g_pool1);
    cudaGetSymbolAddress((void**)&vec1,  g_vec1);
    cudaGetSymbolAddress((void**)&sq2,   g_sq2);
    cudaGetSymbolAddress((void**)&nbr2,  g_nbr2);
    cudaGetSymbolAddress((void**)&p2,    g_p2);
    cudaGetSymbolAddress((void**)&q2,    g_q2);
    cudaGetSymbolAddress((void**)&x2f,   g_x2f);
    cudaGetSymbolAddress((void**)&sc2,   g_sc2);
    cudaGetSymbolAddress((void**)&pool2, g_pool2);
    cudaGetSymbolAddress((void**)&vec2,  g_vec2);
    cudaGetSymbolAddress((void**)&xa_hi, g_xa_hi);
    cudaGetSymbolAddress((void**)&xa_lo, g_xa_lo);
    cudaGetSymbolAddress((void**)&xb_hi, g_xb_hi);
    cudaGetSymbolAddress((void**)&xb_lo, g_xb_lo);
    cudaGetSymbolAddress((void**)&wk_hi, g_wk_hi);
    cudaGetSymbolAddress((void**)&wk_lo, g_wk_lo);
    cudaGetSymbolAddress((void**)&wihhi, g_wih_hi);
    cudaGetSymbolAddress((void**)&wihlo, g_wih_lo);

    cudaFuncSetAttribute(conv_wmma_kernel, cudaFuncAttributeMaxDynamicSharedMemorySize, CV_SMEM);
    cudaFuncSetAttribute(wmma3_nt, cudaFuncAttributeMaxDynamicSharedMemorySize, WM_SMEM);

    // prep: pad zeros, transpose input, repack weights
    zero_pad_kernel<<<512, 256>>>(xa_hi, xa_lo, xb_hi, xb_lo);
    prep_x_kernel<<<dim3(32, 4, 32), 256>>>(ts, xa_hi, xa_lo);
    prep_w_kernel<<<1024, 256>>>(c1w, wk_hi, wk_lo);
    conv_wmma_kernel<<<dim3(8, 32), 256, CV_SMEM>>>(xa_hi, xa_lo, wk_hi, wk_lo, c1b,
                                                    xb_hi, xb_lo, 0);
    prep_w_kernel<<<1024, 256>>>(c2w, wk_hi, wk_lo);
    conv_wmma_kernel<<<dim3(8, 32), 256, CV_SMEM>>>(xb_hi, xb_lo, wk_hi, wk_lo, c2b,
                                                    xa_hi, xa_lo, 0);
    prep_w_kernel<<<1024, 256>>>(c3w, wk_hi, wk_lo);
    conv_wmma_kernel<<<dim3(8, 32), 256, CV_SMEM>>>(xa_hi, xa_lo, wk_hi, wk_lo, c3b,
                                                    xb_hi, xb_lo, 1);

    // gi = d @ wih.T + bih  (pipelined wmma 3-pass)
    split_kernel<<<(3*HG*D_ + 255)/256, 256>>>(wih, wihhi, wihlo, 3*HG*D_);
    wmma3_nt<<<dim3(5, (T_*N_)/128), 256, WM_SMEM>>>(xb_hi, xb_lo, wihhi, wihlo,
                                                     bih, gi, T_*N_, 3*HG, D_);
    gru_kernel<<<N_/8, 320>>>(gi, whh, bhh, tf, tfhi, tflo);

    // Gram (pipelined wmma 3-pass) + knn1
    wmma3_nt<<<dim3(16, 8), 256, WM_SMEM>>>(tfhi, tflo, tfhi, tflo,
                                            nullptr, G, N_, N_, FEAT);
    diag_kernel<<<4, 256>>>(G, dg);
    topk1_kernel<<<N_, 256>>>(G, dg, nbr1);

    // DGCN1
    pq1_kernel<<<N_, 256>>>(tf, m1w1, p1, q1);
    edge_kernel<<<4, 256>>>(p1, q1, m1b1, m1w2, m1b2, nbr1, x1f, N_, 1);

    score_kernel<<<4, 256>>>(x1f, p1w, N_, sc1);
    rank_pool_kernel<<<4, 256>>>(x1f, sc1, N_, NP1, pool1);
    gap_kernel<<<1, 256>>>(pool1, g1w, g1b, NP1, vec1);

    // DGCN2
    sq_kernel<<<4, 256>>>(pool1, NP1, sq2);
    topk2_kernel<<<NP1, 256>>>(pool1, sq2, NP1, nbr2);
    pq2_kernel<<<4, 256>>>(pool1, m2w1, p2, q2, NP1);
    edge_kernel<<<4, 256>>>(p2, q2, m2b1, m2w2, m2b2, nbr2, x2f, NP1, 0);

    score_kernel<<<4, 256>>>(x2f, p2w, NP1, sc2);
    rank_pool_kernel<<<4, 256>>>(x2f, sc2, NP1, NP2, pool2);
    gap_kernel<<<1, 256>>>(pool2, g2w, g2b, NP2, vec2);

    final_kernel<<<1, 32>>>(vec1, vec2, l2w, l2b, out);
}

// round 17
// speedup vs baseline: 3.1664x; 1.1053x over previous
#include <cuda_runtime.h>
#include <cuda_bf16.h>
#include <mma.h>
#include <math.h>
#include <float.h>
#include <stdint.h>

using namespace nvcuda;

#define T_   32
#define N_   1024
#define D_   128
#define HG   100
#define FEAT 3200
#define HC   16
#define KNN  20
#define NP1  820
#define NP2  656

// ---------------- scratch (device globals; no allocs) ----------------
__device__ float g_gi[T_*N_*3*HG];
__device__ float g_tfeat[N_*FEAT];
__device__ __nv_bfloat16 g_tf_hi[N_*FEAT];
__device__ __nv_bfloat16 g_tf_lo[N_*FEAT];
__device__ float g_G[N_*N_];
__device__ float g_diag[N_];
__device__ int   g_nbr1[N_*KNN];
__device__ float g_p1[N_*HC], g_q1[N_*HC];
__device__ float g_x1f[N_*HC];
__device__ float g_sc1[N_];
__device__ float g_pool1[NP1*HC];
__device__ float g_vec1[HC];
__device__ float g_sq2[NP1];
__device__ int   g_nbr2[NP1*KNN];
__device__ float g_p2[NP1*HC], g_q2[NP1*HC];
__device__ float g_x2f[NP1*HC];
__device__ float g_sc2[NP1];
__device__ float g_pool2[NP2*HC];
__device__ float g_vec2[HC];
// bf16 hi/lo padded transposed activations: [t][132 rows][1024 ch]
__device__ __nv_bfloat16 g_xa_hi[T_*132*1024];
__device__ __nv_bfloat16 g_xa_lo[T_*132*1024];
__device__ __nv_bfloat16 g_xb_hi[T_*132*1024];   // also reused as gi-A [32768][128]
__device__ __nv_bfloat16 g_xb_lo[T_*132*1024];
// repacked weights [k][o][ic] bf16 hi/lo
__device__ __nv_bfloat16 g_wk_hi[5*1024*1024];
__device__ __nv_bfloat16 g_wk_lo[5*1024*1024];
__device__ __nv_bfloat16 g_wih_hi[3*HG*D_];
__device__ __nv_bfloat16 g_wih_lo[3*HG*D_];

// ---------------- cp.async helpers ----------------
__device__ __forceinline__ uint32_t smem_u32(const void* p) {
    uint32_t a;
    asm("{ .reg .u64 t; cvta.to.shared.u64 t, %1; cvt.u32.u64 %0, t; }" : "=r"(a) : "l"(p));
    return a;
}
__device__ __forceinline__ void cpa16(uint32_t dst, const void* src) {
    asm volatile("cp.async.cg.shared.global [%0], [%1], 16;" :: "r"(dst), "l"(src));
}
#define CPA_COMMIT asm volatile("cp.async.commit_group;" ::: "memory")
#define CPA_WAIT0  asm volatile("cp.async.wait_group 0;" ::: "memory")

// ---------------- prep kernels ----------------
__global__ __launch_bounds__(256)
void prep_w_kernel(const float* __restrict__ w,
                   __nv_bfloat16* __restrict__ whi, __nv_bfloat16* __restrict__ wlo)
{
    __shared__ float buf[5120];
    const int o = blockIdx.x, tid = threadIdx.x;
    const float* src = w + (size_t)o * 5120;
    for (int i = tid; i < 5120; i += 256) buf[i] = src[i];
    __syncthreads();
#pragma unroll
    for (int k = 0; k < 5; k++) {
        for (int ic = tid; ic < 1024; ic += 256) {
            float v = buf[ic * 5 + k];
            __nv_bfloat16 h = __float2bfloat16(v);
            size_t idx = ((size_t)k << 20) + ((size_t)o << 10) + ic;
            whi[idx] = h;
            wlo[idx] = __float2bfloat16(v - __bfloat162float(h));
        }
    }
}

__global__ void split_kernel(const float* __restrict__ in,
                             __nv_bfloat16* __restrict__ hi, __nv_bfloat16* __restrict__ lo, int n)
{
    int i = blockIdx.x * 256 + threadIdx.x;
    if (i >= n) return;
    float v = in[i];
    __nv_bfloat16 h = __float2bfloat16(v);
    hi[i] = h;
    lo[i] = __float2bfloat16(v - __bfloat162float(h));
}

// transpose+split: in fp32 [t][c][128] -> Xp bf16 [t][h+2][c]
__global__ void prep_x_kernel(const float* __restrict__ in,
                              __nv_bfloat16* __restrict__ xhi, __nv_bfloat16* __restrict__ xlo)
{
    __shared__ float tile[32][33];
    int t = blockIdx.z, c0 = blockIdx.x * 32, h0 = blockIdx.y * 32;
    int lx = threadIdx.x & 31, ly = threadIdx.x >> 5;
#pragma unroll
    for (int i = 0; i < 4; i++) {
        int c = c0 + ly + i * 8;
        tile[ly + i * 8][lx] = in[((size_t)t * 1024 + c) * 128 + h0 + lx];
    }
    __syncthreads();
#pragma unroll
    for (int i = 0; i < 4; i++) {
        int h = h0 + ly + i * 8;
        float v = tile[lx][ly + i * 8];
        __nv_bfloat16 hb = __float2bfloat16(v);
        size_t o = ((size_t)t * 132 + h + 2) * 1024 + c0 + lx;
        xhi[o] = hb;
        xlo[o] = __float2bfloat16(v - __bfloat162float(hb));
    }
}

__global__ void zero_pad_kernel(__nv_bfloat16* a, __nv_bfloat16* b,
                                __nv_bfloat16* c, __nv_bfloat16* d)
{
    int idx = blockIdx.x * 256 + threadIdx.x;   // 32t * 4rows * 1024
    if (idx >= 32 * 4 * 1024) return;
    int t = idx >> 12, r = (idx >> 10) & 3, ic = idx & 1023;
    int hp = (r < 2) ? r : 128 + r;
    size_t o = ((size_t)t * 132 + hp) * 1024 + ic;
    __nv_bfloat16 z = __float2bfloat16(0.f);
    a[o] = z; b[o] = z; c[o] = z; d[o] = z;
}

// ---------------- wmma conv kernel (cp.async double-buffered, ic-chunk 32) ----------------
// grid (8 o-tiles, 32 t), 128 thr (4 warps, each 64x64 tile), 2 CTAs/SM.
#define XLD2 40
#define CV_XB 21120u
#define CV_WOFF 42240u
#define CV_WB 20480u
#define CV_SMEM 83200
#define CV_THR 128

__device__ __forceinline__ void conv_issue_stage(
    int qq, int tid, int t, int o0, uint32_t smX, uint32_t smW,
    const __nv_bfloat16* xhi, const __nv_bfloat16* xlo,
    const __nv_bfloat16* whi, const __nv_bfloat16* wlo)
{
    const int ch = qq / 5, s = qq % 5, ic0 = ch << 5;
    const uint32_t wb = smW + (uint32_t)(qq & 1) * CV_WB;
    for (int u = tid; u < 1024; u += CV_THR) {
        int p = u >> 9, r = u & 511;
        int row = r >> 2, cb = r & 3;
        const __nv_bfloat16* src = (p ? wlo : whi)
            + ((size_t)s << 20) + ((size_t)(o0 + row) << 10) + ic0 + cb * 8;
        cpa16(wb + (uint32_t)(p * 128 + row) * 80u + cb * 16, src);
    }
    if (s == 0) {
        const uint32_t xb = smX + (uint32_t)(ch & 1) * CV_XB;
        for (int u = tid; u < 1056; u += CV_THR) {
            int p = (u >= 528) ? 1 : 0;
            int r = u - p * 528;
            int row = r >> 2, cb = r & 3;
            const __nv_bfloat16* src = (p ? xlo : xhi)
                + (((size_t)t * 132 + row) << 10) + ic0 + cb * 8;
            cpa16(xb + (uint32_t)(p * 132 + row) * 80u + cb * 16, src);
        }
    }
    CPA_COMMIT;
}

__global__ __launch_bounds__(CV_THR, 2)
void conv_wmma_kernel(const __nv_bfloat16* __restrict__ xhi, const __nv_bfloat16* __restrict__ xlo,
                      const __nv_bfloat16* __restrict__ whi, const __nv_bfloat16* __restrict__ wlo,
                      const float* __restrict__ bias,
                      __nv_bfloat16* __restrict__ ohi, __nv_bfloat16* __restrict__ olo,
                      int mode)
{
    extern __shared__ char smem[];
    const uint32_t smX = smem_u32(smem);
    const uint32_t smW = smX + CV_WOFF;
    float* cs = (float*)smem;

    const int tid = threadIdx.x;
    const int wid = tid >> 5;
    const int o0 = blockIdx.x * 128;
    const int t  = blockIdx.y;
    const int m0 = (wid >> 1) * 64;                // warp row offset (o), 64-wide
    const int n0 = (wid & 1) * 64;                 // warp col offset (h), 64-wide

    wmma::fragment<wmma::accumulator, 16, 16, 16, float> acc[4][4];
#pragma unroll
    for (int i = 0; i < 4; i++)
#pragma unroll
        for (int j = 0; j < 4; j++) wmma::fill_fragment(acc[i][j], 0.f);

    conv_issue_stage(0, tid, t, o0, smX, smW, xhi, xlo, whi, wlo);

    for (int q = 0; q < 160; q++) {
        const int ch = q / 5, s = q % 5;
        CPA_WAIT0;
        __syncthreads();
        if (q < 159)
            conv_issue_stage(q + 1, tid, t, o0, smX, smW, xhi, xlo, whi, wlo);

        const __nv_bfloat16* Xbase = (const __nv_bfloat16*)(smem) + (size_t)(ch & 1) * (2*132*XLD2);
        const __nv_bfloat16* Wbase = (const __nv_bfloat16*)(smem + CV_WOFF) + (size_t)(q & 1) * (2*128*XLD2);
        const __nv_bfloat16* Whi_s = Wbase;
        const __nv_bfloat16* Wlo_s = Wbase + 128*XLD2;
        const __nv_bfloat16* Xhi_s = Xbase + (size_t)s * XLD2;
        const __nv_bfloat16* Xlo_s = Xbase + 132*XLD2 + (size_t)s * XLD2;

#pragma unroll
        for (int ks = 0; ks < 2; ks++) {
            wmma::fragment<wmma::matrix_a, 16, 16, 16, __nv_bfloat16, wmma::row_major> ah[4], al[4];
            wmma::fragment<wmma::matrix_b, 16, 16, 16, __nv_bfloat16, wmma::col_major> bh[4], bl[4];
#pragma unroll
            for (int i = 0; i < 4; i++) {
                wmma::load_matrix_sync(ah[i], Whi_s + (m0 + i * 16) * XLD2 + ks * 16, XLD2);
                wmma::load_matrix_sync(al[i], Wlo_s + (m0 + i * 16) * XLD2 + ks * 16, XLD2);
            }
#pragma unroll
            for (int j = 0; j < 4; j++) {
                wmma::load_matrix_sync(bh[j], Xhi_s + (n0 + j * 16) * XLD2 + ks * 16, XLD2);
                wmma::load_matrix_sync(bl[j], Xlo_s + (n0 + j * 16) * XLD2 + ks * 16, XLD2);
            }
#pragma unroll
            for (int i = 0; i < 4; i++)
#pragma unroll
                for (int j = 0; j < 4; j++) wmma::mma_sync(acc[i][j], ah[i], bh[j], acc[i][j]);
#pragma unroll
            for (int i = 0; i < 4; i++)
#pragma unroll
                for (int j = 0; j < 4; j++) wmma::mma_sync(acc[i][j], ah[i], bl[j], acc[i][j]);
#pragma unroll
            for (int i = 0; i < 4; i++)
#pragma unroll
                for (int j = 0; j < 4; j++) wmma::mma_sync(acc[i][j], al[i], bh[j], acc[i][j]);
        }
    }

    __syncthreads();
#pragma unroll
    for (int i = 0; i < 4; i++)
#pragma unroll
        for (int j = 0; j < 4; j++)
            wmma::store_matrix_sync(cs + (m0 + i * 16) * 132 + (n0 + j * 16),
                                    acc[i][j], 132, wmma::mem_row_major);
    __syncthreads();

    if (mode == 0) {
        for (int idx = tid; idx < 128 * 128; idx += CV_THR) {
            int o_r = idx & 127, h = idx >> 7;
            float v = cs[o_r * 132 + h] + bias[o0 + o_r];
            v = v > 0.f ? v : 0.1f * v;
            __nv_bfloat16 hb = __float2bfloat16(v);
            size_t g = (((size_t)t * 132) + h + 2) * 1024 + o0 + o_r;
            ohi[g] = hb;
            olo[g] = __float2bfloat16(v - __bfloat162float(hb));
        }
    } else {
        for (int idx = tid; idx < 128 * 128; idx += CV_THR) {
            int h = idx & 127, o_r = idx >> 7;
            float v = cs[o_r * 132 + h] + bias[o0 + o_r];
            v = v > 0.f ? v : 0.1f * v;
            __nv_bfloat16 hb = __float2bfloat16(v);
            size_t g = ((size_t)t * 1024 + o0 + o_r) * 128 + h;
            ohi[g] = hb;
            olo[g] = __float2bfloat16(v - __bfloat162float(hb));
        }
    }
}

// ------------- generic 3-pass bf16 wmma GEMM-NT (cp.async double-buffered) -------------
#define WM_AB 18432      // halfs per A buffer (2*128*72)
#define WM_BB 9216       // halfs per B buffer (2*64*72)
#define WM_SMEM 110592

__device__ __forceinline__ void wm_issue(
    int k0, int buf, int tid, int m0g, int n0g, int Ncols, int Kd,
    uint32_t smA, uint32_t smB,
    const __nv_bfloat16* Ahi, const __nv_bfloat16* Alo,
    const __nv_bfloat16* Bhi, const __nv_bfloat16* Blo)
{
    const uint32_t ab = smA + (uint32_t)buf * (WM_AB * 2);
    for (int u = tid; u < 2048; u += 256) {
        int p = u >> 10, r = u & 1023;
        int row = r >> 3, cb = (r & 7) << 3;
        cpa16(ab + (uint32_t)((p * 128 + row) * 72 + cb) * 2,
              (p ? Alo : Ahi) + (size_t)(m0g + row) * Kd + k0 + cb);
    }
    const uint32_t bb = smB + (uint32_t)buf * (WM_BB * 2);
    for (int u = tid; u < 1024; u += 256) {
        int p = u >> 9, r = u & 511;
        int row = r >> 3, cb = (r & 7) << 3;
        if (n0g + row < Ncols)
            cpa16(bb + (uint32_t)((p * 64 + row) * 72 + cb) * 2,
                  (p ? Blo : Bhi) + (size_t)(n0g + row) * Kd + k0 + cb);
    }
    CPA_COMMIT;
}

__global__ __launch_bounds__(256, 2)
void wmma3_nt(const __nv_bfloat16* __restrict__ Ahi, const __nv_bfloat16* __restrict__ Alo,
              const __nv_bfloat16* __restrict__ Bhi, const __nv_bfloat16* __restrict__ Blo,
              const float* __restrict__ bias, float* __restrict__ C,
              int M, int Ncols, int Kd)
{
    extern __shared__ char sm[];
    __nv_bfloat16* As = (__nv_bfloat16*)sm;
    __nv_bfloat16* Bs = As + 2 * WM_AB;
    float* cs = (float*)sm;
    const uint32_t smA = smem_u32(As);
    const uint32_t smB = smem_u32(Bs);
    const int tid = threadIdx.x, wid = tid >> 5;
    const int n0g = blockIdx.x * 64, m0g = blockIdx.y * 128;
    const int m0 = (wid >> 1) * 32, n0 = (wid & 1) * 32;

    for (int u = tid; u < 2 * WM_BB / 8; u += 256)
        *(uint4*)(Bs + u * 8) = make_uint4(0, 0, 0, 0);
    __syncthreads();

    wmma::fragment<wmma::accumulator, 16, 16, 16, float> acc[2][2];
#pragma unroll
    for (int i = 0; i < 2; i++)
#pragma unroll
        for (int j = 0; j < 2; j++) wmma::fill_fragment(acc[i][j], 0.f);

    wm_issue(0, 0, tid, m0g, n0g, Ncols, Kd, smA, smB, Ahi, Alo, Bhi, Blo);

    const int nk = Kd >> 6;
    for (int kk = 0; kk < nk; kk++) {
        CPA_WAIT0;
        __syncthreads();
        if (kk + 1 < nk)
            wm_issue((kk + 1) << 6, (kk + 1) & 1, tid, m0g, n0g, Ncols, Kd,
                     smA, smB, Ahi, Alo, Bhi, Blo);

        const __nv_bfloat16* Ab = As + (size_t)(kk & 1) * WM_AB;
        const __nv_bfloat16* Bb = Bs + (size_t)(kk & 1) * WM_BB;
#pragma unroll
        for (int ks = 0; ks < 4; ks++) {
            wmma::fragment<wmma::matrix_a, 16, 16, 16, __nv_bfloat16, wmma::row_major> ah[2], al[2];
            wmma::fragment<wmma::matrix_b, 16, 16, 16, __nv_bfloat16, wmma::col_major> bh[2], bl[2];
#pragma unroll
            for (int i = 0; i < 2; i++) {
                wmma::load_matrix_sync(ah[i], Ab + (m0 + i * 16) * 72 + ks * 16, 72);
                wmma::load_matrix_sync(al[i], Ab + 128*72 + (m0 + i * 16) * 72 + ks * 16, 72);
            }
#pragma unroll
            for (int j = 0; j < 2; j++) {
                wmma::load_matrix_sync(bh[j], Bb + (n0 + j * 16) * 72 + ks * 16, 72);
                wmma::load_matrix_sync(bl[j], Bb + 64*72 + (n0 + j * 16) * 72 + ks * 16, 72);
            }
#pragma unroll
            for (int i = 0; i < 2; i++)
#pragma unroll
                for (int j = 0; j < 2; j++) wmma::mma_sync(acc[i][j], ah[i], bh[j], acc[i][j]);
#pragma unroll
            for (int i = 0; i < 2; i++)
#pragma unroll
                for (int j = 0; j < 2; j++) wmma::mma_sync(acc[i][j], ah[i], bl[j], acc[i][j]);
#pragma unroll
            for (int i = 0; i < 2; i++)
#pragma unroll
                for (int j = 0; j < 2; j++) wmma::mma_sync(acc[i][j], al[i], bh[j], acc[i][j]);
        }
    }
    __syncthreads();
#pragma unroll
    for (int i = 0; i < 2; i++)
#pragma unroll
        for (int j = 0; j < 2; j++)
            wmma::store_matrix_sync(cs + (m0 + i * 16) * 68 + (n0 + j * 16),
                                    acc[i][j], 68, wmma::mem_row_major);
    __syncthreads();
    for (int idx = tid; idx < 128 * 64; idx += 256) {
        int m_r = idx >> 6, nn = idx & 63;
        int n = n0g + nn;
        if (n < Ncols)
            C[(size_t)(m0g + m_r) * Ncols + n] = cs[m_r * 68 + nn] + (bias ? bias[n] : 0.f);
    }
}

// ---------------- GRU over T=32 (8 nodes / block) ----------------
__global__ __launch_bounds__(320)
void gru_kernel(const float* __restrict__ gi, const float* __restrict__ whh,
                const float* __restrict__ bhh, float* __restrict__ tf,
                __nv_bfloat16* __restrict__ tfhi, __nv_bfloat16* __restrict__ tflo)
{
    __shared__ float h_s[8][HG];
    __shared__ float gh_s[8][304];
    const int tid = threadIdx.x;
    const int n0 = blockIdx.x * 8;
    for (int p = tid; p < 8 * HG; p += 320) h_s[p / HG][p % HG] = 0.f;
    __syncthreads();

    for (int t = 0; t < T_; t++) {
        if (tid < 300) {
            const int j = tid;
            float acc[8];
#pragma unroll
            for (int n = 0; n < 8; n++) acc[n] = 0.f;
            const float4* wr = (const float4*)(whh + (size_t)j * HG);
#pragma unroll 5
            for (int d4 = 0; d4 < HG / 4; d4++) {
                float4 w4 = wr[d4];
#pragma unroll
                for (int n = 0; n < 8; n++) {
                    float4 h4 = ((const float4*)h_s[n])[d4];
                    acc[n] += w4.x*h4.x + w4.y*h4.y + w4.z*h4.z + w4.w*h4.w;
                }
            }
            float bb = bhh[j];
#pragma unroll
            for (int n = 0; n < 8; n++) gh_s[n][j] = acc[n] + bb;
        }
        __syncthreads();
        for (int p = tid; p < 8 * HG; p += 320) {
            int n = p / HG, d = p % HG;
            int ng = n0 + n;
            const float* gin = gi + ((size_t)t * N_ + ng) * (3 * HG);
            float rg = 1.f / (1.f + expf(-(gin[d]        + gh_s[n][d])));
            float zg = 1.f / (1.f + expf(-(gin[HG + d]   + gh_s[n][HG + d])));
            float nn = tanhf(gin[2*HG + d] + rg * gh_s[n][2*HG + d]);
            float hnew = (1.f - zg) * nn + zg * h_s[n][d];
            float act = hnew > 0.f ? hnew : 0.1f * hnew;
            size_t idx = (size_t)ng * FEAT + t * HG + d;
            tf[idx] = act;
            __nv_bfloat16 hb = __float2bfloat16(act);
            tfhi[idx] = hb;
            tflo[idx] = __float2bfloat16(act - __bfloat162float(hb));
            h_s[n][d] = hnew;
        }
        __syncthreads();
    }
}

// ---------------- small kernels ----------------
__global__ void diag_kernel(const float* __restrict__ G, float* __restrict__ dg)
{
    int n = blockIdx.x * blockDim.x + threadIdx.x;
    if (n < N_) dg[n] = G[(size_t)n * N_ + n];
}

__global__ __launch_bounds__(256)
void topk1_kernel(const float* __restrict__ G, const float* __restrict__ dg,
                  int* __restrict__ nbr)
{
    __shared__ float s[N_];
    __shared__ float rv[8]; __shared__ int ri[8];
    const int i = blockIdx.x, tid = threadIdx.x;
    const float dii = dg[i];
    for (int j = tid; j < N_; j += 256) s[j] = 2.f * G[(size_t)i * N_ + j] - dii - dg[j];
    __syncthreads();
    for (int it = 0; it < KNN; it++) {
        float bv = -FLT_MAX; int bi = 1 << 30;
        for (int j = tid; j < N_; j += 256) {
            float v = s[j];
            if (v > bv || (v == bv && j < bi)) { bv = v; bi = j; }
        }
        for (int off = 16; off; off >>= 1) {
            float ov = __shfl_down_sync(0xffffffffu, bv, off);
            int   oi = __shfl_down_sync(0xffffffffu, bi, off);
            if (ov > bv || (ov == bv && oi < bi)) { bv = ov; bi = oi; }
        }
        if ((tid & 31) == 0) { rv[tid >> 5] = bv; ri[tid >> 5] = bi; }
        __syncthreads();
        if (tid == 0) {
            float fv = rv[0]; int fi = ri[0];
            for (int w = 1; w < 8; w++)
                if (rv[w] > fv || (rv[w] == fv && ri[w] < fi)) { fv = rv[w]; fi = ri[w]; }
            nbr[i * KNN + it] = fi;
            s[fi] = -FLT_MAX;
        }
        __syncthreads();
    }
}

__global__ __launch_bounds__(256)
void topk2_kernel(const float* __restrict__ x, const float* __restrict__ sq,
                  int Nn, int* __restrict__ nbr)
{
    __shared__ float s[NP1 + 12];
    __shared__ float xi[HC];
    __shared__ float rv[8]; __shared__ int ri[8];
    const int i = blockIdx.x, tid = threadIdx.x;
    if (tid < HC) xi[tid] = x[(size_t)i * HC + tid];
    __syncthreads();
    const float sqi = sq[i];
    for (int j = tid; j < Nn; j += 256) {
        const float* xj = x + (size_t)j * HC;
        float dot = 0.f;
#pragma unroll
        for (int c = 0; c < HC; c++) dot += xi[c] * xj[c];
        s[j] = 2.f * dot - sqi - sq[j];
    }
    __syncthreads();
    for (int it = 0; it < KNN; it++) {
        float bv = -FLT_MAX; int bi = 1 << 30;
        for (int j = tid; j < Nn; j += 256) {
            float v = s[j];
            if (v > bv || (v == bv && j < bi)) { bv = v; bi = j; }
        }
        for (int off = 16; off; off >>= 1) {
            float ov = __shfl_down_sync(0xffffffffu, bv, off);
            int   oi = __shfl_down_sync(0xffffffffu, bi, off);
            if (ov > bv || (ov == bv && oi < bi)) { bv = ov; bi = oi; }
        }
        if ((tid & 31) == 0) { rv[tid >> 5] = bv; ri[tid >> 5] = bi; }
        __syncthreads();
        if (tid == 0) {
            float fv = rv[0]; int fi = ri[0];
            for (int w = 1; w < 8; w++)
                if (rv[w] > fv || (rv[w] == fv && ri[w] < fi)) { fv = rv[w]; fi = ri[w]; }
            nbr[i * KNN + it] = fi;
            s[fi] = -FLT_MAX;
        }
        __syncthreads();
    }
}

__global__ __launch_bounds__(256)
void pq1_kernel(const float* __restrict__ tf, const float* __restrict__ w1,
                float* __restrict__ p, float* __restrict__ q)
{
    __shared__ float redm[8][32];
    const int n = blockIdx.x, tid = threadIdx.x;
    float ap[HC], aq[HC];
#pragma unroll
    for (int c = 0; c < HC; c++) { ap[c] = 0.f; aq[c] = 0.f; }
    for (int f = tid; f < FEAT; f += 256) {
        float xv = tf[(size_t)n * FEAT + f];
        const float4* wp = (const float4*)(w1 + (size_t)f * HC);
        const float4* wq = (const float4*)(w1 + (size_t)(FEAT + f) * HC);
#pragma unroll
        for (int c4 = 0; c4 < 4; c4++) {
            float4 a = wp[c4];
            ap[c4*4+0] += xv*a.x; ap[c4*4+1] += xv*a.y;
            ap[c4*4+2] += xv*a.z; ap[c4*4+3] += xv*a.w;
            float4 b = wq[c4];
            aq[c4*4+0] += xv*b.x; aq[c4*4+1] += xv*b.y;
            aq[c4*4+2] += xv*b.z; aq[c4*4+3] += xv*b.w;
        }
    }
    const int lane = tid & 31, wid = tid >> 5;
    for (int c = 0; c < 32; c++) {
        float v = (c < HC) ? ap[c] : aq[c - HC];
        for (int off = 16; off; off >>= 1) v += __shfl_down_sync(0xffffffffu, v, off);
        if (lane == 0) redm[wid][c] = v;
    }
    __syncthreads();
    if (tid < 32) {
        float v = 0.f;
        for (int w = 0; w < 8; w++) v += redm[w][tid];
        if (tid < HC) p[(size_t)n * HC + tid] = v;
        else          q[(size_t)n * HC + tid - HC] = v;
    }
}

__global__ __launch_bounds__(256)
void pq2_kernel(const float* __restrict__ x, const float* __restrict__ w1,
                float* __restrict__ p, float* __restrict__ q, int Nn)
{
    int n = blockIdx.x * blockDim.x + threadIdx.x;
    if (n >= Nn) return;
    float xi[HC];
#pragma unroll
    for (int c = 0; c < HC; c++) xi[c] = x[(size_t)n * HC + c];
#pragma unroll
    for (int c = 0; c < HC; c++) {
        float pp = 0.f, qq = 0.f;
#pragma unroll
        for (int u = 0; u < HC; u++) {
            pp += xi[u] * w1[u * HC + c];
            qq += xi[u] * w1[(HC + u) * HC + c];
        }
        p[(size_t)n * HC + c] = pp;
        q[(size_t)n * HC + c] = qq;
    }
}

__global__ __launch_bounds__(256)
void edge_kernel(const float* __restrict__ p, const float* __restrict__ q,
                 const float* __restrict__ b1, const float* __restrict__ w2,
                 const float* __restrict__ b2, const int* __restrict__ nbr,
                 float* __restrict__ out, int Nn, int doRelu)
{
    __shared__ float w2s[HC*HC];
    __shared__ float b1s[HC], b2s[HC];
    const int tid = threadIdx.x;
    if (tid < HC*HC) w2s[tid] = w2[tid];
    if (tid < HC) { b1s[tid] = b1[tid]; b2s[tid] = b2[tid]; }
    __syncthreads();
    const int n = blockIdx.x * blockDim.x + tid;
    if (n >= Nn) return;
    float base[HC], best[HC];
#pragma unroll
    for (int c = 0; c < HC; c++) {
        base[c] = p[(size_t)n*HC + c] - q[(size_t)n*HC + c] + b1s[c];
        best[c] = -FLT_MAX;
    }
    for (int kk = 0; kk < KNN; kk++) {
        int j = nbr[n * KNN + kk];
        const float* qj = q + (size_t)j * HC;
        float o[HC];
#pragma unroll
        for (int c = 0; c < HC; c++) o[c] = b2s[c];
#pragma unroll
        for (int u = 0; u < HC; u++) {
            float hv = base[u] + qj[u];
            hv = hv > 0.f ? hv : 0.f;
#pragma unroll
            for (int c = 0; c < HC; c++) o[c] += hv * w2s[u*HC + c];
        }
#pragma unroll
        for (int c = 0; c < HC; c++) best[c] = fmaxf(best[c], o[c]);
    }
#pragma unroll
    for (int c = 0; c < HC; c++) {
        float v = best[c];
        if (doRelu) v = fmaxf(v, 0.f);
        out[(size_t)n * HC + c] = v;
    }
}

__global__ void score_kernel(const float* __restrict__ x, const float* __restrict__ w,
                             int Nn, float* __restrict__ s)
{
    int n = blockIdx.x * blockDim.x + threadIdx.x;
    if (n >= Nn) return;
    float nw = 0.f, d = 0.f;
#pragma unroll
    for (int c = 0; c < HC; c++) nw += w[c] * w[c];
    nw = sqrtf(nw);
#pragma unroll
    for (int c = 0; c < HC; c++) d += x[(size_t)n*HC + c] * w[c];
    s[n] = tanhf(d / nw);
}

__global__ void sq_kernel(const float* __restrict__ x, int Nn, float* __restrict__ sq)
{
    int n = blockIdx.x * blockDim.x + threadIdx.x;
    if (n >= Nn) return;
    float a = 0.f;
#pragma unroll
    for (int c = 0; c < HC; c++) { float v = x[(size_t)n*HC + c]; a += v * v; }
    sq[n] = a;
}

__global__ void rank_pool_kernel(const float* __restrict__ x, const float* __restrict__ s,
                                 int Nn, int nkeep, float* __restrict__ out)
{
    int n = blockIdx.x * blockDim.x + threadIdx.x;
    if (n >= Nn) return;
    float sn = s[n];
    int rank = 0;
    for (int m = 0; m < Nn; m++) {
        float sm = s[m];
        if (sm > sn || (sm == sn && m < n)) rank++;
    }
    if (rank < nkeep) {
#pragma unroll
        for (int c = 0; c < HC; c++)
            out[(size_t)rank * HC + c] = x[(size_t)n * HC + c] * sn;
    }
}

__global__ __launch_bounds__(256)
void gap_kernel(const float* __restrict__ x, const float* __restrict__ gw,
                const float* __restrict__ gb, int Nn, float* __restrict__ vec)
{
    __shared__ float a[NP1 + 12];
    __shared__ float red[8];
    __shared__ float vacc[HC];
    const int tid = threadIdx.x;
    if (tid < HC) vacc[tid] = 0.f;
    float lmax = -FLT_MAX;
    for (int n = tid; n < Nn; n += 256) {
        float d = gb[0];
#pragma unroll
        for (int c = 0; c < HC; c++) d += x[(size_t)n*HC + c] * gw[c];
        a[n] = d;
        lmax = fmaxf(lmax, d);
    }
    for (int off = 16; off; off >>= 1) lmax = fmaxf(lmax, __shfl_xor_sync(0xffffffffu, lmax, off));
    if ((tid & 31) == 0) red[tid >> 5] = lmax;
    __syncthreads();
    lmax = red[0];
    for (int w = 1; w < 8; w++) lmax = fmaxf(lmax, red[w]);
    __syncthreads();
    float lsum = 0.f;
    for (int n = tid; n < Nn; n += 256) {
        float e = expf(a[n] - lmax);
        a[n] = e;
        lsum += e;
    }
    for (int off = 16; off; off >>= 1) lsum += __shfl_xor_sync(0xffffffffu, lsum, off);
    if ((tid & 31) == 0) red[tid >> 5] = lsum;
    __syncthreads();
    lsum = 0.f;
    for (int w = 0; w < 8; w++) lsum += red[w];

    float vloc[HC];
#pragma unroll
    for (int c = 0; c < HC; c++) vloc[c] = 0.f;
    for (int n = tid; n < Nn; n += 256) {
        float e = a[n];
        const float4* xr = (const float4*)(x + (size_t)n * HC);
#pragma unroll
        for (int c4 = 0; c4 < 4; c4++) {
            float4 xv = xr[c4];
            vloc[c4*4+0] += e * xv.x; vloc[c4*4+1] += e * xv.y;
            vloc[c4*4+2] += e * xv.z; vloc[c4*4+3] += e * xv.w;
        }
    }
#pragma unroll
    for (int c = 0; c < HC; c++) {
        float v = vloc[c];
        for (int off = 16; off; off >>= 1) v += __shfl_xor_sync(0xffffffffu, v, off);
        if ((tid & 31) == 0) atomicAdd(&vacc[c], v);
    }
    __syncthreads();
    if (tid < HC) vec[tid] = vacc[tid] / lsum;
}

__global__ void final_kernel(const float* __restrict__ v1, const float* __restrict__ v2,
                             const float* __restrict__ w, const float* __restrict__ b,
                             float* __restrict__ out)
{
    int c = threadIdx.x;
    if (c < 2) {
        float acc = b[c];
#pragma unroll
        for (int u = 0; u < HC; u++) acc += (v1[u] + v2[u]) * w[u*2 + c];
        out[c] = acc;
    }
}

// ---------------- launch ----------------
extern "C" void kernel_launch(void* const* d_in, const int* in_sizes, int n_in,
                              void* d_out, int out_size)
{
    const float* ts   = (const float*)d_in[0];
    const float* c1w  = (const float*)d_in[1];
    const float* c1b  = (const float*)d_in[2];
    const float* c2w  = (const float*)d_in[3];
    const float* c2b  = (const float*)d_in[4];
    const float* c3w  = (const float*)d_in[5];
    const float* c3b  = (const float*)d_in[6];
    const float* wih  = (const float*)d_in[7];
    const float* whh  = (const float*)d_in[8];
    const float* bih  = (const float*)d_in[9];
    const float* bhh  = (const float*)d_in[10];
    const float* m1w1 = (const float*)d_in[11];
    const float* m1b1 = (const float*)d_in[12];
    const float* m1w2 = (const float*)d_in[13];
    const float* m1b2 = (const float*)d_in[14];
    const float* p1w  = (const float*)d_in[15];
    const float* g1w  = (const float*)d_in[16];
    const float* g1b  = (const float*)d_in[17];
    const float* m2w1 = (const float*)d_in[18];
    const float* m2b1 = (const float*)d_in[19];
    const float* m2w2 = (const float*)d_in[20];
    const float* m2b2 = (const float*)d_in[21];
    const float* p2w  = (const float*)d_in[22];
    const float* g2w  = (const float*)d_in[23];
    const float* g2b  = (const float*)d_in[24];
    const float* l2w  = (const float*)d_in[25];
    const float* l2b  = (const float*)d_in[26];
    float* out        = (float*)d_out;

    float *gi, *tf, *G, *dg, *p1, *q1, *x1f, *sc1, *pool1, *vec1;
    float *sq2, *p2, *q2, *x2f, *sc2, *pool2, *vec2;
    int *nbr1, *nbr2;
    __nv_bfloat16 *xa_hi, *xa_lo, *xb_hi, *xb_lo, *wk_hi, *wk_lo;
    __nv_bfloat16 *tfhi, *tflo, *wihhi, *wihlo;
    cudaGetSymbolAddress((void**)&gi,    g_gi);
    cudaGetSymbolAddress((void**)&tf,    g_tfeat);
    cudaGetSymbolAddress((void**)&tfhi,  g_tf_hi);
    cudaGetSymbolAddress((void**)&tflo,  g_tf_lo);
    cudaGetSymbolAddress((void**)&G,     g_G);
    cudaGetSymbolAddress((void**)&dg,    g_diag);
    cudaGetSymbolAddress((void**)&nbr1,  g_nbr1);
    cudaGetSymbolAddress((void**)&p1,    g_p1);
    cudaGetSymbolAddress((void**)&q1,    g_q1);
    cudaGetSymbolAddress((void**)&x1f,   g_x1f);
    cudaGetSymbolAddress((void**)&sc1,   g_sc1);
    cudaGetSymbolAddress((void**)&pool1, g_pool1);
    cudaGetSymbolAddress((void**)&vec1,  g_vec1);
    cudaGetSymbolAddress((void**)&sq2,   g_sq2);
    cudaGetSymbolAddress((void**)&nbr2,  g_nbr2);
    cudaGetSymbolAddress((void**)&p2,    g_p2);
    cudaGetSymbolAddress((void**)&q2,    g_q2);
    cudaGetSymbolAddress((void**)&x2f,   g_x2f);
    cudaGetSymbolAddress((void**)&sc2,   g_sc2);
    cudaGetSymbolAddress((void**)&pool2, g_pool2);
    cudaGetSymbolAddress((void**)&vec2,  g_vec2);
    cudaGetSymbolAddress((void**)&xa_hi, g_xa_hi);
    cudaGetSymbolAddress((void**)&xa_lo, g_xa_lo);
    cudaGetSymbolAddress((void**)&xb_hi, g_xb_hi);
    cudaGetSymbolAddress((void**)&xb_lo, g_xb_lo);
    cudaGetSymbolAddress((void**)&wk_hi, g_wk_hi);
    cudaGetSymbolAddress((void**)&wk_lo, g_wk_lo);
    cudaGetSymbolAddress((void**)&wihhi, g_wih_hi);
    cudaGetSymbolAddress((void**)&wihlo, g_wih_lo);

    cudaFuncSetAttribute(conv_wmma_kernel, cudaFuncAttributeMaxDynamicSharedMemorySize, CV_SMEM);
    cudaFuncSetAttribute(wmma3_nt, cudaFuncAttributeMaxDynamicSharedMemorySize, WM_SMEM);

    // prep: pad zeros, transpose input, repack weights
    zero_pad_kernel<<<512, 256>>>(xa_hi, xa_lo, xb_hi, xb_lo);
    prep_x_kernel<<<dim3(32, 4, 32), 256>>>(ts, xa_hi, xa_lo);
    prep_w_kernel<<<1024, 256>>>(c1w, wk_hi, wk_lo);
    conv_wmma_kernel<<<dim3(8, 32), CV_THR, CV_SMEM>>>(xa_hi, xa_lo, wk_hi, wk_lo, c1b,
                                                       xb_hi, xb_lo, 0);
    prep_w_kernel<<<1024, 256>>>(c2w, wk_hi, wk_lo);
    conv_wmma_kernel<<<dim3(8, 32), CV_THR, CV_SMEM>>>(xb_hi, xb_lo, wk_hi, wk_lo, c2b,
                                                       xa_hi, xa_lo, 0);
    prep_w_kernel<<<1024, 256>>>(c3w, wk_hi, wk_lo);
    conv_wmma_kernel<<<dim3(8, 32), CV_THR, CV_SMEM>>>(xa_hi, xa_lo, wk_hi, wk_lo, c3b,
                                                       xb_hi, xb_lo, 1);

    // gi = d @ wih.T + bih  (pipelined wmma 3-pass)
    split_kernel<<<(3*HG*D_ + 255)/256, 256>>>(wih, wihhi, wihlo, 3*HG*D_);
    wmma3_nt<<<dim3(5, (T_*N_)/128), 256, WM_SMEM>>>(xb_hi, xb_lo, wihhi, wihlo,
                                                     bih, gi, T_*N_, 3*HG, D_);
    gru_kernel<<<N_/8, 320>>>(gi, whh, bhh, tf, tfhi, tflo);

    // Gram (pipelined wmma 3-pass) + knn1
    wmma3_nt<<<dim3(16, 8), 256, WM_SMEM>>>(tfhi, tflo, tfhi, tflo,
                                            nullptr, G, N_, N_, FEAT);
    diag_kernel<<<4, 256>>>(G, dg);
    topk1_kernel<<<N_, 256>>>(G, dg, nbr1);

    // DGCN1
    pq1_kernel<<<N_, 256>>>(tf, m1w1, p1, q1);
    edge_kernel<<<4, 256>>>(p1, q1, m1b1, m1w2, m1b2, nbr1, x1f, N_, 1);

    score_kernel<<<4, 256>>>(x1f, p1w, N_, sc1);
    rank_pool_kernel<<<4, 256>>>(x1f, sc1, N_, NP1, pool1);
    gap_kernel<<<1, 256>>>(pool1, g1w, g1b, NP1, vec1);

    // DGCN2
    sq_kernel<<<4, 256>>>(pool1, NP1, sq2);
    topk2_kernel<<<NP1, 256>>>(pool1, sq2, NP1, nbr2);
    pq2_kernel<<<4, 256>>>(pool1, m2w1, p2, q2, NP1);
    edge_kernel<<<4, 256>>>(p2, q2, m2b1, m2w2, m2b2, nbr2, x2f, NP1, 0);

    score_kernel<<<4, 256>>>(x2f, p2w, NP1, sc2);
    rank_pool_kernel<<<4, 256>>>(x2f, sc2, NP1, NP2, pool2);
    gap_kernel<<<1, 256>>>(pool2, g2w, g2b, NP2, vec2);

    final_kernel<<<1, 32>>>(vec1, vec2, l2w, l2b, out);
}